// round 1
// baseline (speedup 1.0000x reference)
#include <cuda_runtime.h>
#include <math.h>

#define BQ   1024
#define NT   50000
#define NL   8
#define KNN  75
#define HD   128
#define NC   10000

// ---------------- device scratch (no runtime allocation allowed) ----------------
__device__ float g_h1[BQ * HD];
__device__ float g_h2[BQ * HD];
__device__ float g_h3[BQ * HD];
__device__ float g_q4[BQ * NL];
__device__ float g_t1[(size_t)NT * HD];
__device__ float g_t2[(size_t)NT * HD];
__device__ float g_t3[(size_t)NT * HD];
__device__ float g_t4[(size_t)NT * NL];
__device__ float g_d2[(size_t)BQ * NT];   // 204.8 MB distance scratch
__device__ float g_qn[BQ];
__device__ float g_tn[NT];
__device__ float g_tot[BQ * NL];

// ---------------------------------------------------------------------------
// Generic fused linear + ReLU:  out[M x 128] = relu(A[M x K] @ W[K x 128] + b)
// 64x128 output tile per 256-thread block, 4x8 register micro-tile.
// ---------------------------------------------------------------------------
__global__ void __launch_bounds__(256)
linear_relu_kernel(const float* __restrict__ A, const float* __restrict__ W,
                   const float* __restrict__ bias, float* __restrict__ out,
                   int M, int K)
{
    __shared__ __align__(16) float As[16 * 68];
    __shared__ __align__(16) float Bs[16 * 136];
    const int tx = threadIdx.x, ty = threadIdx.y;
    const int tid = ty * 16 + tx;
    const int m0 = blockIdx.x * 64;

    float acc[4][8];
#pragma unroll
    for (int r = 0; r < 4; r++)
#pragma unroll
        for (int c = 0; c < 8; c++) acc[r][c] = 0.f;

    const int nChunks = (K + 15) / 16;
    for (int ch = 0; ch < nChunks; ch++) {
        const int k0 = ch * 16;
#pragma unroll
        for (int i = 0; i < 4; i++) {
            int e = tid + i * 256;
            int k = e & 15, m = e >> 4;
            float v = 0.f;
            if (k0 + k < K && m0 + m < M) v = A[(size_t)(m0 + m) * K + k0 + k];
            As[k * 68 + m] = v;
        }
#pragma unroll
        for (int i = 0; i < 8; i++) {
            int e = tid + i * 256;
            int h = e & 127, k = e >> 7;
            float v = 0.f;
            if (k0 + k < K) v = W[(size_t)(k0 + k) * HD + h];
            Bs[k * 136 + h] = v;
        }
        __syncthreads();
#pragma unroll
        for (int k = 0; k < 16; k++) {
            float4 a  = *(const float4*)&As[k * 68 + ty * 4];
            float4 b0 = *(const float4*)&Bs[k * 136 + tx * 4];
            float4 b1 = *(const float4*)&Bs[k * 136 + 64 + tx * 4];
            float av[4] = {a.x, a.y, a.z, a.w};
            float bv[8] = {b0.x, b0.y, b0.z, b0.w, b1.x, b1.y, b1.z, b1.w};
#pragma unroll
            for (int r = 0; r < 4; r++)
#pragma unroll
                for (int c = 0; c < 8; c++) acc[r][c] += av[r] * bv[c];
        }
        __syncthreads();
    }
#pragma unroll
    for (int r = 0; r < 4; r++) {
        int m = m0 + ty * 4 + r;
        if (m >= M) continue;
#pragma unroll
        for (int half = 0; half < 2; half++) {
#pragma unroll
            for (int c = 0; c < 4; c++) {
                int h = half * 64 + tx * 4 + c;
                float v = acc[r][half * 4 + c] + bias[h];
                out[(size_t)m * HD + h] = fmaxf(v, 0.f);
            }
        }
    }
}

// ---------------------------------------------------------------------------
// Final linear + softmax: out[M x 8] = softmax(A[M x 128] @ W[128 x 8] + b)
// One warp per row.
// ---------------------------------------------------------------------------
__global__ void __launch_bounds__(256)
linear_softmax_kernel(const float* __restrict__ A, const float* __restrict__ W,
                      const float* __restrict__ bias, float* __restrict__ out, int M)
{
    __shared__ float Ws[HD * NL];
    __shared__ float bs[NL];
    int tid = threadIdx.x;
    for (int i = tid; i < HD * NL; i += 256) Ws[i] = W[i];
    if (tid < NL) bs[tid] = bias[tid];
    __syncthreads();

    int warp = tid >> 5, lane = tid & 31;
    int m = blockIdx.x * 8 + warp;
    if (m >= M) return;

    float acc[NL];
#pragma unroll
    for (int h = 0; h < NL; h++) acc[h] = 0.f;
    for (int k = lane; k < HD; k += 32) {
        float x = A[(size_t)m * HD + k];
#pragma unroll
        for (int h = 0; h < NL; h++) acc[h] += x * Ws[k * NL + h];
    }
#pragma unroll
    for (int h = 0; h < NL; h++)
#pragma unroll
        for (int off = 16; off > 0; off >>= 1)
            acc[h] += __shfl_down_sync(0xFFFFFFFFu, acc[h], off);

    if (lane == 0) {
        float v[NL], mx = -1e30f;
#pragma unroll
        for (int h = 0; h < NL; h++) { v[h] = acc[h] + bs[h]; mx = fmaxf(mx, v[h]); }
        float s = 0.f;
#pragma unroll
        for (int h = 0; h < NL; h++) { v[h] = expf(v[h] - mx); s += v[h]; }
        float inv = 1.0f / s;
#pragma unroll
        for (int h = 0; h < NL; h++) out[(size_t)m * NL + h] = v[h] * inv;
    }
}

// ---------------------------------------------------------------------------
// Row squared norms. One warp per row, 8 rows per block.
// ---------------------------------------------------------------------------
__global__ void __launch_bounds__(256)
rownorm_kernel(const float* __restrict__ A, float* __restrict__ out, int M, int D)
{
    int warp = threadIdx.x >> 5, lane = threadIdx.x & 31;
    int m = blockIdx.x * 8 + warp;
    if (m >= M) return;
    float s = 0.f;
    for (int k = lane; k < D; k += 32) { float v = A[(size_t)m * D + k]; s += v * v; }
#pragma unroll
    for (int off = 16; off > 0; off >>= 1) s += __shfl_down_sync(0xFFFFFFFFu, s, off);
    if (lane == 0) out[m] = s;
}

// ---------------------------------------------------------------------------
// Distance GEMM: d2[b,n] = max(qn[b] + tn[n] - 2*dot(q_b, t_n), 0)
// 64(q) x 128(n) tile, k-chunks of 16, 4x8 micro-tile.
// ---------------------------------------------------------------------------
__global__ void __launch_bounds__(256)
dist_kernel(const float* __restrict__ Q, const float* __restrict__ T,
            const float* __restrict__ qn, const float* __restrict__ tn,
            float* __restrict__ out, int D, int Ncols)
{
    __shared__ __align__(16) float As[16 * 68];
    __shared__ __align__(16) float Bs[16 * 136];
    const int tx = threadIdx.x, ty = threadIdx.y;
    const int tid = ty * 16 + tx;
    const int n0 = blockIdx.x * 128;
    const int m0 = blockIdx.y * 64;

    float acc[4][8];
#pragma unroll
    for (int r = 0; r < 4; r++)
#pragma unroll
        for (int c = 0; c < 8; c++) acc[r][c] = 0.f;

    const int nChunks = (D + 15) / 16;
    for (int ch = 0; ch < nChunks; ch++) {
        const int k0 = ch * 16;
#pragma unroll
        for (int i = 0; i < 4; i++) {
            int e = tid + i * 256;
            int k = e & 15, m = e >> 4;
            float v = (k0 + k < D) ? Q[(size_t)(m0 + m) * D + k0 + k] : 0.f;
            As[k * 68 + m] = v;
        }
#pragma unroll
        for (int i = 0; i < 8; i++) {
            int e = tid + i * 256;
            int k = e & 15, n = e >> 4;
            int gn = n0 + n;
            float v = 0.f;
            if (k0 + k < D && gn < Ncols) v = T[(size_t)gn * D + k0 + k];
            Bs[k * 136 + n] = v;
        }
        __syncthreads();
#pragma unroll
        for (int k = 0; k < 16; k++) {
            float4 a  = *(const float4*)&As[k * 68 + ty * 4];
            float4 b0 = *(const float4*)&Bs[k * 136 + tx * 4];
            float4 b1 = *(const float4*)&Bs[k * 136 + 64 + tx * 4];
            float av[4] = {a.x, a.y, a.z, a.w};
            float bv[8] = {b0.x, b0.y, b0.z, b0.w, b1.x, b1.y, b1.z, b1.w};
#pragma unroll
            for (int r = 0; r < 4; r++)
#pragma unroll
                for (int c = 0; c < 8; c++) acc[r][c] += av[r] * bv[c];
        }
        __syncthreads();
    }
#pragma unroll
    for (int r = 0; r < 4; r++) {
        int m = m0 + ty * 4 + r;
        float qv = qn[m];
#pragma unroll
        for (int half = 0; half < 2; half++) {
#pragma unroll
            for (int c = 0; c < 4; c++) {
                int n = n0 + half * 64 + tx * 4 + c;
                if (n < Ncols) {
                    float d = qv + tn[n] - 2.f * acc[r][half * 4 + c];
                    out[(size_t)m * Ncols + n] = fmaxf(d, 0.f);
                }
            }
        }
    }
}

// ---------------------------------------------------------------------------
// Per-query exact top-K selection (radix select on float bits, nonneg floats
// are bit-order monotone) + weighted per-class accumulation.
// One block per query; the full 50000-float row is staged in dynamic smem.
// Dynamic smem layout: row[NT] | hist[256] (u32) | acc[256*9]
// ---------------------------------------------------------------------------
#define SELECT_SMEM ((NT + 256 + 256 * 9) * 4)

__global__ void __launch_bounds__(256)
select_kernel(const float* __restrict__ d2mat, const int* __restrict__ labels,
              float* __restrict__ total, int init)
{
    extern __shared__ __align__(16) float sm[];
    float*    row  = sm;
    unsigned* hist = (unsigned*)(sm + NT);
    float*    acc  = sm + NT + 256;

    __shared__ unsigned s_prefix, s_kth, s_eqcnt, s_cless;
    __shared__ int s_eqidx[64];
    __shared__ float s_sums[9];

    const int b = blockIdx.x;
    const int tid = threadIdx.x;
    const int lane = tid & 31;

    // stage row into smem (vectorized; NT % 4 == 0)
    const float4* src = (const float4*)(d2mat + (size_t)b * NT);
    float4* dst = (float4*)row;
    for (int i = tid; i < NT / 4; i += 256) dst[i] = src[i];
    if (tid == 0) { s_eqcnt = 0; s_cless = 0; }
    __syncthreads();

    // 4-round radix select for the exact KNN-th smallest key
    unsigned prefix = 0, kth = KNN;
    const int PADN = ((NT + 255) / 256) * 256;
    for (int shift = 24; shift >= 0; shift -= 8) {
        hist[tid] = 0;
        __syncthreads();
        unsigned maskAbove = (shift == 24) ? 0u : (0xFFFFFFFFu << (shift + 8));
        for (int i = tid; i < PADN; i += 256) {
            unsigned bin = 0xFFFFFFFFu;  // sentinel: does not count
            if (i < NT) {
                unsigned key = __float_as_uint(row[i]);
                if ((key & maskAbove) == prefix) bin = (key >> shift) & 0xFF;
            }
            unsigned grp = __match_any_sync(0xFFFFFFFFu, bin);
            int leader = __ffs(grp) - 1;
            if (bin != 0xFFFFFFFFu && lane == leader)
                atomicAdd(&hist[bin], (unsigned)__popc(grp));
        }
        __syncthreads();
        if (tid == 0) {
            unsigned a = 0;
            for (int bin = 0; bin < 256; bin++) {
                unsigned c = hist[bin];
                if (a + c >= kth) { s_prefix = prefix | ((unsigned)bin << shift);
                                    s_kth = kth - a; break; }
                a += c;
            }
        }
        __syncthreads();
        prefix = s_prefix; kth = s_kth;
    }
    const unsigned Tkey = prefix;

    // accumulate: strict-less neighbors contribute fully; equals handled by rank
#pragma unroll
    for (int j = 0; j < 9; j++) acc[tid * 9 + j] = 0.f;
    float sT = 0.f;
    unsigned cless = 0;
    for (int i = tid; i < NT; i += 256) {
        float d2 = row[i];
        unsigned key = __float_as_uint(d2);
        if (key < Tkey) {
            float w = (d2 > 0.f) ? __fdiv_rn(1.0f, __fsqrt_rn(d2)) : 0.f;
            sT += w;
            acc[tid * 9 + labels[i]] += w;
            cless++;
        } else if (key == Tkey) {
            unsigned slot = atomicAdd(&s_eqcnt, 1u);
            if (slot < 64) s_eqidx[slot] = i;
        }
    }
    acc[tid * 9 + 8] = sT;
    atomicAdd(&s_cless, cless);
    __syncthreads();

    if (tid < 9) {
        float s = 0.f;
        for (int t = 0; t < 256; t++) s += acc[t * 9 + tid];
        s_sums[tid] = s;
    }
    __syncthreads();

    if (tid == 0) {
        int need = KNN - (int)s_cless;
        int ne = (int)s_eqcnt; if (ne > 64) ne = 64;
        // take boundary ties in ascending index order (matches top_k tie-break)
        for (int a2 = 1; a2 < ne; a2++) {
            int v = s_eqidx[a2]; int j = a2 - 1;
            while (j >= 0 && s_eqidx[j] > v) { s_eqidx[j + 1] = s_eqidx[j]; j--; }
            s_eqidx[j + 1] = v;
        }
        float d2T = __uint_as_float(Tkey);
        float wT = (d2T > 0.f) ? __fdiv_rn(1.0f, __fsqrt_rn(d2T)) : 0.f;
        float cls[NL];
#pragma unroll
        for (int l = 0; l < NL; l++) cls[l] = s_sums[l];
        float stot = s_sums[8];
        for (int j = 0; j < need && j < ne; j++) {
            stot += wT;
            cls[labels[s_eqidx[j]]] += wT;
        }
#pragma unroll
        for (int l = 0; l < NL; l++) {
            float val = stot - cls[l];
            size_t o = (size_t)b * NL + l;
            if (init) total[o] = val; else total[o] += val;
        }
    }
}

// ---------------------------------------------------------------------------
// Empirical p-value: out[b,l] = count(cali >= total[b,l]) / NC
// ---------------------------------------------------------------------------
__global__ void __launch_bounds__(256)
pvalue_kernel(const float* __restrict__ total, const float* __restrict__ cali,
              float* __restrict__ out)
{
    const int b = blockIdx.x, tid = threadIdx.x;
    float t[NL];
#pragma unroll
    for (int l = 0; l < NL; l++) t[l] = total[(size_t)b * NL + l];
    int cnt[NL];
#pragma unroll
    for (int l = 0; l < NL; l++) cnt[l] = 0;
    for (int i = tid; i < NC; i += 256) {
        float c = cali[i];
#pragma unroll
        for (int l = 0; l < NL; l++) cnt[l] += (c >= t[l]) ? 1 : 0;
    }
    __shared__ int sc[NL];
    if (tid < NL) sc[tid] = 0;
    __syncthreads();
#pragma unroll
    for (int l = 0; l < NL; l++) atomicAdd(&sc[l], cnt[l]);
    __syncthreads();
    if (tid < NL) out[(size_t)b * NL + tid] = (float)sc[tid] * (1.0f / NC);
}

// ---------------------------------------------------------------------------
extern "C" void kernel_launch(void* const* d_in, const int* in_sizes, int n_in,
                              void* d_out, int out_size)
{
    const float* x        = (const float*)d_in[0];
    const float* train_x  = (const float*)d_in[1];
    const int*   lab      = (const int*)  d_in[2];
    const float* cali     = (const float*)d_in[3];
    const float* W1 = (const float*)d_in[4];  const float* b1 = (const float*)d_in[5];
    const float* W2 = (const float*)d_in[6];  const float* b2 = (const float*)d_in[7];
    const float* W3 = (const float*)d_in[8];  const float* b3 = (const float*)d_in[9];
    const float* W4 = (const float*)d_in[10]; const float* b4 = (const float*)d_in[11];
    float* out = (float*)d_out;

    float *h1p, *h2p, *h3p, *q4p, *t1p, *t2p, *t3p, *t4p, *d2p, *qnp, *tnp, *totp;
    cudaGetSymbolAddress((void**)&h1p, g_h1);
    cudaGetSymbolAddress((void**)&h2p, g_h2);
    cudaGetSymbolAddress((void**)&h3p, g_h3);
    cudaGetSymbolAddress((void**)&q4p, g_q4);
    cudaGetSymbolAddress((void**)&t1p, g_t1);
    cudaGetSymbolAddress((void**)&t2p, g_t2);
    cudaGetSymbolAddress((void**)&t3p, g_t3);
    cudaGetSymbolAddress((void**)&t4p, g_t4);
    cudaGetSymbolAddress((void**)&d2p, g_d2);
    cudaGetSymbolAddress((void**)&qnp, g_qn);
    cudaGetSymbolAddress((void**)&tnp, g_tn);
    cudaGetSymbolAddress((void**)&totp, g_tot);

    cudaFuncSetAttribute(select_kernel,
                         cudaFuncAttributeMaxDynamicSharedMemorySize, SELECT_SMEM);

    dim3 tb(16, 16);
    const int D0 = 83;

    // query-side MLP
    linear_relu_kernel<<<BQ / 64, tb>>>(x,   W1, b1, h1p, BQ, D0);
    linear_relu_kernel<<<BQ / 64, tb>>>(h1p, W2, b2, h2p, BQ, HD);
    linear_relu_kernel<<<BQ / 64, tb>>>(h2p, W3, b3, h3p, BQ, HD);
    linear_softmax_kernel<<<(BQ + 7) / 8, 256>>>(h3p, W4, b4, q4p, BQ);

    // train-side feature banks
    const int gtm = (NT + 63) / 64;
    linear_relu_kernel<<<gtm, tb>>>(train_x, W1, b1, t1p, NT, D0);
    linear_relu_kernel<<<gtm, tb>>>(t1p,     W2, b2, t2p, NT, HD);
    linear_relu_kernel<<<gtm, tb>>>(t2p,     W3, b3, t3p, NT, HD);
    linear_softmax_kernel<<<(NT + 7) / 8, 256>>>(t3p, W4, b4, t4p, NT);

    // 5 kNN nonconformity layers
    const float* Qs[5] = {x, h1p, h2p, h3p, q4p};
    const float* Ts[5] = {train_x, t1p, t2p, t3p, t4p};
    const int    Ds[5] = {D0, HD, HD, HD, NL};
    for (int i = 0; i < 5; i++) {
        rownorm_kernel<<<(BQ + 7) / 8, 256>>>(Qs[i], qnp, BQ, Ds[i]);
        rownorm_kernel<<<(NT + 7) / 8, 256>>>(Ts[i], tnp, NT, Ds[i]);
        dist_kernel<<<dim3((NT + 127) / 128, BQ / 64), tb>>>(Qs[i], Ts[i], qnp, tnp,
                                                             d2p, Ds[i], NT);
        select_kernel<<<BQ, 256, SELECT_SMEM>>>(d2p, lab, totp, (i == 0) ? 1 : 0);
    }

    // p-values
    pvalue_kernel<<<BQ, 256>>>(totp, cali, out);
}

// round 3
// speedup vs baseline: 1.1125x; 1.1125x over previous
#include <cuda_runtime.h>
#include <cuda_bf16.h>
#include <math.h>
#include <stdint.h>

#define BQ   1024
#define NT   50000
#define NTP  50048          // NT padded to multiple of 128
#define NL   8
#define KNN  75
#define HD   128
#define NC   10000

// ---------------- device scratch (no runtime allocation allowed) ----------------
__device__ float g_h1[BQ * HD];
__device__ float g_h2[BQ * HD];
__device__ float g_h3[BQ * HD];
__device__ float g_q4[BQ * NL];
__device__ float g_t1[(size_t)NT * HD];
__device__ float g_t2[(size_t)NT * HD];
__device__ float g_t3[(size_t)NT * HD];
__device__ float g_t4[(size_t)NT * NL];
__device__ float g_d2[(size_t)BQ * NT];   // 204.8 MB distance scratch
__device__ float g_qn[BQ];
__device__ float g_tn[NT];
__device__ float g_tot[BQ * NL];
// bf16 hi/lo feature banks (K-major, padded to 128 cols)
__device__ __nv_bfloat16 g_qhi[(size_t)BQ * 128];
__device__ __nv_bfloat16 g_qlo[(size_t)BQ * 128];
__device__ __nv_bfloat16 g_thi[(size_t)NTP * 128];
__device__ __nv_bfloat16 g_tlo[(size_t)NTP * 128];

// ---------------------------------------------------------------------------
// mma.sync bf16 helper (baseline sm_80+ instruction, no arch-accel needed)
// ---------------------------------------------------------------------------
__device__ __forceinline__ void mma_bf16(float* d, const uint32_t* a, const uint32_t* b)
{
    asm volatile(
        "mma.sync.aligned.m16n8k16.row.col.f32.bf16.bf16.f32 "
        "{%0,%1,%2,%3}, {%4,%5,%6,%7}, {%8,%9}, {%0,%1,%2,%3};"
        : "+f"(d[0]), "+f"(d[1]), "+f"(d[2]), "+f"(d[3])
        : "r"(a[0]), "r"(a[1]), "r"(a[2]), "r"(a[3]), "r"(b[0]), "r"(b[1]));
}

// ---------------------------------------------------------------------------
// Split-convert: fp32 features -> (hi, lo) bf16 banks, K padded w/ zeros.
// ---------------------------------------------------------------------------
__global__ void __launch_bounds__(256)
convert_kernel(const float* __restrict__ A, __nv_bfloat16* __restrict__ hi,
               __nv_bfloat16* __restrict__ lo, int Mreal, int Mpad, int D)
{
    int total = Mpad * 128;
    for (int i = blockIdx.x * 256 + threadIdx.x; i < total; i += gridDim.x * 256) {
        int row = i >> 7, col = i & 127;
        float x = (row < Mreal && col < D) ? A[(size_t)row * D + col] : 0.f;
        __nv_bfloat16 h = __float2bfloat16_rn(x);
        hi[i] = h;
        lo[i] = __float2bfloat16_rn(x - __bfloat162float(h));
    }
}

// ---------------------------------------------------------------------------
// Tensor-core bf16x3 distance GEMM:
//   S = Qhi·Thi^T + Qlo·Thi^T + Qhi·Tlo^T   (fp32 accum)
//   d2[m,n] = max(qn[m] + tn[n] - 2 S, 0)
// 128x128 tile / 256 threads; warp = 32(m) x 64(n); smem rows stride 24
// (48B) -> all fragment LDS.32 bank-conflict-free.
// ---------------------------------------------------------------------------
__global__ void __launch_bounds__(256)
mma_dist_kernel(const __nv_bfloat16* __restrict__ Qhi, const __nv_bfloat16* __restrict__ Qlo,
                const __nv_bfloat16* __restrict__ Thi, const __nv_bfloat16* __restrict__ Tlo,
                const float* __restrict__ qn, const float* __restrict__ tn,
                float* __restrict__ out, int KP)
{
    __shared__ __align__(16) __nv_bfloat16 As[128 * 24];
    __shared__ __align__(16) __nv_bfloat16 Bs[128 * 24];
    const int tid = threadIdx.x;
    const int wid = tid >> 5, lane = tid & 31;
    const int n0 = blockIdx.x * 128;
    const int m0 = blockIdx.y * 128;
    const int wm = (wid & 3) * 32;    // warp row offset in tile
    const int wn = (wid >> 2) * 64;   // warp col offset in tile

    const int lr = tid >> 1, lh = tid & 1;      // loader: row, 16B half
    const int fr = lane >> 2, fc = (lane & 3) * 2;  // fragment row/col

    float acc[2][8][4];
#pragma unroll
    for (int mt = 0; mt < 2; mt++)
#pragma unroll
        for (int nt = 0; nt < 8; nt++)
#pragma unroll
            for (int j = 0; j < 4; j++) acc[mt][nt][j] = 0.f;

#pragma unroll 1
    for (int seg = 0; seg < 3; seg++) {
        const __nv_bfloat16* Ap = (seg == 1) ? Qlo : Qhi;
        const __nv_bfloat16* Bp = (seg == 2) ? Tlo : Thi;
#pragma unroll 1
        for (int k0 = 0; k0 < KP; k0 += 16) {
            *(uint4*)&As[lr * 24 + lh * 8] =
                *(const uint4*)&Ap[(size_t)(m0 + lr) * 128 + k0 + lh * 8];
            *(uint4*)&Bs[lr * 24 + lh * 8] =
                *(const uint4*)&Bp[(size_t)(n0 + lr) * 128 + k0 + lh * 8];
            __syncthreads();

            uint32_t a[2][4];
#pragma unroll
            for (int mt = 0; mt < 2; mt++) {
                int base = wm + mt * 16;
                a[mt][0] = *(const uint32_t*)&As[(base + fr) * 24 + fc];
                a[mt][1] = *(const uint32_t*)&As[(base + fr + 8) * 24 + fc];
                a[mt][2] = *(const uint32_t*)&As[(base + fr) * 24 + fc + 8];
                a[mt][3] = *(const uint32_t*)&As[(base + fr + 8) * 24 + fc + 8];
            }
#pragma unroll
            for (int nt = 0; nt < 8; nt++) {
                uint32_t b[2];
                int nb = wn + nt * 8;
                b[0] = *(const uint32_t*)&Bs[(nb + fr) * 24 + fc];
                b[1] = *(const uint32_t*)&Bs[(nb + fr) * 24 + fc + 8];
                mma_bf16(acc[0][nt], a[0], b);
                mma_bf16(acc[1][nt], a[1], b);
            }
            __syncthreads();
        }
    }

    // epilogue: d2 = max(qn + tn - 2S, 0), written straight from fragments
#pragma unroll
    for (int mt = 0; mt < 2; mt++) {
        int mrow = m0 + wm + mt * 16 + fr;
        float q0 = qn[mrow], q1 = qn[mrow + 8];
#pragma unroll
        for (int nt = 0; nt < 8; nt++) {
            int n = n0 + wn + nt * 8 + fc;
            if (n < NT) {   // NT even, n even -> n+1 < NT too
                float t0 = tn[n], t1 = tn[n + 1];
                float2 o;
                o.x = fmaxf(q0 + t0 - 2.f * acc[mt][nt][0], 0.f);
                o.y = fmaxf(q0 + t1 - 2.f * acc[mt][nt][1], 0.f);
                *(float2*)&out[(size_t)mrow * NT + n] = o;
                o.x = fmaxf(q1 + t0 - 2.f * acc[mt][nt][2], 0.f);
                o.y = fmaxf(q1 + t1 - 2.f * acc[mt][nt][3], 0.f);
                *(float2*)&out[(size_t)(mrow + 8) * NT + n] = o;
            }
        }
    }
}

// ---------------------------------------------------------------------------
// Generic fused linear + ReLU:  out[M x 128] = relu(A[M x K] @ W[K x 128] + b)
// ---------------------------------------------------------------------------
__global__ void __launch_bounds__(256)
linear_relu_kernel(const float* __restrict__ A, const float* __restrict__ W,
                   const float* __restrict__ bias, float* __restrict__ out,
                   int M, int K)
{
    __shared__ __align__(16) float As[16 * 68];
    __shared__ __align__(16) float Bs[16 * 136];
    const int tx = threadIdx.x, ty = threadIdx.y;
    const int tid = ty * 16 + tx;
    const int m0 = blockIdx.x * 64;

    float acc[4][8];
#pragma unroll
    for (int r = 0; r < 4; r++)
#pragma unroll
        for (int c = 0; c < 8; c++) acc[r][c] = 0.f;

    const int nChunks = (K + 15) / 16;
    for (int ch = 0; ch < nChunks; ch++) {
        const int k0 = ch * 16;
#pragma unroll
        for (int i = 0; i < 4; i++) {
            int e = tid + i * 256;
            int k = e & 15, m = e >> 4;
            float v = 0.f;
            if (k0 + k < K && m0 + m < M) v = A[(size_t)(m0 + m) * K + k0 + k];
            As[k * 68 + m] = v;
        }
#pragma unroll
        for (int i = 0; i < 8; i++) {
            int e = tid + i * 256;
            int h = e & 127, k = e >> 7;
            float v = 0.f;
            if (k0 + k < K) v = W[(size_t)(k0 + k) * HD + h];
            Bs[k * 136 + h] = v;
        }
        __syncthreads();
#pragma unroll
        for (int k = 0; k < 16; k++) {
            float4 a  = *(const float4*)&As[k * 68 + ty * 4];
            float4 b0 = *(const float4*)&Bs[k * 136 + tx * 4];
            float4 b1 = *(const float4*)&Bs[k * 136 + 64 + tx * 4];
            float av[4] = {a.x, a.y, a.z, a.w};
            float bv[8] = {b0.x, b0.y, b0.z, b0.w, b1.x, b1.y, b1.z, b1.w};
#pragma unroll
            for (int r = 0; r < 4; r++)
#pragma unroll
                for (int c = 0; c < 8; c++) acc[r][c] += av[r] * bv[c];
        }
        __syncthreads();
    }
#pragma unroll
    for (int r = 0; r < 4; r++) {
        int m = m0 + ty * 4 + r;
        if (m >= M) continue;
#pragma unroll
        for (int half = 0; half < 2; half++) {
#pragma unroll
            for (int c = 0; c < 4; c++) {
                int h = half * 64 + tx * 4 + c;
                float v = acc[r][half * 4 + c] + bias[h];
                out[(size_t)m * HD + h] = fmaxf(v, 0.f);
            }
        }
    }
}

// ---------------------------------------------------------------------------
// Final linear + softmax: out[M x 8] = softmax(A[M x 128] @ W[128 x 8] + b)
// ---------------------------------------------------------------------------
__global__ void __launch_bounds__(256)
linear_softmax_kernel(const float* __restrict__ A, const float* __restrict__ W,
                      const float* __restrict__ bias, float* __restrict__ out, int M)
{
    __shared__ float Ws[HD * NL];
    __shared__ float bs[NL];
    int tid = threadIdx.x;
    for (int i = tid; i < HD * NL; i += 256) Ws[i] = W[i];
    if (tid < NL) bs[tid] = bias[tid];
    __syncthreads();

    int warp = tid >> 5, lane = tid & 31;
    int m = blockIdx.x * 8 + warp;
    if (m >= M) return;

    float acc[NL];
#pragma unroll
    for (int h = 0; h < NL; h++) acc[h] = 0.f;
    for (int k = lane; k < HD; k += 32) {
        float x = A[(size_t)m * HD + k];
#pragma unroll
        for (int h = 0; h < NL; h++) acc[h] += x * Ws[k * NL + h];
    }
#pragma unroll
    for (int h = 0; h < NL; h++)
#pragma unroll
        for (int off = 16; off > 0; off >>= 1)
            acc[h] += __shfl_down_sync(0xFFFFFFFFu, acc[h], off);

    if (lane == 0) {
        float v[NL], mx = -1e30f;
#pragma unroll
        for (int h = 0; h < NL; h++) { v[h] = acc[h] + bs[h]; mx = fmaxf(mx, v[h]); }
        float s = 0.f;
#pragma unroll
        for (int h = 0; h < NL; h++) { v[h] = expf(v[h] - mx); s += v[h]; }
        float inv = 1.0f / s;
#pragma unroll
        for (int h = 0; h < NL; h++) out[(size_t)m * NL + h] = v[h] * inv;
    }
}

// ---------------------------------------------------------------------------
__global__ void __launch_bounds__(256)
rownorm_kernel(const float* __restrict__ A, float* __restrict__ out, int M, int D)
{
    int warp = threadIdx.x >> 5, lane = threadIdx.x & 31;
    int m = blockIdx.x * 8 + warp;
    if (m >= M) return;
    float s = 0.f;
    for (int k = lane; k < D; k += 32) { float v = A[(size_t)m * D + k]; s += v * v; }
#pragma unroll
    for (int off = 16; off > 0; off >>= 1) s += __shfl_down_sync(0xFFFFFFFFu, s, off);
    if (lane == 0) out[m] = s;
}

// ---------------------------------------------------------------------------
// SIMT fp32 distance GEMM (layer 4, D=8, precision-critical)
// ---------------------------------------------------------------------------
__global__ void __launch_bounds__(256)
dist_kernel(const float* __restrict__ Q, const float* __restrict__ T,
            const float* __restrict__ qn, const float* __restrict__ tn,
            float* __restrict__ out, int D, int Ncols)
{
    __shared__ __align__(16) float As[16 * 68];
    __shared__ __align__(16) float Bs[16 * 136];
    const int tx = threadIdx.x, ty = threadIdx.y;
    const int tid = ty * 16 + tx;
    const int n0 = blockIdx.x * 128;
    const int m0 = blockIdx.y * 64;

    float acc[4][8];
#pragma unroll
    for (int r = 0; r < 4; r++)
#pragma unroll
        for (int c = 0; c < 8; c++) acc[r][c] = 0.f;

    const int nChunks = (D + 15) / 16;
    for (int ch = 0; ch < nChunks; ch++) {
        const int k0 = ch * 16;
#pragma unroll
        for (int i = 0; i < 4; i++) {
            int e = tid + i * 256;
            int k = e & 15, m = e >> 4;
            float v = (k0 + k < D) ? Q[(size_t)(m0 + m) * D + k0 + k] : 0.f;
            As[k * 68 + m] = v;
        }
#pragma unroll
        for (int i = 0; i < 8; i++) {
            int e = tid + i * 256;
            int k = e & 15, n = e >> 4;
            int gn = n0 + n;
            float v = 0.f;
            if (k0 + k < D && gn < Ncols) v = T[(size_t)gn * D + k0 + k];
            Bs[k * 136 + n] = v;
        }
        __syncthreads();
#pragma unroll
        for (int k = 0; k < 16; k++) {
            float4 a  = *(const float4*)&As[k * 68 + ty * 4];
            float4 b0 = *(const float4*)&Bs[k * 136 + tx * 4];
            float4 b1 = *(const float4*)&Bs[k * 136 + 64 + tx * 4];
            float av[4] = {a.x, a.y, a.z, a.w};
            float bv[8] = {b0.x, b0.y, b0.z, b0.w, b1.x, b1.y, b1.z, b1.w};
#pragma unroll
            for (int r = 0; r < 4; r++)
#pragma unroll
                for (int c = 0; c < 8; c++) acc[r][c] += av[r] * bv[c];
        }
        __syncthreads();
    }
#pragma unroll
    for (int r = 0; r < 4; r++) {
        int m = m0 + ty * 4 + r;
        float qv = qn[m];
#pragma unroll
        for (int half = 0; half < 2; half++) {
#pragma unroll
            for (int c = 0; c < 4; c++) {
                int n = n0 + half * 64 + tx * 4 + c;
                if (n < Ncols) {
                    float d = qv + tn[n] - 2.f * acc[r][half * 4 + c];
                    out[(size_t)m * Ncols + n] = fmaxf(d, 0.f);
                }
            }
        }
    }
}

// ---------------------------------------------------------------------------
// Per-query exact top-K radix select + weighted per-class accumulation.
// ---------------------------------------------------------------------------
#define SELECT_SMEM ((NT + 256 + 256 * 9) * 4)

__global__ void __launch_bounds__(256)
select_kernel(const float* __restrict__ d2mat, const int* __restrict__ labels,
              float* __restrict__ total, int init)
{
    extern __shared__ __align__(16) float sm[];
    float*    row  = sm;
    unsigned* hist = (unsigned*)(sm + NT);
    float*    acc  = sm + NT + 256;

    __shared__ unsigned s_prefix, s_kth, s_eqcnt, s_cless;
    __shared__ int s_eqidx[64];
    __shared__ float s_sums[9];

    const int b = blockIdx.x;
    const int tid = threadIdx.x;
    const int lane = tid & 31;

    const float4* src = (const float4*)(d2mat + (size_t)b * NT);
    float4* dst = (float4*)row;
    for (int i = tid; i < NT / 4; i += 256) dst[i] = src[i];
    if (tid == 0) { s_eqcnt = 0; s_cless = 0; }
    __syncthreads();

    unsigned prefix = 0, kth = KNN;
    const int PADN = ((NT + 255) / 256) * 256;
    for (int shift = 24; shift >= 0; shift -= 8) {
        hist[tid] = 0;
        __syncthreads();
        unsigned maskAbove = (shift == 24) ? 0u : (0xFFFFFFFFu << (shift + 8));
        for (int i = tid; i < PADN; i += 256) {
            unsigned bin = 0xFFFFFFFFu;
            if (i < NT) {
                unsigned key = __float_as_uint(row[i]);
                if ((key & maskAbove) == prefix) bin = (key >> shift) & 0xFF;
            }
            unsigned grp = __match_any_sync(0xFFFFFFFFu, bin);
            int leader = __ffs(grp) - 1;
            if (bin != 0xFFFFFFFFu && lane == leader)
                atomicAdd(&hist[bin], (unsigned)__popc(grp));
        }
        __syncthreads();
        if (tid == 0) {
            unsigned a = 0;
            for (int bin = 0; bin < 256; bin++) {
                unsigned c = hist[bin];
                if (a + c >= kth) { s_prefix = prefix | ((unsigned)bin << shift);
                                    s_kth = kth - a; break; }
                a += c;
            }
        }
        __syncthreads();
        prefix = s_prefix; kth = s_kth;
    }
    const unsigned Tkey = prefix;

#pragma unroll
    for (int j = 0; j < 9; j++) acc[tid * 9 + j] = 0.f;
    float sT = 0.f;
    unsigned cless = 0;
    for (int i = tid; i < NT; i += 256) {
        float d2 = row[i];
        unsigned key = __float_as_uint(d2);
        if (key < Tkey) {
            float w = (d2 > 0.f) ? __fdiv_rn(1.0f, __fsqrt_rn(d2)) : 0.f;
            sT += w;
            acc[tid * 9 + labels[i]] += w;
            cless++;
        } else if (key == Tkey) {
            unsigned slot = atomicAdd(&s_eqcnt, 1u);
            if (slot < 64) s_eqidx[slot] = i;
        }
    }
    acc[tid * 9 + 8] = sT;
    atomicAdd(&s_cless, cless);
    __syncthreads();

    if (tid < 9) {
        float s = 0.f;
        for (int t = 0; t < 256; t++) s += acc[t * 9 + tid];
        s_sums[tid] = s;
    }
    __syncthreads();

    if (tid == 0) {
        int need = KNN - (int)s_cless;
        int ne = (int)s_eqcnt; if (ne > 64) ne = 64;
        for (int a2 = 1; a2 < ne; a2++) {
            int v = s_eqidx[a2]; int j = a2 - 1;
            while (j >= 0 && s_eqidx[j] > v) { s_eqidx[j + 1] = s_eqidx[j]; j--; }
            s_eqidx[j + 1] = v;
        }
        float d2T = __uint_as_float(Tkey);
        float wT = (d2T > 0.f) ? __fdiv_rn(1.0f, __fsqrt_rn(d2T)) : 0.f;
        float cls[NL];
#pragma unroll
        for (int l = 0; l < NL; l++) cls[l] = s_sums[l];
        float stot = s_sums[8];
        for (int j = 0; j < need && j < ne; j++) {
            stot += wT;
            cls[labels[s_eqidx[j]]] += wT;
        }
#pragma unroll
        for (int l = 0; l < NL; l++) {
            float val = stot - cls[l];
            size_t o = (size_t)b * NL + l;
            if (init) total[o] = val; else total[o] += val;
        }
    }
}

// ---------------------------------------------------------------------------
__global__ void __launch_bounds__(256)
pvalue_kernel(const float* __restrict__ total, const float* __restrict__ cali,
              float* __restrict__ out)
{
    const int b = blockIdx.x, tid = threadIdx.x;
    float t[NL];
#pragma unroll
    for (int l = 0; l < NL; l++) t[l] = total[(size_t)b * NL + l];
    int cnt[NL];
#pragma unroll
    for (int l = 0; l < NL; l++) cnt[l] = 0;
    for (int i = tid; i < NC; i += 256) {
        float c = cali[i];
#pragma unroll
        for (int l = 0; l < NL; l++) cnt[l] += (c >= t[l]) ? 1 : 0;
    }
    __shared__ int sc[NL];
    if (tid < NL) sc[tid] = 0;
    __syncthreads();
#pragma unroll
    for (int l = 0; l < NL; l++) atomicAdd(&sc[l], cnt[l]);
    __syncthreads();
    if (tid < NL) out[(size_t)b * NL + tid] = (float)sc[tid] * (1.0f / NC);
}

// ---------------------------------------------------------------------------
extern "C" void kernel_launch(void* const* d_in, const int* in_sizes, int n_in,
                              void* d_out, int out_size)
{
    const float* x        = (const float*)d_in[0];
    const float* train_x  = (const float*)d_in[1];
    const int*   lab      = (const int*)  d_in[2];
    const float* cali     = (const float*)d_in[3];
    const float* W1 = (const float*)d_in[4];  const float* b1 = (const float*)d_in[5];
    const float* W2 = (const float*)d_in[6];  const float* b2 = (const float*)d_in[7];
    const float* W3 = (const float*)d_in[8];  const float* b3 = (const float*)d_in[9];
    const float* W4 = (const float*)d_in[10]; const float* b4 = (const float*)d_in[11];
    float* out = (float*)d_out;

    float *h1p, *h2p, *h3p, *q4p, *t1p, *t2p, *t3p, *t4p, *d2p, *qnp, *tnp, *totp;
    __nv_bfloat16 *qhip, *qlop, *thip, *tlop;
    cudaGetSymbolAddress((void**)&h1p, g_h1);
    cudaGetSymbolAddress((void**)&h2p, g_h2);
    cudaGetSymbolAddress((void**)&h3p, g_h3);
    cudaGetSymbolAddress((void**)&q4p, g_q4);
    cudaGetSymbolAddress((void**)&t1p, g_t1);
    cudaGetSymbolAddress((void**)&t2p, g_t2);
    cudaGetSymbolAddress((void**)&t3p, g_t3);
    cudaGetSymbolAddress((void**)&t4p, g_t4);
    cudaGetSymbolAddress((void**)&d2p, g_d2);
    cudaGetSymbolAddress((void**)&qnp, g_qn);
    cudaGetSymbolAddress((void**)&tnp, g_tn);
    cudaGetSymbolAddress((void**)&totp, g_tot);
    cudaGetSymbolAddress((void**)&qhip, g_qhi);
    cudaGetSymbolAddress((void**)&qlop, g_qlo);
    cudaGetSymbolAddress((void**)&thip, g_thi);
    cudaGetSymbolAddress((void**)&tlop, g_tlo);

    cudaFuncSetAttribute(select_kernel,
                         cudaFuncAttributeMaxDynamicSharedMemorySize, SELECT_SMEM);

    dim3 tb(16, 16);
    const int D0 = 83;

    // query-side MLP
    linear_relu_kernel<<<BQ / 64, tb>>>(x,   W1, b1, h1p, BQ, D0);
    linear_relu_kernel<<<BQ / 64, tb>>>(h1p, W2, b2, h2p, BQ, HD);
    linear_relu_kernel<<<BQ / 64, tb>>>(h2p, W3, b3, h3p, BQ, HD);
    linear_softmax_kernel<<<(BQ + 7) / 8, 256>>>(h3p, W4, b4, q4p, BQ);

    // train-side feature banks
    const int gtm = (NT + 63) / 64;
    linear_relu_kernel<<<gtm, tb>>>(train_x, W1, b1, t1p, NT, D0);
    linear_relu_kernel<<<gtm, tb>>>(t1p,     W2, b2, t2p, NT, HD);
    linear_relu_kernel<<<gtm, tb>>>(t2p,     W3, b3, t3p, NT, HD);
    linear_softmax_kernel<<<(NT + 7) / 8, 256>>>(t3p, W4, b4, t4p, NT);

    // layers 0-3: tensor-core bf16x3 distance GEMM
    const float* Qs[4] = {x, h1p, h2p, h3p};
    const float* Ts[4] = {train_x, t1p, t2p, t3p};
    const int    Ds[4] = {D0, HD, HD, HD};
    const int    KPs[4] = {96, 128, 128, 128};
    for (int i = 0; i < 4; i++) {
        rownorm_kernel<<<(BQ + 7) / 8, 256>>>(Qs[i], qnp, BQ, Ds[i]);
        rownorm_kernel<<<(NT + 7) / 8, 256>>>(Ts[i], tnp, NT, Ds[i]);
        convert_kernel<<<(BQ * 128 + 255) / 256, 256>>>(Qs[i], qhip, qlop, BQ, BQ, Ds[i]);
        convert_kernel<<<(NTP * 128 + 255) / 256, 256>>>(Ts[i], thip, tlop, NT, NTP, Ds[i]);
        mma_dist_kernel<<<dim3(NTP / 128, BQ / 128), 256>>>(
            qhip, qlop, thip, tlop, qnp, tnp, d2p, KPs[i]);
        select_kernel<<<BQ, 256, SELECT_SMEM>>>(d2p, lab, totp, (i == 0) ? 1 : 0);
    }

    // layer 4 (softmax features, D=8): exact fp32 path
    rownorm_kernel<<<(BQ + 7) / 8, 256>>>(q4p, qnp, BQ, NL);
    rownorm_kernel<<<(NT + 7) / 8, 256>>>(t4p, tnp, NT, NL);
    dist_kernel<<<dim3((NT + 127) / 128, BQ / 64), tb>>>(q4p, t4p, qnp, tnp, d2p, NL, NT);
    select_kernel<<<BQ, 256, SELECT_SMEM>>>(d2p, lab, totp, 0);

    // p-values
    pvalue_kernel<<<BQ, 256>>>(totp, cali, out);
}

// round 4
// speedup vs baseline: 1.7426x; 1.5664x over previous
#include <cuda_runtime.h>
#include <cuda_bf16.h>
#include <math.h>
#include <stdint.h>

#define BQ   1024
#define NT   50000
#define NTP  50048          // NT padded to multiple of 128
#define NL   8
#define KNN  75
#define HD   128
#define NC   10000

// ---------------- device scratch (no runtime allocation allowed) ----------------
__device__ float g_h1[BQ * HD];
__device__ float g_h2[BQ * HD];
__device__ float g_h3[BQ * HD];
__device__ float g_q4[BQ * NL];
__device__ float g_t1[(size_t)NT * HD];
__device__ float g_t2[(size_t)NT * HD];
__device__ float g_t3[(size_t)NT * HD];
__device__ float g_t4[(size_t)NT * NL];
__device__ float g_d2[(size_t)BQ * NT];   // 204.8 MB distance scratch
__device__ float g_qn[BQ];
__device__ float g_tn[NT];
__device__ float g_tot[BQ * NL];
// bf16 hi/lo feature banks (K-major, padded to 128 cols)
__device__ __nv_bfloat16 g_qhi[(size_t)BQ * 128];
__device__ __nv_bfloat16 g_qlo[(size_t)BQ * 128];
__device__ __nv_bfloat16 g_thi[(size_t)NTP * 128];
__device__ __nv_bfloat16 g_tlo[(size_t)NTP * 128];

// ---------------------------------------------------------------------------
// mma.sync bf16 helper (baseline sm_80+ instruction)
// ---------------------------------------------------------------------------
__device__ __forceinline__ void mma_bf16(float* d, const uint32_t* a, const uint32_t* b)
{
    asm volatile(
        "mma.sync.aligned.m16n8k16.row.col.f32.bf16.bf16.f32 "
        "{%0,%1,%2,%3}, {%4,%5,%6,%7}, {%8,%9}, {%0,%1,%2,%3};"
        : "+f"(d[0]), "+f"(d[1]), "+f"(d[2]), "+f"(d[3])
        : "r"(a[0]), "r"(a[1]), "r"(a[2]), "r"(a[3]), "r"(b[0]), "r"(b[1]));
}

// ---------------------------------------------------------------------------
// Fused split-convert + row norm. One warp per row; rows >= Mreal are zeroed.
// hi/lo layout: [row, 0..127] K-major padded.
// ---------------------------------------------------------------------------
__global__ void __launch_bounds__(256)
conv_norm_kernel(const float* __restrict__ A, __nv_bfloat16* __restrict__ hi,
                 __nv_bfloat16* __restrict__ lo, float* __restrict__ nrm,
                 int Mreal, int D)
{
    int warp = threadIdx.x >> 5, lane = threadIdx.x & 31;
    int row = blockIdx.x * 8 + warp;
    int base = lane * 4;

    float x[4], ss = 0.f;
    __nv_bfloat16 hb[4], lb[4];
#pragma unroll
    for (int j = 0; j < 4; j++) {
        int col = base + j;
        float v = (row < Mreal && col < D) ? A[(size_t)row * D + col] : 0.f;
        x[j] = v;
        ss += v * v;
        hb[j] = __float2bfloat16_rn(v);
        lb[j] = __float2bfloat16_rn(v - __bfloat162float(hb[j]));
    }
    __nv_bfloat162 h01, h23, l01, l23;
    h01.x = hb[0]; h01.y = hb[1]; h23.x = hb[2]; h23.y = hb[3];
    l01.x = lb[0]; l01.y = lb[1]; l23.x = lb[2]; l23.y = lb[3];
    *(__nv_bfloat162*)&hi[(size_t)row * 128 + base]     = h01;
    *(__nv_bfloat162*)&hi[(size_t)row * 128 + base + 2] = h23;
    *(__nv_bfloat162*)&lo[(size_t)row * 128 + base]     = l01;
    *(__nv_bfloat162*)&lo[(size_t)row * 128 + base + 2] = l23;

#pragma unroll
    for (int off = 16; off > 0; off >>= 1) ss += __shfl_down_sync(0xFFFFFFFFu, ss, off);
    if (lane == 0 && row < Mreal) nrm[row] = ss;
}

// ---------------------------------------------------------------------------
// Tensor-core bf16x3 distance GEMM with cp.async double buffering.
// ---------------------------------------------------------------------------
__device__ __forceinline__ void tile_load_async(
    const __nv_bfloat16* __restrict__ Ap, const __nv_bfloat16* __restrict__ Bp,
    __nv_bfloat16* As, __nv_bfloat16* Bs, int m0, int n0, int k0, int lr, int lh)
{
    uint32_t sa = (uint32_t)__cvta_generic_to_shared(As + lr * 24 + lh * 8);
    uint32_t sb = (uint32_t)__cvta_generic_to_shared(Bs + lr * 24 + lh * 8);
    const void* ga = Ap + (size_t)(m0 + lr) * 128 + k0 + lh * 8;
    const void* gb = Bp + (size_t)(n0 + lr) * 128 + k0 + lh * 8;
    asm volatile(
        "cp.async.cg.shared.global [%0], [%1], 16;\n\t"
        "cp.async.cg.shared.global [%2], [%3], 16;\n\t"
        "cp.async.commit_group;\n"
        :: "r"(sa), "l"(ga), "r"(sb), "l"(gb));
}

__global__ void __launch_bounds__(256)
mma_dist_kernel(const __nv_bfloat16* __restrict__ Qhi, const __nv_bfloat16* __restrict__ Qlo,
                const __nv_bfloat16* __restrict__ Thi, const __nv_bfloat16* __restrict__ Tlo,
                const float* __restrict__ qn, const float* __restrict__ tn,
                float* __restrict__ out, int KP)
{
    __shared__ __align__(16) __nv_bfloat16 As[2][128 * 24];
    __shared__ __align__(16) __nv_bfloat16 Bs[2][128 * 24];
    const int tid = threadIdx.x;
    const int wid = tid >> 5, lane = tid & 31;
    const int n0 = blockIdx.x * 128;
    const int m0 = blockIdx.y * 128;
    const int wm = (wid & 3) * 32;
    const int wn = (wid >> 2) * 64;

    const int lr = tid >> 1, lh = tid & 1;
    const int fr = lane >> 2, fc = (lane & 3) * 2;

    float acc[2][8][4];
#pragma unroll
    for (int mt = 0; mt < 2; mt++)
#pragma unroll
        for (int nt = 0; nt < 8; nt++)
#pragma unroll
            for (int j = 0; j < 4; j++) acc[mt][nt][j] = 0.f;

    const int SPS = KP >> 4;
    const int S = 3 * SPS;

    tile_load_async(Qhi, Thi, As[0], Bs[0], m0, n0, 0, lr, lh);

    int nseg = 0, nk = 16;   // state for step s+1
    for (int s = 0; s < S; s++) {
        int buf = s & 1;
        if (s + 1 < S) {
            if (nk == KP) { nk = 0; nseg++; }
            const __nv_bfloat16* Ap = (nseg == 1) ? Qlo : Qhi;
            const __nv_bfloat16* Bp = (nseg == 2) ? Tlo : Thi;
            tile_load_async(Ap, Bp, As[buf ^ 1], Bs[buf ^ 1], m0, n0, nk, lr, lh);
            nk += 16;
            asm volatile("cp.async.wait_group 1;" ::: "memory");
        } else {
            asm volatile("cp.async.wait_group 0;" ::: "memory");
        }
        __syncthreads();

        const __nv_bfloat16* Ab = As[buf];
        const __nv_bfloat16* Bb = Bs[buf];
        uint32_t a[2][4];
#pragma unroll
        for (int mt = 0; mt < 2; mt++) {
            int basem = wm + mt * 16;
            a[mt][0] = *(const uint32_t*)&Ab[(basem + fr) * 24 + fc];
            a[mt][1] = *(const uint32_t*)&Ab[(basem + fr + 8) * 24 + fc];
            a[mt][2] = *(const uint32_t*)&Ab[(basem + fr) * 24 + fc + 8];
            a[mt][3] = *(const uint32_t*)&Ab[(basem + fr + 8) * 24 + fc + 8];
        }
#pragma unroll
        for (int nt = 0; nt < 8; nt++) {
            uint32_t b[2];
            int nb = wn + nt * 8;
            b[0] = *(const uint32_t*)&Bb[(nb + fr) * 24 + fc];
            b[1] = *(const uint32_t*)&Bb[(nb + fr) * 24 + fc + 8];
            mma_bf16(acc[0][nt], a[0], b);
            mma_bf16(acc[1][nt], a[1], b);
        }
        __syncthreads();
    }

    // epilogue: d2 = max(qn + tn - 2S, 0)
#pragma unroll
    for (int mt = 0; mt < 2; mt++) {
        int mrow = m0 + wm + mt * 16 + fr;
        float q0 = qn[mrow], q1 = qn[mrow + 8];
#pragma unroll
        for (int nt = 0; nt < 8; nt++) {
            int n = n0 + wn + nt * 8 + fc;
            if (n < NT) {
                float t0 = tn[n], t1 = tn[n + 1];
                float2 o;
                o.x = fmaxf(q0 + t0 - 2.f * acc[mt][nt][0], 0.f);
                o.y = fmaxf(q0 + t1 - 2.f * acc[mt][nt][1], 0.f);
                *(float2*)&out[(size_t)mrow * NT + n] = o;
                o.x = fmaxf(q1 + t0 - 2.f * acc[mt][nt][2], 0.f);
                o.y = fmaxf(q1 + t1 - 2.f * acc[mt][nt][3], 0.f);
                *(float2*)&out[(size_t)(mrow + 8) * NT + n] = o;
            }
        }
    }
}

// ---------------------------------------------------------------------------
// Generic fused linear + ReLU:  out[M x 128] = relu(A[M x K] @ W[K x 128] + b)
// ---------------------------------------------------------------------------
__global__ void __launch_bounds__(256)
linear_relu_kernel(const float* __restrict__ A, const float* __restrict__ W,
                   const float* __restrict__ bias, float* __restrict__ out,
                   int M, int K)
{
    __shared__ __align__(16) float As[16 * 68];
    __shared__ __align__(16) float Bs[16 * 136];
    const int tx = threadIdx.x, ty = threadIdx.y;
    const int tid = ty * 16 + tx;
    const int m0 = blockIdx.x * 64;

    float acc[4][8];
#pragma unroll
    for (int r = 0; r < 4; r++)
#pragma unroll
        for (int c = 0; c < 8; c++) acc[r][c] = 0.f;

    const int nChunks = (K + 15) / 16;
    for (int ch = 0; ch < nChunks; ch++) {
        const int k0 = ch * 16;
#pragma unroll
        for (int i = 0; i < 4; i++) {
            int e = tid + i * 256;
            int k = e & 15, m = e >> 4;
            float v = 0.f;
            if (k0 + k < K && m0 + m < M) v = A[(size_t)(m0 + m) * K + k0 + k];
            As[k * 68 + m] = v;
        }
#pragma unroll
        for (int i = 0; i < 8; i++) {
            int e = tid + i * 256;
            int h = e & 127, k = e >> 7;
            float v = 0.f;
            if (k0 + k < K) v = W[(size_t)(k0 + k) * HD + h];
            Bs[k * 136 + h] = v;
        }
        __syncthreads();
#pragma unroll
        for (int k = 0; k < 16; k++) {
            float4 a  = *(const float4*)&As[k * 68 + ty * 4];
            float4 b0 = *(const float4*)&Bs[k * 136 + tx * 4];
            float4 b1 = *(const float4*)&Bs[k * 136 + 64 + tx * 4];
            float av[4] = {a.x, a.y, a.z, a.w};
            float bv[8] = {b0.x, b0.y, b0.z, b0.w, b1.x, b1.y, b1.z, b1.w};
#pragma unroll
            for (int r = 0; r < 4; r++)
#pragma unroll
                for (int c = 0; c < 8; c++) acc[r][c] += av[r] * bv[c];
        }
        __syncthreads();
    }
#pragma unroll
    for (int r = 0; r < 4; r++) {
        int m = m0 + ty * 4 + r;
        if (m >= M) continue;
#pragma unroll
        for (int half = 0; half < 2; half++) {
#pragma unroll
            for (int c = 0; c < 4; c++) {
                int h = half * 64 + tx * 4 + c;
                float v = acc[r][half * 4 + c] + bias[h];
                out[(size_t)m * HD + h] = fmaxf(v, 0.f);
            }
        }
    }
}

// ---------------------------------------------------------------------------
// Final linear + softmax: out[M x 8] = softmax(A[M x 128] @ W[128 x 8] + b)
// ---------------------------------------------------------------------------
__global__ void __launch_bounds__(256)
linear_softmax_kernel(const float* __restrict__ A, const float* __restrict__ W,
                      const float* __restrict__ bias, float* __restrict__ out, int M)
{
    __shared__ float Ws[HD * NL];
    __shared__ float bs[NL];
    int tid = threadIdx.x;
    for (int i = tid; i < HD * NL; i += 256) Ws[i] = W[i];
    if (tid < NL) bs[tid] = bias[tid];
    __syncthreads();

    int warp = tid >> 5, lane = tid & 31;
    int m = blockIdx.x * 8 + warp;
    if (m >= M) return;

    float acc[NL];
#pragma unroll
    for (int h = 0; h < NL; h++) acc[h] = 0.f;
    for (int k = lane; k < HD; k += 32) {
        float x = A[(size_t)m * HD + k];
#pragma unroll
        for (int h = 0; h < NL; h++) acc[h] += x * Ws[k * NL + h];
    }
#pragma unroll
    for (int h = 0; h < NL; h++)
#pragma unroll
        for (int off = 16; off > 0; off >>= 1)
            acc[h] += __shfl_down_sync(0xFFFFFFFFu, acc[h], off);

    if (lane == 0) {
        float v[NL], mx = -1e30f;
#pragma unroll
        for (int h = 0; h < NL; h++) { v[h] = acc[h] + bs[h]; mx = fmaxf(mx, v[h]); }
        float s = 0.f;
#pragma unroll
        for (int h = 0; h < NL; h++) { v[h] = expf(v[h] - mx); s += v[h]; }
        float inv = 1.0f / s;
#pragma unroll
        for (int h = 0; h < NL; h++) out[(size_t)m * NL + h] = v[h] * inv;
    }
}

// ---------------------------------------------------------------------------
__global__ void __launch_bounds__(256)
rownorm_kernel(const float* __restrict__ A, float* __restrict__ out, int M, int D)
{
    int warp = threadIdx.x >> 5, lane = threadIdx.x & 31;
    int m = blockIdx.x * 8 + warp;
    if (m >= M) return;
    float s = 0.f;
    for (int k = lane; k < D; k += 32) { float v = A[(size_t)m * D + k]; s += v * v; }
#pragma unroll
    for (int off = 16; off > 0; off >>= 1) s += __shfl_down_sync(0xFFFFFFFFu, s, off);
    if (lane == 0) out[m] = s;
}

// ---------------------------------------------------------------------------
// SIMT fp32 distance GEMM (layer 4, D=8, precision-critical)
// ---------------------------------------------------------------------------
__global__ void __launch_bounds__(256)
dist_kernel(const float* __restrict__ Q, const float* __restrict__ T,
            const float* __restrict__ qn, const float* __restrict__ tn,
            float* __restrict__ out, int D, int Ncols)
{
    __shared__ __align__(16) float As[16 * 68];
    __shared__ __align__(16) float Bs[16 * 136];
    const int tx = threadIdx.x, ty = threadIdx.y;
    const int tid = ty * 16 + tx;
    const int n0 = blockIdx.x * 128;
    const int m0 = blockIdx.y * 64;

    float acc[4][8];
#pragma unroll
    for (int r = 0; r < 4; r++)
#pragma unroll
        for (int c = 0; c < 8; c++) acc[r][c] = 0.f;

    const int nChunks = (D + 15) / 16;
    for (int ch = 0; ch < nChunks; ch++) {
        const int k0 = ch * 16;
#pragma unroll
        for (int i = 0; i < 4; i++) {
            int e = tid + i * 256;
            int k = e & 15, m = e >> 4;
            float v = (k0 + k < D) ? Q[(size_t)(m0 + m) * D + k0 + k] : 0.f;
            As[k * 68 + m] = v;
        }
#pragma unroll
        for (int i = 0; i < 8; i++) {
            int e = tid + i * 256;
            int k = e & 15, n = e >> 4;
            int gn = n0 + n;
            float v = 0.f;
            if (k0 + k < D && gn < Ncols) v = T[(size_t)gn * D + k0 + k];
            Bs[k * 136 + n] = v;
        }
        __syncthreads();
#pragma unroll
        for (int k = 0; k < 16; k++) {
            float4 a  = *(const float4*)&As[k * 68 + ty * 4];
            float4 b0 = *(const float4*)&Bs[k * 136 + tx * 4];
            float4 b1 = *(const float4*)&Bs[k * 136 + 64 + tx * 4];
            float av[4] = {a.x, a.y, a.z, a.w};
            float bv[8] = {b0.x, b0.y, b0.z, b0.w, b1.x, b1.y, b1.z, b1.w};
#pragma unroll
            for (int r = 0; r < 4; r++)
#pragma unroll
                for (int c = 0; c < 8; c++) acc[r][c] += av[r] * bv[c];
        }
        __syncthreads();
    }
#pragma unroll
    for (int r = 0; r < 4; r++) {
        int m = m0 + ty * 4 + r;
        float qv = qn[m];
#pragma unroll
        for (int half = 0; half < 2; half++) {
#pragma unroll
            for (int c = 0; c < 4; c++) {
                int n = n0 + half * 64 + tx * 4 + c;
                if (n < Ncols) {
                    float d = qv + tn[n] - 2.f * acc[r][half * 4 + c];
                    out[(size_t)m * Ncols + n] = fmaxf(d, 0.f);
                }
            }
        }
    }
}

// ---------------------------------------------------------------------------
// Exact top-K radix select (12/12/8 bits), 512 threads, 4 fused scans.
// ---------------------------------------------------------------------------
#define SEL_THREADS 512
#define SEL_SMEM (NT * 4 + 4096 * 4 + 64)

__device__ __forceinline__ void find_kth(const unsigned* hist, int NB, unsigned kth,
                                         int tid, unsigned* s_bin, unsigned* s_kthr)
{
    if (tid < 32) {
        unsigned running = 0;
        for (int base = 0; base < NB; base += 32) {
            unsigned v = hist[base + tid];
            unsigned sc = v;
#pragma unroll
            for (int off = 1; off < 32; off <<= 1) {
                unsigned t = __shfl_up_sync(0xFFFFFFFFu, sc, off);
                if (tid >= off) sc += t;
            }
            unsigned tot = __shfl_sync(0xFFFFFFFFu, sc, 31);
            if (running + tot >= kth) {
                unsigned mask = __ballot_sync(0xFFFFFFFFu, running + sc >= kth);
                int l = __ffs(mask) - 1;
                if (tid == l) { *s_bin = (unsigned)(base + l); *s_kthr = kth - running - (sc - v); }
                break;
            }
            running += tot;
        }
    }
}

__global__ void __launch_bounds__(SEL_THREADS)
select_kernel(const float* __restrict__ d2mat, const int* __restrict__ labels,
              float* __restrict__ total, int init)
{
    extern __shared__ __align__(16) float sm[];
    float*    row  = sm;
    unsigned* hist = (unsigned*)(sm + NT);

    __shared__ unsigned s_bin, s_kthr, s_selcnt, s_eqcnt;
    __shared__ int s_selidx[96], s_eqidx[96], s_l2[96];
    __shared__ float s_w2[96], s_cls[NL];

    const int b = blockIdx.x, tid = threadIdx.x, lane = tid & 31;

    for (int i = tid; i < 4096; i += SEL_THREADS) hist[i] = 0;
    if (tid == 0) { s_selcnt = 0; s_eqcnt = 0; }
    if (tid < NL) s_cls[tid] = 0.f;
    __syncthreads();

    // ---- scan 1: gmem load + 12-bit histogram (bins = key >> 20) ----
    const float4* src = (const float4*)(d2mat + (size_t)b * NT);
    const int nIt4 = (NT / 4 + SEL_THREADS - 1) / SEL_THREADS;
    for (int it = 0; it < nIt4; it++) {
        int i = it * SEL_THREADS + tid;
        bool valid = (i < NT / 4);
        float4 v = valid ? src[i] : make_float4(0.f, 0.f, 0.f, 0.f);
        if (valid) ((float4*)row)[i] = v;
        float e[4] = {v.x, v.y, v.z, v.w};
#pragma unroll
        for (int j = 0; j < 4; j++) {
            unsigned bin = valid ? (__float_as_uint(e[j]) >> 20) : 0xFFFFFFFFu;
            unsigned grp = __match_any_sync(0xFFFFFFFFu, bin);
            if (bin != 0xFFFFFFFFu && lane == __ffs(grp) - 1)
                atomicAdd(&hist[bin], (unsigned)__popc(grp));
        }
    }
    __syncthreads();
    find_kth(hist, 4096, KNN, tid, &s_bin, &s_kthr);
    __syncthreads();
    const unsigned pfx12 = s_bin;
    unsigned kth = s_kthr;

    for (int i = tid; i < 4096; i += SEL_THREADS) hist[i] = 0;
    __syncthreads();

    // ---- scan 2: 12-bit pass (bins = bits [8,20)) ----
    for (int it = 0; it < nIt4; it++) {
        int i = it * SEL_THREADS + tid;
        bool valid = (i < NT / 4);
        float4 v = valid ? ((const float4*)row)[i] : make_float4(0.f, 0.f, 0.f, 0.f);
        float e[4] = {v.x, v.y, v.z, v.w};
#pragma unroll
        for (int j = 0; j < 4; j++) {
            unsigned key = __float_as_uint(e[j]);
            unsigned bin = (valid && (key >> 20) == pfx12) ? ((key >> 8) & 0xFFFu)
                                                           : 0xFFFFFFFFu;
            unsigned grp = __match_any_sync(0xFFFFFFFFu, bin);
            if (bin != 0xFFFFFFFFu && lane == __ffs(grp) - 1)
                atomicAdd(&hist[bin], (unsigned)__popc(grp));
        }
    }
    __syncthreads();
    find_kth(hist, 4096, kth, tid, &s_bin, &s_kthr);
    __syncthreads();
    const unsigned pfx20 = (pfx12 << 12) | s_bin;
    kth = s_kthr;

    for (int i = tid; i < 256; i += SEL_THREADS) hist[i] = 0;
    __syncthreads();

    // ---- scan 3: 8-bit pass (bins = low byte) ----
    for (int it = 0; it < nIt4; it++) {
        int i = it * SEL_THREADS + tid;
        bool valid = (i < NT / 4);
        float4 v = valid ? ((const float4*)row)[i] : make_float4(0.f, 0.f, 0.f, 0.f);
        float e[4] = {v.x, v.y, v.z, v.w};
#pragma unroll
        for (int j = 0; j < 4; j++) {
            unsigned key = __float_as_uint(e[j]);
            unsigned bin = (valid && (key >> 8) == pfx20) ? (key & 0xFFu) : 0xFFFFFFFFu;
            unsigned grp = __match_any_sync(0xFFFFFFFFu, bin);
            if (bin != 0xFFFFFFFFu && lane == __ffs(grp) - 1)
                atomicAdd(&hist[bin], (unsigned)__popc(grp));
        }
    }
    __syncthreads();
    find_kth(hist, 256, kth, tid, &s_bin, &s_kthr);
    __syncthreads();
    const unsigned Tkey = (pfx20 << 8) | s_bin;

    // ---- scan 4: gather winners (<Tkey) and boundary ties (==Tkey) ----
    for (int it = 0; it < nIt4; it++) {
        int i = it * SEL_THREADS + tid;
        if (i < NT / 4) {
            float4 v = ((const float4*)row)[i];
            float e[4] = {v.x, v.y, v.z, v.w};
#pragma unroll
            for (int j = 0; j < 4; j++) {
                unsigned key = __float_as_uint(e[j]);
                if (key < Tkey) {
                    unsigned s = atomicAdd(&s_selcnt, 1u);
                    if (s < 96) s_selidx[s] = i * 4 + j;
                } else if (key == Tkey) {
                    unsigned s = atomicAdd(&s_eqcnt, 1u);
                    if (s < 96) s_eqidx[s] = i * 4 + j;
                }
            }
        }
    }
    __syncthreads();

    int ns = min((int)s_selcnt, 96);
    int ne = min((int)s_eqcnt, 96);

    // parallel rank-by-index gather (deterministic ordering)
    if (tid < ns) {
        int my = s_selidx[tid];
        int rank = 0;
        for (int j = 0; j < ns; j++) rank += (s_selidx[j] < my);
        float d2 = row[my];
        s_w2[rank] = (d2 > 0.f) ? __fdiv_rn(1.0f, __fsqrt_rn(d2)) : 0.f;
        s_l2[rank] = labels[my];
    }
    if (tid >= 128 && tid - 128 < ne) {
        int t = tid - 128;
        int my = s_eqidx[t];
        int rank = 0;
        for (int j = 0; j < ne; j++) rank += (s_eqidx[j] < my);
        ((int*)hist)[512 + rank] = labels[my];   // reuse hist scratch
    }
    __syncthreads();

    if (tid == 0) {
        float stot = 0.f;
        for (int j = 0; j < ns; j++) { stot += s_w2[j]; s_cls[s_l2[j]] += s_w2[j]; }
        int need = KNN - ns;
        float d2T = __uint_as_float(Tkey);
        float wT = (d2T > 0.f) ? __fdiv_rn(1.0f, __fsqrt_rn(d2T)) : 0.f;
        int m = (need < ne) ? need : ne;
        for (int j = 0; j < m; j++) { stot += wT; s_cls[((int*)hist)[512 + j]] += wT; }
#pragma unroll
        for (int l = 0; l < NL; l++) {
            float val = stot - s_cls[l];
            size_t o = (size_t)b * NL + l;
            if (init) total[o] = val; else total[o] += val;
        }
    }
}

// ---------------------------------------------------------------------------
__global__ void __launch_bounds__(256)
pvalue_kernel(const float* __restrict__ total, const float* __restrict__ cali,
              float* __restrict__ out)
{
    const int b = blockIdx.x, tid = threadIdx.x;
    float t[NL];
#pragma unroll
    for (int l = 0; l < NL; l++) t[l] = total[(size_t)b * NL + l];
    int cnt[NL];
#pragma unroll
    for (int l = 0; l < NL; l++) cnt[l] = 0;
    for (int i = tid; i < NC; i += 256) {
        float c = cali[i];
#pragma unroll
        for (int l = 0; l < NL; l++) cnt[l] += (c >= t[l]) ? 1 : 0;
    }
    __shared__ int sc[NL];
    if (tid < NL) sc[tid] = 0;
    __syncthreads();
#pragma unroll
    for (int l = 0; l < NL; l++) atomicAdd(&sc[l], cnt[l]);
    __syncthreads();
    if (tid < NL) out[(size_t)b * NL + tid] = (float)sc[tid] * (1.0f / NC);
}

// ---------------------------------------------------------------------------
extern "C" void kernel_launch(void* const* d_in, const int* in_sizes, int n_in,
                              void* d_out, int out_size)
{
    const float* x        = (const float*)d_in[0];
    const float* train_x  = (const float*)d_in[1];
    const int*   lab      = (const int*)  d_in[2];
    const float* cali     = (const float*)d_in[3];
    const float* W1 = (const float*)d_in[4];  const float* b1 = (const float*)d_in[5];
    const float* W2 = (const float*)d_in[6];  const float* b2 = (const float*)d_in[7];
    const float* W3 = (const float*)d_in[8];  const float* b3 = (const float*)d_in[9];
    const float* W4 = (const float*)d_in[10]; const float* b4 = (const float*)d_in[11];
    float* out = (float*)d_out;

    float *h1p, *h2p, *h3p, *q4p, *t1p, *t2p, *t3p, *t4p, *d2p, *qnp, *tnp, *totp;
    __nv_bfloat16 *qhip, *qlop, *thip, *tlop;
    cudaGetSymbolAddress((void**)&h1p, g_h1);
    cudaGetSymbolAddress((void**)&h2p, g_h2);
    cudaGetSymbolAddress((void**)&h3p, g_h3);
    cudaGetSymbolAddress((void**)&q4p, g_q4);
    cudaGetSymbolAddress((void**)&t1p, g_t1);
    cudaGetSymbolAddress((void**)&t2p, g_t2);
    cudaGetSymbolAddress((void**)&t3p, g_t3);
    cudaGetSymbolAddress((void**)&t4p, g_t4);
    cudaGetSymbolAddress((void**)&d2p, g_d2);
    cudaGetSymbolAddress((void**)&qnp, g_qn);
    cudaGetSymbolAddress((void**)&tnp, g_tn);
    cudaGetSymbolAddress((void**)&totp, g_tot);
    cudaGetSymbolAddress((void**)&qhip, g_qhi);
    cudaGetSymbolAddress((void**)&qlop, g_qlo);
    cudaGetSymbolAddress((void**)&thip, g_thi);
    cudaGetSymbolAddress((void**)&tlop, g_tlo);

    cudaFuncSetAttribute(select_kernel,
                         cudaFuncAttributeMaxDynamicSharedMemorySize, SEL_SMEM);

    dim3 tb(16, 16);
    const int D0 = 83;
    const dim3 mgrid(NTP / 128, BQ / 128);

    // ---- layer 0 first (select_kernel becomes launch #4 -> gets profiled) ----
    conv_norm_kernel<<<BQ / 8, 256>>>(x, qhip, qlop, qnp, BQ, D0);
    conv_norm_kernel<<<NTP / 8, 256>>>(train_x, thip, tlop, tnp, NT, D0);
    mma_dist_kernel<<<mgrid, 256>>>(qhip, qlop, thip, tlop, qnp, tnp, d2p, 96);
    select_kernel<<<BQ, SEL_THREADS, SEL_SMEM>>>(d2p, lab, totp, 1);

    // ---- MLPs ----
    linear_relu_kernel<<<BQ / 64, tb>>>(x,   W1, b1, h1p, BQ, D0);
    linear_relu_kernel<<<BQ / 64, tb>>>(h1p, W2, b2, h2p, BQ, HD);
    linear_relu_kernel<<<BQ / 64, tb>>>(h2p, W3, b3, h3p, BQ, HD);
    linear_softmax_kernel<<<(BQ + 7) / 8, 256>>>(h3p, W4, b4, q4p, BQ);
    const int gtm = (NT + 63) / 64;
    linear_relu_kernel<<<gtm, tb>>>(train_x, W1, b1, t1p, NT, D0);
    linear_relu_kernel<<<gtm, tb>>>(t1p,     W2, b2, t2p, NT, HD);
    linear_relu_kernel<<<gtm, tb>>>(t2p,     W3, b3, t3p, NT, HD);
    linear_softmax_kernel<<<(NT + 7) / 8, 256>>>(t3p, W4, b4, t4p, NT);

    // ---- layers 1-3 ----
    const float* Qs[3] = {h1p, h2p, h3p};
    const float* Ts[3] = {t1p, t2p, t3p};
    for (int i = 0; i < 3; i++) {
        conv_norm_kernel<<<BQ / 8, 256>>>(Qs[i], qhip, qlop, qnp, BQ, HD);
        conv_norm_kernel<<<NTP / 8, 256>>>(Ts[i], thip, tlop, tnp, NT, HD);
        mma_dist_kernel<<<mgrid, 256>>>(qhip, qlop, thip, tlop, qnp, tnp, d2p, 128);
        select_kernel<<<BQ, SEL_THREADS, SEL_SMEM>>>(d2p, lab, totp, 0);
    }

    // ---- layer 4 (softmax features, D=8): exact fp32 path ----
    rownorm_kernel<<<(BQ + 7) / 8, 256>>>(q4p, qnp, BQ, NL);
    rownorm_kernel<<<(NT + 7) / 8, 256>>>(t4p, tnp, NT, NL);
    dist_kernel<<<dim3((NT + 127) / 128, BQ / 64), tb>>>(q4p, t4p, qnp, tnp, d2p, NL, NT);
    select_kernel<<<BQ, SEL_THREADS, SEL_SMEM>>>(d2p, lab, totp, 0);

    // ---- p-values ----
    pvalue_kernel<<<BQ, 256>>>(totp, cali, out);
}

// round 5
// speedup vs baseline: 2.7290x; 1.5660x over previous
#include <cuda_runtime.h>
#include <cuda_bf16.h>
#include <math.h>
#include <stdint.h>

#define BQ   1024
#define NT   50000
#define NTP  50048          // NT padded to multiple of 128
#define NL   8
#define KNN  75
#define HD   128
#define NC   10000

typedef unsigned long long u64;

// ---------------- device scratch (no runtime allocation allowed) ----------------
__device__ float g_h1[BQ * HD];
__device__ float g_h2[BQ * HD];
__device__ float g_h3[BQ * HD];
__device__ float g_q4[BQ * NL];
__device__ float g_t1[(size_t)NT * HD];
__device__ float g_t2[(size_t)NT * HD];
__device__ float g_t3[(size_t)NT * HD];
__device__ float g_t4[(size_t)NT * NL];
__device__ float g_d2[(size_t)BQ * NT];   // 204.8 MB distance scratch
__device__ float g_qn[BQ];
__device__ float g_tn[NT];
__device__ float g_tot[BQ * NL];
// bf16 hi/lo feature banks (K-major, padded to 128 cols)
__device__ __nv_bfloat16 g_qhi[(size_t)BQ * 128];
__device__ __nv_bfloat16 g_qlo[(size_t)BQ * 128];
__device__ __nv_bfloat16 g_thi[(size_t)NTP * 128];
__device__ __nv_bfloat16 g_tlo[(size_t)NTP * 128];

// ---------------------------------------------------------------------------
// mma.sync bf16 helper (baseline sm_80+ instruction)
// ---------------------------------------------------------------------------
__device__ __forceinline__ void mma_bf16(float* d, const uint32_t* a, const uint32_t* b)
{
    asm volatile(
        "mma.sync.aligned.m16n8k16.row.col.f32.bf16.bf16.f32 "
        "{%0,%1,%2,%3}, {%4,%5,%6,%7}, {%8,%9}, {%0,%1,%2,%3};"
        : "+f"(d[0]), "+f"(d[1]), "+f"(d[2]), "+f"(d[3])
        : "r"(a[0]), "r"(a[1]), "r"(a[2]), "r"(a[3]), "r"(b[0]), "r"(b[1]));
}

// ---------------------------------------------------------------------------
// Fused split-convert + row norm. One warp per row; rows >= Mreal are zeroed.
// ---------------------------------------------------------------------------
__global__ void __launch_bounds__(256)
conv_norm_kernel(const float* __restrict__ A, __nv_bfloat16* __restrict__ hi,
                 __nv_bfloat16* __restrict__ lo, float* __restrict__ nrm,
                 int Mreal, int D)
{
    int warp = threadIdx.x >> 5, lane = threadIdx.x & 31;
    int row = blockIdx.x * 8 + warp;
    int base = lane * 4;

    float ss = 0.f;
    __nv_bfloat16 hb[4], lb[4];
#pragma unroll
    for (int j = 0; j < 4; j++) {
        int col = base + j;
        float v = (row < Mreal && col < D) ? A[(size_t)row * D + col] : 0.f;
        ss += v * v;
        hb[j] = __float2bfloat16_rn(v);
        lb[j] = __float2bfloat16_rn(v - __bfloat162float(hb[j]));
    }
    __nv_bfloat162 h01, h23, l01, l23;
    h01.x = hb[0]; h01.y = hb[1]; h23.x = hb[2]; h23.y = hb[3];
    l01.x = lb[0]; l01.y = lb[1]; l23.x = lb[2]; l23.y = lb[3];
    *(__nv_bfloat162*)&hi[(size_t)row * 128 + base]     = h01;
    *(__nv_bfloat162*)&hi[(size_t)row * 128 + base + 2] = h23;
    *(__nv_bfloat162*)&lo[(size_t)row * 128 + base]     = l01;
    *(__nv_bfloat162*)&lo[(size_t)row * 128 + base + 2] = l23;

#pragma unroll
    for (int off = 16; off > 0; off >>= 1) ss += __shfl_down_sync(0xFFFFFFFFu, ss, off);
    if (lane == 0 && row < Mreal) nrm[row] = ss;
}

// ---------------------------------------------------------------------------
// Tensor-core bf16x3 distance GEMM with cp.async double buffering.
// ---------------------------------------------------------------------------
__device__ __forceinline__ void tile_load_async(
    const __nv_bfloat16* __restrict__ Ap, const __nv_bfloat16* __restrict__ Bp,
    __nv_bfloat16* As, __nv_bfloat16* Bs, int m0, int n0, int k0, int lr, int lh)
{
    uint32_t sa = (uint32_t)__cvta_generic_to_shared(As + lr * 24 + lh * 8);
    uint32_t sb = (uint32_t)__cvta_generic_to_shared(Bs + lr * 24 + lh * 8);
    const void* ga = Ap + (size_t)(m0 + lr) * 128 + k0 + lh * 8;
    const void* gb = Bp + (size_t)(n0 + lr) * 128 + k0 + lh * 8;
    asm volatile(
        "cp.async.cg.shared.global [%0], [%1], 16;\n\t"
        "cp.async.cg.shared.global [%2], [%3], 16;\n\t"
        "cp.async.commit_group;\n"
        :: "r"(sa), "l"(ga), "r"(sb), "l"(gb));
}

__global__ void __launch_bounds__(256)
mma_dist_kernel(const __nv_bfloat16* __restrict__ Qhi, const __nv_bfloat16* __restrict__ Qlo,
                const __nv_bfloat16* __restrict__ Thi, const __nv_bfloat16* __restrict__ Tlo,
                const float* __restrict__ qn, const float* __restrict__ tn,
                float* __restrict__ out, int KP)
{
    __shared__ __align__(16) __nv_bfloat16 As[2][128 * 24];
    __shared__ __align__(16) __nv_bfloat16 Bs[2][128 * 24];
    const int tid = threadIdx.x;
    const int wid = tid >> 5, lane = tid & 31;
    const int n0 = blockIdx.x * 128;
    const int m0 = blockIdx.y * 128;
    const int wm = (wid & 3) * 32;
    const int wn = (wid >> 2) * 64;

    const int lr = tid >> 1, lh = tid & 1;
    const int fr = lane >> 2, fc = (lane & 3) * 2;

    float acc[2][8][4];
#pragma unroll
    for (int mt = 0; mt < 2; mt++)
#pragma unroll
        for (int nt = 0; nt < 8; nt++)
#pragma unroll
            for (int j = 0; j < 4; j++) acc[mt][nt][j] = 0.f;

    const int S = 3 * (KP >> 4);

    tile_load_async(Qhi, Thi, As[0], Bs[0], m0, n0, 0, lr, lh);

    int nseg = 0, nk = 16;
    for (int s = 0; s < S; s++) {
        int buf = s & 1;
        if (s + 1 < S) {
            if (nk == KP) { nk = 0; nseg++; }
            const __nv_bfloat16* Ap = (nseg == 1) ? Qlo : Qhi;
            const __nv_bfloat16* Bp = (nseg == 2) ? Tlo : Thi;
            tile_load_async(Ap, Bp, As[buf ^ 1], Bs[buf ^ 1], m0, n0, nk, lr, lh);
            nk += 16;
            asm volatile("cp.async.wait_group 1;" ::: "memory");
        } else {
            asm volatile("cp.async.wait_group 0;" ::: "memory");
        }
        __syncthreads();

        const __nv_bfloat16* Ab = As[buf];
        const __nv_bfloat16* Bb = Bs[buf];
        uint32_t a[2][4];
#pragma unroll
        for (int mt = 0; mt < 2; mt++) {
            int basem = wm + mt * 16;
            a[mt][0] = *(const uint32_t*)&Ab[(basem + fr) * 24 + fc];
            a[mt][1] = *(const uint32_t*)&Ab[(basem + fr + 8) * 24 + fc];
            a[mt][2] = *(const uint32_t*)&Ab[(basem + fr) * 24 + fc + 8];
            a[mt][3] = *(const uint32_t*)&Ab[(basem + fr + 8) * 24 + fc + 8];
        }
#pragma unroll
        for (int nt = 0; nt < 8; nt++) {
            uint32_t b[2];
            int nb = wn + nt * 8;
            b[0] = *(const uint32_t*)&Bb[(nb + fr) * 24 + fc];
            b[1] = *(const uint32_t*)&Bb[(nb + fr) * 24 + fc + 8];
            mma_bf16(acc[0][nt], a[0], b);
            mma_bf16(acc[1][nt], a[1], b);
        }
        __syncthreads();
    }

#pragma unroll
    for (int mt = 0; mt < 2; mt++) {
        int mrow = m0 + wm + mt * 16 + fr;
        float q0 = qn[mrow], q1 = qn[mrow + 8];
#pragma unroll
        for (int nt = 0; nt < 8; nt++) {
            int n = n0 + wn + nt * 8 + fc;
            if (n < NT) {
                float t0 = tn[n], t1 = tn[n + 1];
                float2 o;
                o.x = fmaxf(q0 + t0 - 2.f * acc[mt][nt][0], 0.f);
                o.y = fmaxf(q0 + t1 - 2.f * acc[mt][nt][1], 0.f);
                *(float2*)&out[(size_t)mrow * NT + n] = o;
                o.x = fmaxf(q1 + t0 - 2.f * acc[mt][nt][2], 0.f);
                o.y = fmaxf(q1 + t1 - 2.f * acc[mt][nt][3], 0.f);
                *(float2*)&out[(size_t)(mrow + 8) * NT + n] = o;
            }
        }
    }
}

// ---------------------------------------------------------------------------
// Generic fused linear + ReLU
// ---------------------------------------------------------------------------
__global__ void __launch_bounds__(256)
linear_relu_kernel(const float* __restrict__ A, const float* __restrict__ W,
                   const float* __restrict__ bias, float* __restrict__ out,
                   int M, int K)
{
    __shared__ __align__(16) float As[16 * 68];
    __shared__ __align__(16) float Bs[16 * 136];
    const int tx = threadIdx.x, ty = threadIdx.y;
    const int tid = ty * 16 + tx;
    const int m0 = blockIdx.x * 64;

    float acc[4][8];
#pragma unroll
    for (int r = 0; r < 4; r++)
#pragma unroll
        for (int c = 0; c < 8; c++) acc[r][c] = 0.f;

    const int nChunks = (K + 15) / 16;
    for (int ch = 0; ch < nChunks; ch++) {
        const int k0 = ch * 16;
#pragma unroll
        for (int i = 0; i < 4; i++) {
            int e = tid + i * 256;
            int k = e & 15, m = e >> 4;
            float v = 0.f;
            if (k0 + k < K && m0 + m < M) v = A[(size_t)(m0 + m) * K + k0 + k];
            As[k * 68 + m] = v;
        }
#pragma unroll
        for (int i = 0; i < 8; i++) {
            int e = tid + i * 256;
            int h = e & 127, k = e >> 7;
            float v = 0.f;
            if (k0 + k < K) v = W[(size_t)(k0 + k) * HD + h];
            Bs[k * 136 + h] = v;
        }
        __syncthreads();
#pragma unroll
        for (int k = 0; k < 16; k++) {
            float4 a  = *(const float4*)&As[k * 68 + ty * 4];
            float4 b0 = *(const float4*)&Bs[k * 136 + tx * 4];
            float4 b1 = *(const float4*)&Bs[k * 136 + 64 + tx * 4];
            float av[4] = {a.x, a.y, a.z, a.w};
            float bv[8] = {b0.x, b0.y, b0.z, b0.w, b1.x, b1.y, b1.z, b1.w};
#pragma unroll
            for (int r = 0; r < 4; r++)
#pragma unroll
                for (int c = 0; c < 8; c++) acc[r][c] += av[r] * bv[c];
        }
        __syncthreads();
    }
#pragma unroll
    for (int r = 0; r < 4; r++) {
        int m = m0 + ty * 4 + r;
        if (m >= M) continue;
#pragma unroll
        for (int half = 0; half < 2; half++) {
#pragma unroll
            for (int c = 0; c < 4; c++) {
                int h = half * 64 + tx * 4 + c;
                float v = acc[r][half * 4 + c] + bias[h];
                out[(size_t)m * HD + h] = fmaxf(v, 0.f);
            }
        }
    }
}

// ---------------------------------------------------------------------------
// Final linear + softmax
// ---------------------------------------------------------------------------
__global__ void __launch_bounds__(256)
linear_softmax_kernel(const float* __restrict__ A, const float* __restrict__ W,
                      const float* __restrict__ bias, float* __restrict__ out, int M)
{
    __shared__ float Ws[HD * NL];
    __shared__ float bs[NL];
    int tid = threadIdx.x;
    for (int i = tid; i < HD * NL; i += 256) Ws[i] = W[i];
    if (tid < NL) bs[tid] = bias[tid];
    __syncthreads();

    int warp = tid >> 5, lane = tid & 31;
    int m = blockIdx.x * 8 + warp;
    if (m >= M) return;

    float acc[NL];
#pragma unroll
    for (int h = 0; h < NL; h++) acc[h] = 0.f;
    for (int k = lane; k < HD; k += 32) {
        float x = A[(size_t)m * HD + k];
#pragma unroll
        for (int h = 0; h < NL; h++) acc[h] += x * Ws[k * NL + h];
    }
#pragma unroll
    for (int h = 0; h < NL; h++)
#pragma unroll
        for (int off = 16; off > 0; off >>= 1)
            acc[h] += __shfl_down_sync(0xFFFFFFFFu, acc[h], off);

    if (lane == 0) {
        float v[NL], mx = -1e30f;
#pragma unroll
        for (int h = 0; h < NL; h++) { v[h] = acc[h] + bs[h]; mx = fmaxf(mx, v[h]); }
        float s = 0.f;
#pragma unroll
        for (int h = 0; h < NL; h++) { v[h] = expf(v[h] - mx); s += v[h]; }
        float inv = 1.0f / s;
#pragma unroll
        for (int h = 0; h < NL; h++) out[(size_t)m * NL + h] = v[h] * inv;
    }
}

// ---------------------------------------------------------------------------
__global__ void __launch_bounds__(256)
rownorm_kernel(const float* __restrict__ A, float* __restrict__ out, int M, int D)
{
    int warp = threadIdx.x >> 5, lane = threadIdx.x & 31;
    int m = blockIdx.x * 8 + warp;
    if (m >= M) return;
    float s = 0.f;
    for (int k = lane; k < D; k += 32) { float v = A[(size_t)m * D + k]; s += v * v; }
#pragma unroll
    for (int off = 16; off > 0; off >>= 1) s += __shfl_down_sync(0xFFFFFFFFu, s, off);
    if (lane == 0) out[m] = s;
}

// ---------------------------------------------------------------------------
// SIMT fp32 distance GEMM (layer 4, D=8, precision-critical)
// ---------------------------------------------------------------------------
__global__ void __launch_bounds__(256)
dist_kernel(const float* __restrict__ Q, const float* __restrict__ T,
            const float* __restrict__ qn, const float* __restrict__ tn,
            float* __restrict__ out, int D, int Ncols)
{
    __shared__ __align__(16) float As[16 * 68];
    __shared__ __align__(16) float Bs[16 * 136];
    const int tx = threadIdx.x, ty = threadIdx.y;
    const int tid = ty * 16 + tx;
    const int n0 = blockIdx.x * 128;
    const int m0 = blockIdx.y * 64;

    float acc[4][8];
#pragma unroll
    for (int r = 0; r < 4; r++)
#pragma unroll
        for (int c = 0; c < 8; c++) acc[r][c] = 0.f;

    const int nChunks = (D + 15) / 16;
    for (int ch = 0; ch < nChunks; ch++) {
        const int k0 = ch * 16;
#pragma unroll
        for (int i = 0; i < 4; i++) {
            int e = tid + i * 256;
            int k = e & 15, m = e >> 4;
            float v = (k0 + k < D) ? Q[(size_t)(m0 + m) * D + k0 + k] : 0.f;
            As[k * 68 + m] = v;
        }
#pragma unroll
        for (int i = 0; i < 8; i++) {
            int e = tid + i * 256;
            int k = e & 15, n = e >> 4;
            int gn = n0 + n;
            float v = 0.f;
            if (k0 + k < D && gn < Ncols) v = T[(size_t)gn * D + k0 + k];
            Bs[k * 136 + n] = v;
        }
        __syncthreads();
#pragma unroll
        for (int k = 0; k < 16; k++) {
            float4 a  = *(const float4*)&As[k * 68 + ty * 4];
            float4 b0 = *(const float4*)&Bs[k * 136 + tx * 4];
            float4 b1 = *(const float4*)&Bs[k * 136 + 64 + tx * 4];
            float av[4] = {a.x, a.y, a.z, a.w};
            float bv[8] = {b0.x, b0.y, b0.z, b0.w, b1.x, b1.y, b1.z, b1.w};
#pragma unroll
            for (int r = 0; r < 4; r++)
#pragma unroll
                for (int c = 0; c < 8; c++) acc[r][c] += av[r] * bv[c];
        }
        __syncthreads();
    }
#pragma unroll
    for (int r = 0; r < 4; r++) {
        int m = m0 + ty * 4 + r;
        float qv = qn[m];
#pragma unroll
        for (int half = 0; half < 2; half++) {
#pragma unroll
            for (int c = 0; c < 4; c++) {
                int n = n0 + half * 64 + tx * 4 + c;
                if (n < Ncols) {
                    float d = qv + tn[n] - 2.f * acc[r][half * 4 + c];
                    out[(size_t)m * Ncols + n] = fmaxf(d, 0.f);
                }
            }
        }
    }
}

// ---------------------------------------------------------------------------
// Exact top-K select v2: candidate-compaction radix select.
//   scan 1 (gmem): 12-bit histogram of key>>20
//   scan 2 (gmem): compact winners (<bin) + candidate bin (==bin) into smem
//   passes A/B over the COMPACT candidate list (bits 19..8, 7..0)
//   fallback to gmem passes if candidates overflow CAP (rare).
// smem ~50.5 KB -> 4 CTAs/SM, 2048 threads/SM.
// ---------------------------------------------------------------------------
#define SEL_THREADS 512
#define SEL_CAP 4096
#define SEL_SMEM (4096 * 4 + SEL_CAP * 8 + 128 * 8 * 2 + 128 * 4)

__device__ __forceinline__ void find_kth(const unsigned* hist, int NB, unsigned kth,
                                         int tid, unsigned* s_bin, unsigned* s_kthr)
{
    if (tid < 32) {
        unsigned running = 0;
        for (int base = 0; base < NB; base += 32) {
            unsigned v = hist[base + tid];
            unsigned sc = v;
#pragma unroll
            for (int off = 1; off < 32; off <<= 1) {
                unsigned t = __shfl_up_sync(0xFFFFFFFFu, sc, off);
                if (tid >= off) sc += t;
            }
            unsigned tot = __shfl_sync(0xFFFFFFFFu, sc, 31);
            if (running + tot >= kth) {
                unsigned mask = __ballot_sync(0xFFFFFFFFu, running + sc >= kth);
                int l = __ffs(mask) - 1;
                if (tid == l) { *s_bin = (unsigned)(base + l); *s_kthr = kth - running - (sc - v); }
                break;
            }
            running += tot;
        }
    }
}

__global__ void __launch_bounds__(SEL_THREADS)
select_kernel(const float* __restrict__ d2mat, const int* __restrict__ labels,
              float* __restrict__ total, int init)
{
    extern __shared__ __align__(16) char sms[];
    unsigned* hist = (unsigned*)sms;                         // 16384 B
    u64* cand = (u64*)(sms + 16384);                         // 32768 B
    u64* sel  = (u64*)(sms + 16384 + SEL_CAP * 8);           // 1024 B
    u64* ties = sel + 128;                                   // 1024 B
    int* tlab = (int*)(ties + 128);                          // 512 B

    __shared__ unsigned s_bin, s_kthr, s_candcnt, s_selcnt, s_tiecnt;
    __shared__ float s_w[80];
    __shared__ int s_lab[80];

    const int b = blockIdx.x, tid = threadIdx.x, lane = tid & 31;
    const float4* src = (const float4*)(d2mat + (size_t)b * NT);
    const int NIT = (NT / 4 + SEL_THREADS - 1) / SEL_THREADS;

    for (int i = tid; i < 4096; i += SEL_THREADS) hist[i] = 0;
    if (tid == 0) { s_candcnt = 0; s_selcnt = 0; s_tiecnt = 0; }
    __syncthreads();

    // ---- scan 1: 12-bit histogram from gmem ----
    for (int it = 0; it < NIT; it++) {
        int i = it * SEL_THREADS + tid;
        bool valid = (i < NT / 4);
        float4 v = valid ? src[i] : make_float4(0.f, 0.f, 0.f, 0.f);
        float e[4] = {v.x, v.y, v.z, v.w};
#pragma unroll
        for (int j = 0; j < 4; j++) {
            unsigned bin = valid ? (__float_as_uint(e[j]) >> 20) : 0xFFFFFFFFu;
            unsigned grp = __match_any_sync(0xFFFFFFFFu, bin);
            if (bin != 0xFFFFFFFFu && lane == __ffs(grp) - 1)
                atomicAdd(&hist[bin], (unsigned)__popc(grp));
        }
    }
    __syncthreads();
    find_kth(hist, 4096, KNN, tid, &s_bin, &s_kthr);
    __syncthreads();
    const unsigned pfx = s_bin;
    unsigned kth = s_kthr;

    // ---- scan 2: compact winners + candidate bin ----
    for (int it = 0; it < NIT; it++) {
        int i = it * SEL_THREADS + tid;
        if (i < NT / 4) {
            float4 v = src[i];
            float e[4] = {v.x, v.y, v.z, v.w};
#pragma unroll
            for (int j = 0; j < 4; j++) {
                unsigned key = __float_as_uint(e[j]);
                unsigned bb = key >> 20;
                if (bb < pfx) {
                    unsigned s = atomicAdd(&s_selcnt, 1u);
                    if (s < 128) sel[s] = ((u64)key << 32) | (unsigned)(i * 4 + j);
                } else if (bb == pfx) {
                    unsigned s = atomicAdd(&s_candcnt, 1u);
                    if (s < SEL_CAP) cand[s] = ((u64)key << 32) | (unsigned)(i * 4 + j);
                }
            }
        }
    }
    __syncthreads();

    unsigned Tkey;
    const unsigned candTotal = s_candcnt;

    if (candTotal <= SEL_CAP) {
        const int cc = (int)candTotal;
        // pass A over candidates: bits 19..8
        for (int i = tid; i < 4096; i += SEL_THREADS) hist[i] = 0;
        __syncthreads();
        for (int i = tid; i < cc; i += SEL_THREADS) {
            unsigned key = (unsigned)(cand[i] >> 32);
            atomicAdd(&hist[(key >> 8) & 0xFFFu], 1u);
        }
        __syncthreads();
        find_kth(hist, 4096, kth, tid, &s_bin, &s_kthr);
        __syncthreads();
        const unsigned binA = s_bin;
        const unsigned kth2 = s_kthr;

        // pass B over candidates: low byte
        for (int i = tid; i < 256; i += SEL_THREADS) hist[i] = 0;
        __syncthreads();
        for (int i = tid; i < cc; i += SEL_THREADS) {
            unsigned key = (unsigned)(cand[i] >> 32);
            if (((key >> 8) & 0xFFFu) == binA) atomicAdd(&hist[key & 0xFFu], 1u);
        }
        __syncthreads();
        find_kth(hist, 256, kth2, tid, &s_bin, &s_kthr);
        __syncthreads();
        Tkey = (pfx << 20) | (binA << 8) | s_bin;

        // gather from candidate list
        for (int i = tid; i < cc; i += SEL_THREADS) {
            u64 cv = cand[i];
            unsigned key = (unsigned)(cv >> 32);
            if (key < Tkey) {
                unsigned s = atomicAdd(&s_selcnt, 1u);
                if (s < 128) sel[s] = cv;
            } else if (key == Tkey) {
                unsigned s = atomicAdd(&s_tiecnt, 1u);
                if (s < 128) ties[s] = cv;
            }
        }
        __syncthreads();
    } else {
        // ---- fallback: gmem radix passes (rare) ----
        for (int i = tid; i < 4096; i += SEL_THREADS) hist[i] = 0;
        __syncthreads();
        for (int it = 0; it < NIT; it++) {
            int i = it * SEL_THREADS + tid;
            bool valid = (i < NT / 4);
            float4 v = valid ? src[i] : make_float4(0.f, 0.f, 0.f, 0.f);
            float e[4] = {v.x, v.y, v.z, v.w};
#pragma unroll
            for (int j = 0; j < 4; j++) {
                unsigned key = __float_as_uint(e[j]);
                unsigned bin = (valid && (key >> 20) == pfx) ? ((key >> 8) & 0xFFFu)
                                                             : 0xFFFFFFFFu;
                unsigned grp = __match_any_sync(0xFFFFFFFFu, bin);
                if (bin != 0xFFFFFFFFu && lane == __ffs(grp) - 1)
                    atomicAdd(&hist[bin], (unsigned)__popc(grp));
            }
        }
        __syncthreads();
        find_kth(hist, 4096, kth, tid, &s_bin, &s_kthr);
        __syncthreads();
        const unsigned binA = s_bin;
        const unsigned kth2 = s_kthr;
        const unsigned pfx20 = (pfx << 12) | binA;

        for (int i = tid; i < 256; i += SEL_THREADS) hist[i] = 0;
        __syncthreads();
        for (int it = 0; it < NIT; it++) {
            int i = it * SEL_THREADS + tid;
            bool valid = (i < NT / 4);
            float4 v = valid ? src[i] : make_float4(0.f, 0.f, 0.f, 0.f);
            float e[4] = {v.x, v.y, v.z, v.w};
#pragma unroll
            for (int j = 0; j < 4; j++) {
                unsigned key = __float_as_uint(e[j]);
                unsigned bin = (valid && (key >> 8) == pfx20) ? (key & 0xFFu)
                                                              : 0xFFFFFFFFu;
                unsigned grp = __match_any_sync(0xFFFFFFFFu, bin);
                if (bin != 0xFFFFFFFFu && lane == __ffs(grp) - 1)
                    atomicAdd(&hist[bin], (unsigned)__popc(grp));
            }
        }
        __syncthreads();
        find_kth(hist, 256, kth2, tid, &s_bin, &s_kthr);
        __syncthreads();
        Tkey = (pfx20 << 8) | s_bin;

        // gather from gmem (only candidate-bin elements; winners already in sel)
        for (int it = 0; it < NIT; it++) {
            int i = it * SEL_THREADS + tid;
            if (i < NT / 4) {
                float4 v = src[i];
                float e[4] = {v.x, v.y, v.z, v.w};
#pragma unroll
                for (int j = 0; j < 4; j++) {
                    unsigned key = __float_as_uint(e[j]);
                    if ((key >> 20) == pfx) {
                        if (key < Tkey) {
                            unsigned s = atomicAdd(&s_selcnt, 1u);
                            if (s < 128) sel[s] = ((u64)key << 32) | (unsigned)(i * 4 + j);
                        } else if (key == Tkey) {
                            unsigned s = atomicAdd(&s_tiecnt, 1u);
                            if (s < 128) ties[s] = ((u64)key << 32) | (unsigned)(i * 4 + j);
                        }
                    }
                }
            }
        }
        __syncthreads();
    }

    const int ns = min((int)s_selcnt, 128);   // provably <= 74
    const int ne = min((int)s_tiecnt, 128);

    // deterministic rank-by-index ordering of winners
    if (tid < ns) {
        u64 mine = sel[tid];
        unsigned my_idx = (unsigned)(mine & 0xFFFFFFFFu);
        int rank = 0;
        for (int j = 0; j < ns; j++) rank += ((unsigned)(sel[j] & 0xFFFFFFFFu) < my_idx);
        float d2 = __uint_as_float((unsigned)(mine >> 32));
        s_w[rank] = (d2 > 0.f) ? __fdiv_rn(1.0f, __fsqrt_rn(d2)) : 0.f;
        s_lab[rank] = labels[my_idx];
    }
    if (tid >= 128 && tid - 128 < ne) {
        int t = tid - 128;
        unsigned my_idx = (unsigned)(ties[t] & 0xFFFFFFFFu);
        int rank = 0;
        for (int j = 0; j < ne; j++) rank += ((unsigned)(ties[j] & 0xFFFFFFFFu) < my_idx);
        tlab[rank] = labels[my_idx];
    }
    __syncthreads();

    if (tid == 0) {
        float cls[NL];
#pragma unroll
        for (int l = 0; l < NL; l++) cls[l] = 0.f;
        float stot = 0.f;
        for (int j = 0; j < ns; j++) { stot += s_w[j]; cls[s_lab[j]] += s_w[j]; }
        int need = KNN - ns;
        float d2T = __uint_as_float(Tkey);
        float wT = (d2T > 0.f) ? __fdiv_rn(1.0f, __fsqrt_rn(d2T)) : 0.f;
        int m = (need < ne) ? need : ne;
        for (int j = 0; j < m; j++) { stot += wT; cls[tlab[j]] += wT; }
#pragma unroll
        for (int l = 0; l < NL; l++) {
            float val = stot - cls[l];
            size_t o = (size_t)b * NL + l;
            if (init) total[o] = val; else total[o] += val;
        }
    }
}

// ---------------------------------------------------------------------------
__global__ void __launch_bounds__(256)
pvalue_kernel(const float* __restrict__ total, const float* __restrict__ cali,
              float* __restrict__ out)
{
    const int b = blockIdx.x, tid = threadIdx.x;
    float t[NL];
#pragma unroll
    for (int l = 0; l < NL; l++) t[l] = total[(size_t)b * NL + l];
    int cnt[NL];
#pragma unroll
    for (int l = 0; l < NL; l++) cnt[l] = 0;
    for (int i = tid; i < NC; i += 256) {
        float c = cali[i];
#pragma unroll
        for (int l = 0; l < NL; l++) cnt[l] += (c >= t[l]) ? 1 : 0;
    }
    __shared__ int sc[NL];
    if (tid < NL) sc[tid] = 0;
    __syncthreads();
#pragma unroll
    for (int l = 0; l < NL; l++) atomicAdd(&sc[l], cnt[l]);
    __syncthreads();
    if (tid < NL) out[(size_t)b * NL + tid] = (float)sc[tid] * (1.0f / NC);
}

// ---------------------------------------------------------------------------
extern "C" void kernel_launch(void* const* d_in, const int* in_sizes, int n_in,
                              void* d_out, int out_size)
{
    const float* x        = (const float*)d_in[0];
    const float* train_x  = (const float*)d_in[1];
    const int*   lab      = (const int*)  d_in[2];
    const float* cali     = (const float*)d_in[3];
    const float* W1 = (const float*)d_in[4];  const float* b1 = (const float*)d_in[5];
    const float* W2 = (const float*)d_in[6];  const float* b2 = (const float*)d_in[7];
    const float* W3 = (const float*)d_in[8];  const float* b3 = (const float*)d_in[9];
    const float* W4 = (const float*)d_in[10]; const float* b4 = (const float*)d_in[11];
    float* out = (float*)d_out;

    float *h1p, *h2p, *h3p, *q4p, *t1p, *t2p, *t3p, *t4p, *d2p, *qnp, *tnp, *totp;
    __nv_bfloat16 *qhip, *qlop, *thip, *tlop;
    cudaGetSymbolAddress((void**)&h1p, g_h1);
    cudaGetSymbolAddress((void**)&h2p, g_h2);
    cudaGetSymbolAddress((void**)&h3p, g_h3);
    cudaGetSymbolAddress((void**)&q4p, g_q4);
    cudaGetSymbolAddress((void**)&t1p, g_t1);
    cudaGetSymbolAddress((void**)&t2p, g_t2);
    cudaGetSymbolAddress((void**)&t3p, g_t3);
    cudaGetSymbolAddress((void**)&t4p, g_t4);
    cudaGetSymbolAddress((void**)&d2p, g_d2);
    cudaGetSymbolAddress((void**)&qnp, g_qn);
    cudaGetSymbolAddress((void**)&tnp, g_tn);
    cudaGetSymbolAddress((void**)&totp, g_tot);
    cudaGetSymbolAddress((void**)&qhip, g_qhi);
    cudaGetSymbolAddress((void**)&qlop, g_qlo);
    cudaGetSymbolAddress((void**)&thip, g_thi);
    cudaGetSymbolAddress((void**)&tlop, g_tlo);

    cudaFuncSetAttribute(select_kernel,
                         cudaFuncAttributeMaxDynamicSharedMemorySize, SEL_SMEM);

    dim3 tb(16, 16);
    const int D0 = 83;
    const dim3 mgrid(NTP / 128, BQ / 128);

    // ---- layer 0 first (select_kernel = launch #4 -> gets profiled) ----
    conv_norm_kernel<<<BQ / 8, 256>>>(x, qhip, qlop, qnp, BQ, D0);
    conv_norm_kernel<<<NTP / 8, 256>>>(train_x, thip, tlop, tnp, NT, D0);
    mma_dist_kernel<<<mgrid, 256>>>(qhip, qlop, thip, tlop, qnp, tnp, d2p, 96);
    select_kernel<<<BQ, SEL_THREADS, SEL_SMEM>>>(d2p, lab, totp, 1);

    // ---- MLPs ----
    linear_relu_kernel<<<BQ / 64, tb>>>(x,   W1, b1, h1p, BQ, D0);
    linear_relu_kernel<<<BQ / 64, tb>>>(h1p, W2, b2, h2p, BQ, HD);
    linear_relu_kernel<<<BQ / 64, tb>>>(h2p, W3, b3, h3p, BQ, HD);
    linear_softmax_kernel<<<(BQ + 7) / 8, 256>>>(h3p, W4, b4, q4p, BQ);
    const int gtm = (NT + 63) / 64;
    linear_relu_kernel<<<gtm, tb>>>(train_x, W1, b1, t1p, NT, D0);
    linear_relu_kernel<<<gtm, tb>>>(t1p,     W2, b2, t2p, NT, HD);
    linear_relu_kernel<<<gtm, tb>>>(t2p,     W3, b3, t3p, NT, HD);
    linear_softmax_kernel<<<(NT + 7) / 8, 256>>>(t3p, W4, b4, t4p, NT);

    // ---- layers 1-3 ----
    const float* Qs[3] = {h1p, h2p, h3p};
    const float* Ts[3] = {t1p, t2p, t3p};
    for (int i = 0; i < 3; i++) {
        conv_norm_kernel<<<BQ / 8, 256>>>(Qs[i], qhip, qlop, qnp, BQ, HD);
        conv_norm_kernel<<<NTP / 8, 256>>>(Ts[i], thip, tlop, tnp, NT, HD);
        mma_dist_kernel<<<mgrid, 256>>>(qhip, qlop, thip, tlop, qnp, tnp, d2p, 128);
        select_kernel<<<BQ, SEL_THREADS, SEL_SMEM>>>(d2p, lab, totp, 0);
    }

    // ---- layer 4 (softmax features, D=8): exact fp32 path ----
    rownorm_kernel<<<(BQ + 7) / 8, 256>>>(q4p, qnp, BQ, NL);
    rownorm_kernel<<<(NT + 7) / 8, 256>>>(t4p, tnp, NT, NL);
    dist_kernel<<<dim3((NT + 127) / 128, BQ / 64), tb>>>(q4p, t4p, qnp, tnp, d2p, NL, NT);
    select_kernel<<<BQ, SEL_THREADS, SEL_SMEM>>>(d2p, lab, totp, 0);

    // ---- p-values ----
    pvalue_kernel<<<BQ, 256>>>(totp, cali, out);
}

// round 6
// speedup vs baseline: 3.2863x; 1.2042x over previous
#include <cuda_runtime.h>
#include <cuda_bf16.h>
#include <math.h>
#include <stdint.h>

#define BQ   1024
#define NT   50000
#define NTP  50048          // NT padded to multiple of 128
#define NL   8
#define KNN  75
#define HD   128
#define NC   10000
#define NTILES 391          // ceil(NT/128) == NTP/128

typedef unsigned long long u64;

// ---------------- device scratch (no runtime allocation allowed) ----------------
__device__ float g_h1[BQ * HD];
__device__ float g_h2[BQ * HD];
__device__ float g_h3[BQ * HD];
__device__ float g_q4[BQ * NL];
__device__ float g_t1[(size_t)NT * HD];
__device__ float g_t2[(size_t)NT * HD];
__device__ float g_t3[(size_t)NT * HD];
__device__ float g_t4[(size_t)NT * NL];
__device__ float g_d2[(size_t)BQ * NT];   // 204.8 MB distance scratch
__device__ float g_min[(size_t)BQ * NTILES]; // per (query, n-tile) minimum d2
__device__ float g_qn[BQ];
__device__ float g_tn[NT];
__device__ float g_tot[BQ * NL];
// bf16 hi/lo feature banks (K-major, padded to 128 cols)
__device__ __nv_bfloat16 g_qhi[(size_t)BQ * 128];
__device__ __nv_bfloat16 g_qlo[(size_t)BQ * 128];
__device__ __nv_bfloat16 g_thi[(size_t)NTP * 128];
__device__ __nv_bfloat16 g_tlo[(size_t)NTP * 128];

// ---------------------------------------------------------------------------
__device__ __forceinline__ void mma_bf16(float* d, const uint32_t* a, const uint32_t* b)
{
    asm volatile(
        "mma.sync.aligned.m16n8k16.row.col.f32.bf16.bf16.f32 "
        "{%0,%1,%2,%3}, {%4,%5,%6,%7}, {%8,%9}, {%0,%1,%2,%3};"
        : "+f"(d[0]), "+f"(d[1]), "+f"(d[2]), "+f"(d[3])
        : "r"(a[0]), "r"(a[1]), "r"(a[2]), "r"(a[3]), "r"(b[0]), "r"(b[1]));
}

// ---------------------------------------------------------------------------
// Fused split-convert + row norm. One warp per row; rows >= Mreal are zeroed.
// ---------------------------------------------------------------------------
__global__ void __launch_bounds__(256)
conv_norm_kernel(const float* __restrict__ A, __nv_bfloat16* __restrict__ hi,
                 __nv_bfloat16* __restrict__ lo, float* __restrict__ nrm,
                 int Mreal, int D)
{
    int warp = threadIdx.x >> 5, lane = threadIdx.x & 31;
    int row = blockIdx.x * 8 + warp;
    int base = lane * 4;

    float ss = 0.f;
    __nv_bfloat16 hb[4], lb[4];
#pragma unroll
    for (int j = 0; j < 4; j++) {
        int col = base + j;
        float v = (row < Mreal && col < D) ? A[(size_t)row * D + col] : 0.f;
        ss += v * v;
        hb[j] = __float2bfloat16_rn(v);
        lb[j] = __float2bfloat16_rn(v - __bfloat162float(hb[j]));
    }
    __nv_bfloat162 h01, h23, l01, l23;
    h01.x = hb[0]; h01.y = hb[1]; h23.x = hb[2]; h23.y = hb[3];
    l01.x = lb[0]; l01.y = lb[1]; l23.x = lb[2]; l23.y = lb[3];
    *(__nv_bfloat162*)&hi[(size_t)row * 128 + base]     = h01;
    *(__nv_bfloat162*)&hi[(size_t)row * 128 + base + 2] = h23;
    *(__nv_bfloat162*)&lo[(size_t)row * 128 + base]     = l01;
    *(__nv_bfloat162*)&lo[(size_t)row * 128 + base + 2] = l23;

#pragma unroll
    for (int off = 16; off > 0; off >>= 1) ss += __shfl_down_sync(0xFFFFFFFFu, ss, off);
    if (lane == 0 && row < Mreal) nrm[row] = ss;
}

// ---------------------------------------------------------------------------
// Tensor-core bf16x3 distance GEMM + per-(query,tile) min output.
// ---------------------------------------------------------------------------
__device__ __forceinline__ void tile_load_async(
    const __nv_bfloat16* __restrict__ Ap, const __nv_bfloat16* __restrict__ Bp,
    __nv_bfloat16* As, __nv_bfloat16* Bs, int m0, int n0, int k0, int lr, int lh)
{
    uint32_t sa = (uint32_t)__cvta_generic_to_shared(As + lr * 24 + lh * 8);
    uint32_t sb = (uint32_t)__cvta_generic_to_shared(Bs + lr * 24 + lh * 8);
    const void* ga = Ap + (size_t)(m0 + lr) * 128 + k0 + lh * 8;
    const void* gb = Bp + (size_t)(n0 + lr) * 128 + k0 + lh * 8;
    asm volatile(
        "cp.async.cg.shared.global [%0], [%1], 16;\n\t"
        "cp.async.cg.shared.global [%2], [%3], 16;\n\t"
        "cp.async.commit_group;\n"
        :: "r"(sa), "l"(ga), "r"(sb), "l"(gb));
}

__global__ void __launch_bounds__(256)
mma_dist_kernel(const __nv_bfloat16* __restrict__ Qhi, const __nv_bfloat16* __restrict__ Qlo,
                const __nv_bfloat16* __restrict__ Thi, const __nv_bfloat16* __restrict__ Tlo,
                const float* __restrict__ qn, const float* __restrict__ tn,
                float* __restrict__ out, float* __restrict__ gmin, int KP)
{
    __shared__ __align__(16) __nv_bfloat16 As[2][128 * 24];
    __shared__ __align__(16) __nv_bfloat16 Bs[2][128 * 24];
    __shared__ float sMin[128][2];
    const int tid = threadIdx.x;
    const int wid = tid >> 5, lane = tid & 31;
    const int n0 = blockIdx.x * 128;
    const int m0 = blockIdx.y * 128;
    const int wm = (wid & 3) * 32;
    const int wn = (wid >> 2) * 64;

    const int lr = tid >> 1, lh = tid & 1;
    const int fr = lane >> 2, fc = (lane & 3) * 2;

    float acc[2][8][4];
#pragma unroll
    for (int mt = 0; mt < 2; mt++)
#pragma unroll
        for (int nt = 0; nt < 8; nt++)
#pragma unroll
            for (int j = 0; j < 4; j++) acc[mt][nt][j] = 0.f;

    const int S = 3 * (KP >> 4);
    tile_load_async(Qhi, Thi, As[0], Bs[0], m0, n0, 0, lr, lh);

    int nseg = 0, nk = 16;
    for (int s = 0; s < S; s++) {
        int buf = s & 1;
        if (s + 1 < S) {
            if (nk == KP) { nk = 0; nseg++; }
            const __nv_bfloat16* Ap = (nseg == 1) ? Qlo : Qhi;
            const __nv_bfloat16* Bp = (nseg == 2) ? Tlo : Thi;
            tile_load_async(Ap, Bp, As[buf ^ 1], Bs[buf ^ 1], m0, n0, nk, lr, lh);
            nk += 16;
            asm volatile("cp.async.wait_group 1;" ::: "memory");
        } else {
            asm volatile("cp.async.wait_group 0;" ::: "memory");
        }
        __syncthreads();

        const __nv_bfloat16* Ab = As[buf];
        const __nv_bfloat16* Bb = Bs[buf];
        uint32_t a[2][4];
#pragma unroll
        for (int mt = 0; mt < 2; mt++) {
            int basem = wm + mt * 16;
            a[mt][0] = *(const uint32_t*)&Ab[(basem + fr) * 24 + fc];
            a[mt][1] = *(const uint32_t*)&Ab[(basem + fr + 8) * 24 + fc];
            a[mt][2] = *(const uint32_t*)&Ab[(basem + fr) * 24 + fc + 8];
            a[mt][3] = *(const uint32_t*)&Ab[(basem + fr + 8) * 24 + fc + 8];
        }
#pragma unroll
        for (int nt = 0; nt < 8; nt++) {
            uint32_t b[2];
            int nb = wn + nt * 8;
            b[0] = *(const uint32_t*)&Bb[(nb + fr) * 24 + fc];
            b[1] = *(const uint32_t*)&Bb[(nb + fr) * 24 + fc + 8];
            mma_bf16(acc[0][nt], a[0], b);
            mma_bf16(acc[1][nt], a[1], b);
        }
        __syncthreads();
    }

    const float FINF = __int_as_float(0x7F800000);
    float rmin[2][2] = {{FINF, FINF}, {FINF, FINF}};

#pragma unroll
    for (int mt = 0; mt < 2; mt++) {
        int mrow = m0 + wm + mt * 16 + fr;
        float q0 = qn[mrow], q1 = qn[mrow + 8];
#pragma unroll
        for (int nt = 0; nt < 8; nt++) {
            int n = n0 + wn + nt * 8 + fc;
            if (n < NT) {
                float t0 = tn[n], t1 = tn[n + 1];
                float2 o;
                o.x = fmaxf(q0 + t0 - 2.f * acc[mt][nt][0], 0.f);
                o.y = fmaxf(q0 + t1 - 2.f * acc[mt][nt][1], 0.f);
                *(float2*)&out[(size_t)mrow * NT + n] = o;
                rmin[mt][0] = fminf(rmin[mt][0], fminf(o.x, o.y));
                o.x = fmaxf(q1 + t0 - 2.f * acc[mt][nt][2], 0.f);
                o.y = fmaxf(q1 + t1 - 2.f * acc[mt][nt][3], 0.f);
                *(float2*)&out[(size_t)(mrow + 8) * NT + n] = o;
                rmin[mt][1] = fminf(rmin[mt][1], fminf(o.x, o.y));
            }
        }
    }
    // reduce min across the 4 lanes sharing a row, then combine wn halves
#pragma unroll
    for (int mt = 0; mt < 2; mt++)
#pragma unroll
        for (int rr = 0; rr < 2; rr++) {
            float m = rmin[mt][rr];
            m = fminf(m, __shfl_xor_sync(0xFFFFFFFFu, m, 1));
            m = fminf(m, __shfl_xor_sync(0xFFFFFFFFu, m, 2));
            if ((lane & 3) == 0)
                sMin[wm + mt * 16 + rr * 8 + fr][wn >> 6] = m;
        }
    __syncthreads();
    if (tid < 128)
        gmin[(size_t)(m0 + tid) * NTILES + blockIdx.x] =
            fminf(sMin[tid][0], sMin[tid][1]);
}

// ---------------------------------------------------------------------------
// Generic fused linear + ReLU
// ---------------------------------------------------------------------------
__global__ void __launch_bounds__(256)
linear_relu_kernel(const float* __restrict__ A, const float* __restrict__ W,
                   const float* __restrict__ bias, float* __restrict__ out,
                   int M, int K)
{
    __shared__ __align__(16) float As[16 * 68];
    __shared__ __align__(16) float Bs[16 * 136];
    const int tx = threadIdx.x, ty = threadIdx.y;
    const int tid = ty * 16 + tx;
    const int m0 = blockIdx.x * 64;

    float acc[4][8];
#pragma unroll
    for (int r = 0; r < 4; r++)
#pragma unroll
        for (int c = 0; c < 8; c++) acc[r][c] = 0.f;

    const int nChunks = (K + 15) / 16;
    for (int ch = 0; ch < nChunks; ch++) {
        const int k0 = ch * 16;
#pragma unroll
        for (int i = 0; i < 4; i++) {
            int e = tid + i * 256;
            int k = e & 15, m = e >> 4;
            float v = 0.f;
            if (k0 + k < K && m0 + m < M) v = A[(size_t)(m0 + m) * K + k0 + k];
            As[k * 68 + m] = v;
        }
#pragma unroll
        for (int i = 0; i < 8; i++) {
            int e = tid + i * 256;
            int h = e & 127, k = e >> 7;
            float v = 0.f;
            if (k0 + k < K) v = W[(size_t)(k0 + k) * HD + h];
            Bs[k * 136 + h] = v;
        }
        __syncthreads();
#pragma unroll
        for (int k = 0; k < 16; k++) {
            float4 a  = *(const float4*)&As[k * 68 + ty * 4];
            float4 b0 = *(const float4*)&Bs[k * 136 + tx * 4];
            float4 b1 = *(const float4*)&Bs[k * 136 + 64 + tx * 4];
            float av[4] = {a.x, a.y, a.z, a.w};
            float bv[8] = {b0.x, b0.y, b0.z, b0.w, b1.x, b1.y, b1.z, b1.w};
#pragma unroll
            for (int r = 0; r < 4; r++)
#pragma unroll
                for (int c = 0; c < 8; c++) acc[r][c] += av[r] * bv[c];
        }
        __syncthreads();
    }
#pragma unroll
    for (int r = 0; r < 4; r++) {
        int m = m0 + ty * 4 + r;
        if (m >= M) continue;
#pragma unroll
        for (int half = 0; half < 2; half++) {
#pragma unroll
            for (int c = 0; c < 4; c++) {
                int h = half * 64 + tx * 4 + c;
                float v = acc[r][half * 4 + c] + bias[h];
                out[(size_t)m * HD + h] = fmaxf(v, 0.f);
            }
        }
    }
}

// ---------------------------------------------------------------------------
__global__ void __launch_bounds__(256)
linear_softmax_kernel(const float* __restrict__ A, const float* __restrict__ W,
                      const float* __restrict__ bias, float* __restrict__ out, int M)
{
    __shared__ float Ws[HD * NL];
    __shared__ float bs[NL];
    int tid = threadIdx.x;
    for (int i = tid; i < HD * NL; i += 256) Ws[i] = W[i];
    if (tid < NL) bs[tid] = bias[tid];
    __syncthreads();

    int warp = tid >> 5, lane = tid & 31;
    int m = blockIdx.x * 8 + warp;
    if (m >= M) return;

    float acc[NL];
#pragma unroll
    for (int h = 0; h < NL; h++) acc[h] = 0.f;
    for (int k = lane; k < HD; k += 32) {
        float x = A[(size_t)m * HD + k];
#pragma unroll
        for (int h = 0; h < NL; h++) acc[h] += x * Ws[k * NL + h];
    }
#pragma unroll
    for (int h = 0; h < NL; h++)
#pragma unroll
        for (int off = 16; off > 0; off >>= 1)
            acc[h] += __shfl_down_sync(0xFFFFFFFFu, acc[h], off);

    if (lane == 0) {
        float v[NL], mx = -1e30f;
#pragma unroll
        for (int h = 0; h < NL; h++) { v[h] = acc[h] + bs[h]; mx = fmaxf(mx, v[h]); }
        float s = 0.f;
#pragma unroll
        for (int h = 0; h < NL; h++) { v[h] = expf(v[h] - mx); s += v[h]; }
        float inv = 1.0f / s;
#pragma unroll
        for (int h = 0; h < NL; h++) out[(size_t)m * NL + h] = v[h] * inv;
    }
}

// ---------------------------------------------------------------------------
__global__ void __launch_bounds__(256)
rownorm_kernel(const float* __restrict__ A, float* __restrict__ out, int M, int D)
{
    int warp = threadIdx.x >> 5, lane = threadIdx.x & 31;
    int m = blockIdx.x * 8 + warp;
    if (m >= M) return;
    float s = 0.f;
    for (int k = lane; k < D; k += 32) { float v = A[(size_t)m * D + k]; s += v * v; }
#pragma unroll
    for (int off = 16; off > 0; off >>= 1) s += __shfl_down_sync(0xFFFFFFFFu, s, off);
    if (lane == 0) out[m] = s;
}

// ---------------------------------------------------------------------------
// SIMT fp32 distance GEMM (layer 4, D=8) + per-(query,tile) min output.
// ---------------------------------------------------------------------------
__global__ void __launch_bounds__(256)
dist_kernel(const float* __restrict__ Q, const float* __restrict__ T,
            const float* __restrict__ qn, const float* __restrict__ tn,
            float* __restrict__ out, float* __restrict__ gmin, int D, int Ncols)
{
    __shared__ __align__(16) float As[16 * 68];
    __shared__ __align__(16) float Bs[16 * 136];
    __shared__ unsigned sMinU[64];
    const int tx = threadIdx.x, ty = threadIdx.y;
    const int tid = ty * 16 + tx;
    const int n0 = blockIdx.x * 128;
    const int m0 = blockIdx.y * 64;

    if (tid < 64) sMinU[tid] = 0x7F800000u;

    float acc[4][8];
#pragma unroll
    for (int r = 0; r < 4; r++)
#pragma unroll
        for (int c = 0; c < 8; c++) acc[r][c] = 0.f;

    const int nChunks = (D + 15) / 16;
    for (int ch = 0; ch < nChunks; ch++) {
        const int k0 = ch * 16;
#pragma unroll
        for (int i = 0; i < 4; i++) {
            int e = tid + i * 256;
            int k = e & 15, m = e >> 4;
            float v = (k0 + k < D) ? Q[(size_t)(m0 + m) * D + k0 + k] : 0.f;
            As[k * 68 + m] = v;
        }
#pragma unroll
        for (int i = 0; i < 8; i++) {
            int e = tid + i * 256;
            int k = e & 15, n = e >> 4;
            int gn = n0 + n;
            float v = 0.f;
            if (k0 + k < D && gn < Ncols) v = T[(size_t)gn * D + k0 + k];
            Bs[k * 136 + n] = v;
        }
        __syncthreads();
#pragma unroll
        for (int k = 0; k < 16; k++) {
            float4 a  = *(const float4*)&As[k * 68 + ty * 4];
            float4 b0 = *(const float4*)&Bs[k * 136 + tx * 4];
            float4 b1 = *(const float4*)&Bs[k * 136 + 64 + tx * 4];
            float av[4] = {a.x, a.y, a.z, a.w};
            float bv[8] = {b0.x, b0.y, b0.z, b0.w, b1.x, b1.y, b1.z, b1.w};
#pragma unroll
            for (int r = 0; r < 4; r++)
#pragma unroll
                for (int c = 0; c < 8; c++) acc[r][c] += av[r] * bv[c];
        }
        __syncthreads();
    }
    const float FINF = __int_as_float(0x7F800000);
#pragma unroll
    for (int r = 0; r < 4; r++) {
        int m = m0 + ty * 4 + r;
        float qv = qn[m];
        float lm = FINF;
#pragma unroll
        for (int half = 0; half < 2; half++) {
#pragma unroll
            for (int c = 0; c < 4; c++) {
                int n = n0 + half * 64 + tx * 4 + c;
                if (n < Ncols) {
                    float d = fmaxf(qv + tn[n] - 2.f * acc[r][half * 4 + c], 0.f);
                    out[(size_t)m * Ncols + n] = d;
                    lm = fminf(lm, d);
                }
            }
        }
        if (lm < FINF) atomicMin(&sMinU[ty * 4 + r], __float_as_uint(lm));
    }
    __syncthreads();
    if (tid < 64)
        gmin[(size_t)(m0 + tid) * NTILES + blockIdx.x] = __uint_as_float(sMinU[tid]);
}

// ---------------------------------------------------------------------------
// Exact top-K select v3: tile-min threshold + single-scan compaction.
// ---------------------------------------------------------------------------
#define SEL_THREADS 512
#define SEL_CAP 2048
// layout: hist[4096]u32 | cand[2048]u64 | sel[128]u64 | ties[128]u64 | tlab[128]int | mins[392]f
#define OFF_CAND  16384
#define OFF_SEL   (OFF_CAND + SEL_CAP * 8)
#define OFF_TIES  (OFF_SEL + 1024)
#define OFF_TLAB  (OFF_TIES + 1024)
#define OFF_MINS  (OFF_TLAB + 512)
#define SEL_SMEM  (OFF_MINS + 392 * 4)

__device__ __forceinline__ void find_kth(const unsigned* hist, int NB, unsigned kth,
                                         int tid, unsigned* s_bin, unsigned* s_kthr)
{
    if (tid < 32) {
        unsigned running = 0;
        for (int base = 0; base < NB; base += 32) {
            unsigned v = hist[base + tid];
            unsigned sc = v;
#pragma unroll
            for (int off = 1; off < 32; off <<= 1) {
                unsigned t = __shfl_up_sync(0xFFFFFFFFu, sc, off);
                if (tid >= off) sc += t;
            }
            unsigned tot = __shfl_sync(0xFFFFFFFFu, sc, 31);
            if (running + tot >= kth) {
                unsigned mask = __ballot_sync(0xFFFFFFFFu, running + sc >= kth);
                int l = __ffs(mask) - 1;
                if (tid == l) { *s_bin = (unsigned)(base + l); *s_kthr = kth - running - (sc - v); }
                break;
            }
            running += tot;
        }
    }
}

__global__ void __launch_bounds__(SEL_THREADS)
select_kernel(const float* __restrict__ d2mat, const float* __restrict__ gmin,
              const int* __restrict__ labels, float* __restrict__ total, int init)
{
    extern __shared__ __align__(16) char sms[];
    unsigned* hist = (unsigned*)sms;
    u64* cand  = (u64*)(sms + OFF_CAND);
    u64* sel   = (u64*)(sms + OFF_SEL);
    u64* ties  = (u64*)(sms + OFF_TIES);
    int* tlab  = (int*)(sms + OFF_TLAB);
    float* mins = (float*)(sms + OFF_MINS);

    __shared__ unsigned s_M75, s_bin, s_kthr, s_candcnt, s_selcnt, s_tiecnt;
    __shared__ float s_w[80];
    __shared__ int s_lab[80];

    const int b = blockIdx.x, tid = threadIdx.x, lane = tid & 31;
    const float4* src = (const float4*)(d2mat + (size_t)b * NT);
    const int NIT = (NT / 4 + SEL_THREADS - 1) / SEL_THREADS;

    // ---- phase 0: threshold from tile minima (M75 = 75th smallest of 391) ----
    for (int i = tid; i < NTILES; i += SEL_THREADS)
        mins[i] = gmin[(size_t)b * NTILES + i];
    if (tid == 0) { s_candcnt = 0; s_selcnt = 0; s_tiecnt = 0; }
    __syncthreads();
    if (tid < NTILES) {
        unsigned key = __float_as_uint(mins[tid]);
        int c = 0;
        for (int j = 0; j < NTILES; j++) {
            unsigned kj = __float_as_uint(mins[j]);
            c += (kj < key) || (kj == key && j < tid);
        }
        if (c == KNN - 1) s_M75 = key;
    }
    __syncthreads();
    const unsigned Mkey = s_M75;

    // ---- phase 1: single full scan, compact elements with key <= Mkey ----
    for (int it = 0; it < NIT; it++) {
        int i = it * SEL_THREADS + tid;
        if (i < NT / 4) {
            float4 v = src[i];
            float e[4] = {v.x, v.y, v.z, v.w};
#pragma unroll
            for (int j = 0; j < 4; j++) {
                unsigned key = __float_as_uint(e[j]);
                if (key <= Mkey) {
                    unsigned s = atomicAdd(&s_candcnt, 1u);
                    if (s < SEL_CAP) cand[s] = ((u64)key << 32) | (unsigned)(i * 4 + j);
                }
            }
        }
    }
    __syncthreads();

    unsigned Tkey;
    const unsigned candTotal = s_candcnt;   // provably >= KNN

    if (candTotal <= SEL_CAP) {
        const int cc = (int)candTotal;
        // pass 0: top-12 bits
        for (int i = tid; i < 4096; i += SEL_THREADS) hist[i] = 0;
        __syncthreads();
        for (int i = tid; i < cc; i += SEL_THREADS)
            atomicAdd(&hist[(unsigned)(cand[i] >> 52)], 1u);
        __syncthreads();
        find_kth(hist, 4096, KNN, tid, &s_bin, &s_kthr);
        __syncthreads();
        const unsigned pfx = s_bin;
        const unsigned k1 = s_kthr;
        // pass A: bits 19..8
        for (int i = tid; i < 4096; i += SEL_THREADS) hist[i] = 0;
        __syncthreads();
        for (int i = tid; i < cc; i += SEL_THREADS) {
            unsigned key = (unsigned)(cand[i] >> 32);
            if ((key >> 20) == pfx) atomicAdd(&hist[(key >> 8) & 0xFFFu], 1u);
        }
        __syncthreads();
        find_kth(hist, 4096, k1, tid, &s_bin, &s_kthr);
        __syncthreads();
        const unsigned pfx20 = (pfx << 12) | s_bin;
        const unsigned k2 = s_kthr;
        // pass B: low byte
        for (int i = tid; i < 256; i += SEL_THREADS) hist[i] = 0;
        __syncthreads();
        for (int i = tid; i < cc; i += SEL_THREADS) {
            unsigned key = (unsigned)(cand[i] >> 32);
            if ((key >> 8) == pfx20) atomicAdd(&hist[key & 0xFFu], 1u);
        }
        __syncthreads();
        find_kth(hist, 256, k2, tid, &s_bin, &s_kthr);
        __syncthreads();
        Tkey = (pfx20 << 8) | s_bin;
        // gather winners and ties from candidate list
        for (int i = tid; i < cc; i += SEL_THREADS) {
            u64 cv = cand[i];
            unsigned key = (unsigned)(cv >> 32);
            if (key < Tkey) {
                unsigned s = atomicAdd(&s_selcnt, 1u);
                if (s < 128) sel[s] = cv;
            } else if (key == Tkey) {
                unsigned s = atomicAdd(&s_tiecnt, 1u);
                if (s < 128) ties[s] = cv;
            }
        }
        __syncthreads();
    } else {
        // ---- fallback: full gmem radix passes (degenerate distributions) ----
        for (int i = tid; i < 4096; i += SEL_THREADS) hist[i] = 0;
        __syncthreads();
        for (int it = 0; it < NIT; it++) {
            int i = it * SEL_THREADS + tid;
            bool valid = (i < NT / 4);
            float4 v = valid ? src[i] : make_float4(0.f, 0.f, 0.f, 0.f);
            float e[4] = {v.x, v.y, v.z, v.w};
#pragma unroll
            for (int j = 0; j < 4; j++) {
                unsigned bin = valid ? (__float_as_uint(e[j]) >> 20) : 0xFFFFFFFFu;
                unsigned grp = __match_any_sync(0xFFFFFFFFu, bin);
                if (bin != 0xFFFFFFFFu && lane == __ffs(grp) - 1)
                    atomicAdd(&hist[bin], (unsigned)__popc(grp));
            }
        }
        __syncthreads();
        find_kth(hist, 4096, KNN, tid, &s_bin, &s_kthr);
        __syncthreads();
        const unsigned pfx = s_bin;
        const unsigned k1 = s_kthr;

        for (int i = tid; i < 4096; i += SEL_THREADS) hist[i] = 0;
        __syncthreads();
        for (int it = 0; it < NIT; it++) {
            int i = it * SEL_THREADS + tid;
            bool valid = (i < NT / 4);
            float4 v = valid ? src[i] : make_float4(0.f, 0.f, 0.f, 0.f);
            float e[4] = {v.x, v.y, v.z, v.w};
#pragma unroll
            for (int j = 0; j < 4; j++) {
                unsigned key = __float_as_uint(e[j]);
                unsigned bin = (valid && (key >> 20) == pfx) ? ((key >> 8) & 0xFFFu)
                                                             : 0xFFFFFFFFu;
                unsigned grp = __match_any_sync(0xFFFFFFFFu, bin);
                if (bin != 0xFFFFFFFFu && lane == __ffs(grp) - 1)
                    atomicAdd(&hist[bin], (unsigned)__popc(grp));
            }
        }
        __syncthreads();
        find_kth(hist, 4096, k1, tid, &s_bin, &s_kthr);
        __syncthreads();
        const unsigned pfx20 = (pfx << 12) | s_bin;
        const unsigned k2 = s_kthr;

        for (int i = tid; i < 256; i += SEL_THREADS) hist[i] = 0;
        __syncthreads();
        for (int it = 0; it < NIT; it++) {
            int i = it * SEL_THREADS + tid;
            bool valid = (i < NT / 4);
            float4 v = valid ? src[i] : make_float4(0.f, 0.f, 0.f, 0.f);
            float e[4] = {v.x, v.y, v.z, v.w};
#pragma unroll
            for (int j = 0; j < 4; j++) {
                unsigned key = __float_as_uint(e[j]);
                unsigned bin = (valid && (key >> 8) == pfx20) ? (key & 0xFFu)
                                                              : 0xFFFFFFFFu;
                unsigned grp = __match_any_sync(0xFFFFFFFFu, bin);
                if (bin != 0xFFFFFFFFu && lane == __ffs(grp) - 1)
                    atomicAdd(&hist[bin], (unsigned)__popc(grp));
            }
        }
        __syncthreads();
        find_kth(hist, 256, k2, tid, &s_bin, &s_kthr);
        __syncthreads();
        Tkey = (pfx20 << 8) | s_bin;

        for (int it = 0; it < NIT; it++) {
            int i = it * SEL_THREADS + tid;
            if (i < NT / 4) {
                float4 v = src[i];
                float e[4] = {v.x, v.y, v.z, v.w};
#pragma unroll
                for (int j = 0; j < 4; j++) {
                    unsigned key = __float_as_uint(e[j]);
                    if (key < Tkey) {
                        unsigned s = atomicAdd(&s_selcnt, 1u);
                        if (s < 128) sel[s] = ((u64)key << 32) | (unsigned)(i * 4 + j);
                    } else if (key == Tkey) {
                        unsigned s = atomicAdd(&s_tiecnt, 1u);
                        if (s < 128) ties[s] = ((u64)key << 32) | (unsigned)(i * 4 + j);
                    }
                }
            }
        }
        __syncthreads();
    }

    const int ns = min((int)s_selcnt, 128);   // provably <= 74
    const int ne = min((int)s_tiecnt, 128);

    // deterministic rank-by-index ordering
    if (tid < ns) {
        u64 mine = sel[tid];
        unsigned my_idx = (unsigned)(mine & 0xFFFFFFFFu);
        int rank = 0;
        for (int j = 0; j < ns; j++) rank += ((unsigned)(sel[j] & 0xFFFFFFFFu) < my_idx);
        float d2 = __uint_as_float((unsigned)(mine >> 32));
        s_w[rank] = (d2 > 0.f) ? __fdiv_rn(1.0f, __fsqrt_rn(d2)) : 0.f;
        s_lab[rank] = labels[my_idx];
    }
    if (tid >= 128 && tid - 128 < ne) {
        int t = tid - 128;
        unsigned my_idx = (unsigned)(ties[t] & 0xFFFFFFFFu);
        int rank = 0;
        for (int j = 0; j < ne; j++) rank += ((unsigned)(ties[j] & 0xFFFFFFFFu) < my_idx);
        tlab[rank] = labels[my_idx];
    }
    __syncthreads();

    if (tid == 0) {
        float cls[NL];
#pragma unroll
        for (int l = 0; l < NL; l++) cls[l] = 0.f;
        float stot = 0.f;
        for (int j = 0; j < ns; j++) { stot += s_w[j]; cls[s_lab[j]] += s_w[j]; }
        int need = KNN - ns;
        float d2T = __uint_as_float(Tkey);
        float wT = (d2T > 0.f) ? __fdiv_rn(1.0f, __fsqrt_rn(d2T)) : 0.f;
        int m = (need < ne) ? need : ne;
        for (int j = 0; j < m; j++) { stot += wT; cls[tlab[j]] += wT; }
#pragma unroll
        for (int l = 0; l < NL; l++) {
            float val = stot - cls[l];
            size_t o = (size_t)b * NL + l;
            if (init) total[o] = val; else total[o] += val;
        }
    }
}

// ---------------------------------------------------------------------------
__global__ void __launch_bounds__(256)
pvalue_kernel(const float* __restrict__ total, const float* __restrict__ cali,
              float* __restrict__ out)
{
    const int b = blockIdx.x, tid = threadIdx.x;
    float t[NL];
#pragma unroll
    for (int l = 0; l < NL; l++) t[l] = total[(size_t)b * NL + l];
    int cnt[NL];
#pragma unroll
    for (int l = 0; l < NL; l++) cnt[l] = 0;
    for (int i = tid; i < NC; i += 256) {
        float c = cali[i];
#pragma unroll
        for (int l = 0; l < NL; l++) cnt[l] += (c >= t[l]) ? 1 : 0;
    }
    __shared__ int sc[NL];
    if (tid < NL) sc[tid] = 0;
    __syncthreads();
#pragma unroll
    for (int l = 0; l < NL; l++) atomicAdd(&sc[l], cnt[l]);
    __syncthreads();
    if (tid < NL) out[(size_t)b * NL + tid] = (float)sc[tid] * (1.0f / NC);
}

// ---------------------------------------------------------------------------
extern "C" void kernel_launch(void* const* d_in, const int* in_sizes, int n_in,
                              void* d_out, int out_size)
{
    const float* x        = (const float*)d_in[0];
    const float* train_x  = (const float*)d_in[1];
    const int*   lab      = (const int*)  d_in[2];
    const float* cali     = (const float*)d_in[3];
    const float* W1 = (const float*)d_in[4];  const float* b1 = (const float*)d_in[5];
    const float* W2 = (const float*)d_in[6];  const float* b2 = (const float*)d_in[7];
    const float* W3 = (const float*)d_in[8];  const float* b3 = (const float*)d_in[9];
    const float* W4 = (const float*)d_in[10]; const float* b4 = (const float*)d_in[11];
    float* out = (float*)d_out;

    float *h1p, *h2p, *h3p, *q4p, *t1p, *t2p, *t3p, *t4p, *d2p, *qnp, *tnp, *totp, *minp;
    __nv_bfloat16 *qhip, *qlop, *thip, *tlop;
    cudaGetSymbolAddress((void**)&h1p, g_h1);
    cudaGetSymbolAddress((void**)&h2p, g_h2);
    cudaGetSymbolAddress((void**)&h3p, g_h3);
    cudaGetSymbolAddress((void**)&q4p, g_q4);
    cudaGetSymbolAddress((void**)&t1p, g_t1);
    cudaGetSymbolAddress((void**)&t2p, g_t2);
    cudaGetSymbolAddress((void**)&t3p, g_t3);
    cudaGetSymbolAddress((void**)&t4p, g_t4);
    cudaGetSymbolAddress((void**)&d2p, g_d2);
    cudaGetSymbolAddress((void**)&minp, g_min);
    cudaGetSymbolAddress((void**)&qnp, g_qn);
    cudaGetSymbolAddress((void**)&tnp, g_tn);
    cudaGetSymbolAddress((void**)&totp, g_tot);
    cudaGetSymbolAddress((void**)&qhip, g_qhi);
    cudaGetSymbolAddress((void**)&qlop, g_qlo);
    cudaGetSymbolAddress((void**)&thip, g_thi);
    cudaGetSymbolAddress((void**)&tlop, g_tlo);

    cudaFuncSetAttribute(select_kernel,
                         cudaFuncAttributeMaxDynamicSharedMemorySize, SEL_SMEM);

    dim3 tb(16, 16);
    const int D0 = 83;
    const dim3 mgrid(NTILES, BQ / 128);

    // ---- layer 0 first (select_kernel = launch #4 -> gets profiled) ----
    conv_norm_kernel<<<BQ / 8, 256>>>(x, qhip, qlop, qnp, BQ, D0);
    conv_norm_kernel<<<NTP / 8, 256>>>(train_x, thip, tlop, tnp, NT, D0);
    mma_dist_kernel<<<mgrid, 256>>>(qhip, qlop, thip, tlop, qnp, tnp, d2p, minp, 96);
    select_kernel<<<BQ, SEL_THREADS, SEL_SMEM>>>(d2p, minp, lab, totp, 1);

    // ---- MLPs ----
    linear_relu_kernel<<<BQ / 64, tb>>>(x,   W1, b1, h1p, BQ, D0);
    linear_relu_kernel<<<BQ / 64, tb>>>(h1p, W2, b2, h2p, BQ, HD);
    linear_relu_kernel<<<BQ / 64, tb>>>(h2p, W3, b3, h3p, BQ, HD);
    linear_softmax_kernel<<<(BQ + 7) / 8, 256>>>(h3p, W4, b4, q4p, BQ);
    const int gtm = (NT + 63) / 64;
    linear_relu_kernel<<<gtm, tb>>>(train_x, W1, b1, t1p, NT, D0);
    linear_relu_kernel<<<gtm, tb>>>(t1p,     W2, b2, t2p, NT, HD);
    linear_relu_kernel<<<gtm, tb>>>(t2p,     W3, b3, t3p, NT, HD);
    linear_softmax_kernel<<<(NT + 7) / 8, 256>>>(t3p, W4, b4, t4p, NT);

    // ---- layers 1-3 ----
    const float* Qs[3] = {h1p, h2p, h3p};
    const float* Ts[3] = {t1p, t2p, t3p};
    for (int i = 0; i < 3; i++) {
        conv_norm_kernel<<<BQ / 8, 256>>>(Qs[i], qhip, qlop, qnp, BQ, HD);
        conv_norm_kernel<<<NTP / 8, 256>>>(Ts[i], thip, tlop, tnp, NT, HD);
        mma_dist_kernel<<<mgrid, 256>>>(qhip, qlop, thip, tlop, qnp, tnp, d2p, minp, 128);
        select_kernel<<<BQ, SEL_THREADS, SEL_SMEM>>>(d2p, minp, lab, totp, 0);
    }

    // ---- layer 4 (softmax features, D=8): exact fp32 path ----
    rownorm_kernel<<<(BQ + 7) / 8, 256>>>(q4p, qnp, BQ, NL);
    rownorm_kernel<<<(NT + 7) / 8, 256>>>(t4p, tnp, NT, NL);
    dist_kernel<<<dim3(NTILES, BQ / 64), tb>>>(q4p, t4p, qnp, tnp, d2p, minp, NL, NT);
    select_kernel<<<BQ, SEL_THREADS, SEL_SMEM>>>(d2p, minp, lab, totp, 0);

    // ---- p-values ----
    pvalue_kernel<<<BQ, 256>>>(totp, cali, out);
}

// round 7
// speedup vs baseline: 3.5044x; 1.0664x over previous
#include <cuda_runtime.h>
#include <cuda_bf16.h>
#include <math.h>
#include <stdint.h>

#define BQ   1024
#define NT   50000
#define NTP  50048
#define NL   8
#define KNN  75
#define HD   128
#define NC   10000
#define NTILES 391          // NTP/128

typedef unsigned long long u64;

// ---------------- device scratch ----------------
__device__ float g_h1[BQ * HD];
__device__ float g_h2[BQ * HD];
__device__ float g_h3[BQ * HD];
__device__ float g_q4[BQ * NL];
__device__ float g_t3[(size_t)NT * HD];
__device__ float g_t4[(size_t)NT * NL];
__device__ float g_d2[(size_t)BQ * NT];
__device__ float g_min[(size_t)BQ * NTILES];
__device__ float g_qn[BQ];
__device__ float g_tn[NT];
__device__ float g_tot[BQ * NL];
__device__ __nv_bfloat16 g_qhi[(size_t)BQ * 128];
__device__ __nv_bfloat16 g_qlo[(size_t)BQ * 128];
__device__ __nv_bfloat16 g_thi[(size_t)NTP * 128];    // bank A
__device__ __nv_bfloat16 g_tlo[(size_t)NTP * 128];
__device__ __nv_bfloat16 g_thi2[(size_t)NTP * 128];   // bank B
__device__ __nv_bfloat16 g_tlo2[(size_t)NTP * 128];
// transposed weight banks (n-major rows, k cols, zero padded)
__device__ __nv_bfloat16 g_w1th[128 * 128], g_w1tl[128 * 128];
__device__ __nv_bfloat16 g_w2th[128 * 128], g_w2tl[128 * 128];
__device__ __nv_bfloat16 g_w3th[128 * 128], g_w3tl[128 * 128];

// ---------------------------------------------------------------------------
__device__ __forceinline__ void mma_bf16(float* d, const uint32_t* a, const uint32_t* b)
{
    asm volatile(
        "mma.sync.aligned.m16n8k16.row.col.f32.bf16.bf16.f32 "
        "{%0,%1,%2,%3}, {%4,%5,%6,%7}, {%8,%9}, {%0,%1,%2,%3};"
        : "+f"(d[0]), "+f"(d[1]), "+f"(d[2]), "+f"(d[3])
        : "r"(a[0]), "r"(a[1]), "r"(a[2]), "r"(a[3]), "r"(b[0]), "r"(b[1]));
}

// ---------------------------------------------------------------------------
// Fused split-convert + row norm (one warp per row).
// ---------------------------------------------------------------------------
__global__ void __launch_bounds__(256)
conv_norm_kernel(const float* __restrict__ A, __nv_bfloat16* __restrict__ hi,
                 __nv_bfloat16* __restrict__ lo, float* __restrict__ nrm,
                 int Mreal, int D)
{
    int warp = threadIdx.x >> 5, lane = threadIdx.x & 31;
    int row = blockIdx.x * 8 + warp;
    int base = lane * 4;

    float ss = 0.f;
    __nv_bfloat16 hb[4], lb[4];
#pragma unroll
    for (int j = 0; j < 4; j++) {
        int col = base + j;
        float v = (row < Mreal && col < D) ? A[(size_t)row * D + col] : 0.f;
        ss += v * v;
        hb[j] = __float2bfloat16_rn(v);
        lb[j] = __float2bfloat16_rn(v - __bfloat162float(hb[j]));
    }
    __nv_bfloat162 h01, h23, l01, l23;
    h01.x = hb[0]; h01.y = hb[1]; h23.x = hb[2]; h23.y = hb[3];
    l01.x = lb[0]; l01.y = lb[1]; l23.x = lb[2]; l23.y = lb[3];
    *(__nv_bfloat162*)&hi[(size_t)row * 128 + base]     = h01;
    *(__nv_bfloat162*)&hi[(size_t)row * 128 + base + 2] = h23;
    *(__nv_bfloat162*)&lo[(size_t)row * 128 + base]     = l01;
    *(__nv_bfloat162*)&lo[(size_t)row * 128 + base + 2] = l23;

#pragma unroll
    for (int off = 16; off > 0; off >>= 1) ss += __shfl_down_sync(0xFFFFFFFFu, ss, off);
    if (lane == 0 && row < Mreal) nrm[row] = ss;
}

// ---------------------------------------------------------------------------
// Weight transpose + hi/lo split: W[K x 128] -> Wt[128 x 128] (n-major).
// ---------------------------------------------------------------------------
__global__ void __launch_bounds__(256)
wt_convert_kernel(const float* __restrict__ W1, const float* __restrict__ W2,
                  const float* __restrict__ W3)
{
    int idx = blockIdx.x * 256 + threadIdx.x;
    if (idx >= 3 * 128 * 128) return;
    int which = idx >> 14;
    int e = idx & 16383;
    int n = e & 127, k = e >> 7;
    const float* W = (which == 0) ? W1 : (which == 1) ? W2 : W3;
    int K = (which == 0) ? 83 : 128;
    float v = (k < K) ? W[(size_t)k * 128 + n] : 0.f;
    __nv_bfloat16 h = __float2bfloat16_rn(v);
    __nv_bfloat16 l = __float2bfloat16_rn(v - __bfloat162float(h));
    __nv_bfloat16* dh = (which == 0) ? g_w1th : (which == 1) ? g_w2th : g_w3th;
    __nv_bfloat16* dl = (which == 0) ? g_w1tl : (which == 1) ? g_w2tl : g_w3tl;
    dh[e] = h;
    dl[e] = l;
}

// ---------------------------------------------------------------------------
__device__ __forceinline__ void tile_load_async(
    const __nv_bfloat16* __restrict__ Ap, const __nv_bfloat16* __restrict__ Bp,
    __nv_bfloat16* As, __nv_bfloat16* Bs, int m0, int n0, int k0, int lr, int lh)
{
    uint32_t sa = (uint32_t)__cvta_generic_to_shared(As + lr * 24 + lh * 8);
    uint32_t sb = (uint32_t)__cvta_generic_to_shared(Bs + lr * 24 + lh * 8);
    const void* ga = Ap + (size_t)(m0 + lr) * 128 + k0 + lh * 8;
    const void* gb = Bp + (size_t)(n0 + lr) * 128 + k0 + lh * 8;
    asm volatile(
        "cp.async.cg.shared.global [%0], [%1], 16;\n\t"
        "cp.async.cg.shared.global [%2], [%3], 16;\n\t"
        "cp.async.commit_group;\n"
        :: "r"(sa), "l"(ga), "r"(sb), "l"(gb));
}

// ---------------------------------------------------------------------------
// Tensor-core bf16x3 distance GEMM + per-(query,tile) min output.
// ---------------------------------------------------------------------------
__global__ void __launch_bounds__(256)
mma_dist_kernel(const __nv_bfloat16* __restrict__ Qhi, const __nv_bfloat16* __restrict__ Qlo,
                const __nv_bfloat16* __restrict__ Thi, const __nv_bfloat16* __restrict__ Tlo,
                const float* __restrict__ qn, const float* __restrict__ tn,
                float* __restrict__ out, float* __restrict__ gmin, int KP)
{
    __shared__ __align__(16) __nv_bfloat16 As[2][128 * 24];
    __shared__ __align__(16) __nv_bfloat16 Bs[2][128 * 24];
    __shared__ float sMin[128][2];
    const int tid = threadIdx.x;
    const int wid = tid >> 5, lane = tid & 31;
    const int n0 = blockIdx.x * 128;
    const int m0 = blockIdx.y * 128;
    const int wm = (wid & 3) * 32;
    const int wn = (wid >> 2) * 64;
    const int lr = tid >> 1, lh = tid & 1;
    const int fr = lane >> 2, fc = (lane & 3) * 2;

    float acc[2][8][4];
#pragma unroll
    for (int mt = 0; mt < 2; mt++)
#pragma unroll
        for (int nt = 0; nt < 8; nt++)
#pragma unroll
            for (int j = 0; j < 4; j++) acc[mt][nt][j] = 0.f;

    const int S = 3 * (KP >> 4);
    tile_load_async(Qhi, Thi, As[0], Bs[0], m0, n0, 0, lr, lh);

    int nseg = 0, nk = 16;
    for (int s = 0; s < S; s++) {
        int buf = s & 1;
        if (s + 1 < S) {
            if (nk == KP) { nk = 0; nseg++; }
            const __nv_bfloat16* Ap = (nseg == 1) ? Qlo : Qhi;
            const __nv_bfloat16* Bp = (nseg == 2) ? Tlo : Thi;
            tile_load_async(Ap, Bp, As[buf ^ 1], Bs[buf ^ 1], m0, n0, nk, lr, lh);
            nk += 16;
            asm volatile("cp.async.wait_group 1;" ::: "memory");
        } else {
            asm volatile("cp.async.wait_group 0;" ::: "memory");
        }
        __syncthreads();

        const __nv_bfloat16* Ab = As[buf];
        const __nv_bfloat16* Bb = Bs[buf];
        uint32_t a[2][4];
#pragma unroll
        for (int mt = 0; mt < 2; mt++) {
            int basem = wm + mt * 16;
            a[mt][0] = *(const uint32_t*)&Ab[(basem + fr) * 24 + fc];
            a[mt][1] = *(const uint32_t*)&Ab[(basem + fr + 8) * 24 + fc];
            a[mt][2] = *(const uint32_t*)&Ab[(basem + fr) * 24 + fc + 8];
            a[mt][3] = *(const uint32_t*)&Ab[(basem + fr + 8) * 24 + fc + 8];
        }
#pragma unroll
        for (int nt = 0; nt < 8; nt++) {
            uint32_t b[2];
            int nb = wn + nt * 8;
            b[0] = *(const uint32_t*)&Bb[(nb + fr) * 24 + fc];
            b[1] = *(const uint32_t*)&Bb[(nb + fr) * 24 + fc + 8];
            mma_bf16(acc[0][nt], a[0], b);
            mma_bf16(acc[1][nt], a[1], b);
        }
        __syncthreads();
    }

    const float FINF = __int_as_float(0x7F800000);
    float rmin[2][2] = {{FINF, FINF}, {FINF, FINF}};
#pragma unroll
    for (int mt = 0; mt < 2; mt++) {
        int mrow = m0 + wm + mt * 16 + fr;
        float q0 = qn[mrow], q1 = qn[mrow + 8];
#pragma unroll
        for (int nt = 0; nt < 8; nt++) {
            int n = n0 + wn + nt * 8 + fc;
            if (n < NT) {
                float t0 = tn[n], t1 = tn[n + 1];
                float2 o;
                o.x = fmaxf(q0 + t0 - 2.f * acc[mt][nt][0], 0.f);
                o.y = fmaxf(q0 + t1 - 2.f * acc[mt][nt][1], 0.f);
                *(float2*)&out[(size_t)mrow * NT + n] = o;
                rmin[mt][0] = fminf(rmin[mt][0], fminf(o.x, o.y));
                o.x = fmaxf(q1 + t0 - 2.f * acc[mt][nt][2], 0.f);
                o.y = fmaxf(q1 + t1 - 2.f * acc[mt][nt][3], 0.f);
                *(float2*)&out[(size_t)(mrow + 8) * NT + n] = o;
                rmin[mt][1] = fminf(rmin[mt][1], fminf(o.x, o.y));
            }
        }
    }
#pragma unroll
    for (int mt = 0; mt < 2; mt++)
#pragma unroll
        for (int rr = 0; rr < 2; rr++) {
            float m = rmin[mt][rr];
            m = fminf(m, __shfl_xor_sync(0xFFFFFFFFu, m, 1));
            m = fminf(m, __shfl_xor_sync(0xFFFFFFFFu, m, 2));
            if ((lane & 3) == 0)
                sMin[wm + mt * 16 + rr * 8 + fr][wn >> 6] = m;
        }
    __syncthreads();
    if (tid < 128)
        gmin[(size_t)(m0 + tid) * NTILES + blockIdx.x] =
            fminf(sMin[tid][0], sMin[tid][1]);
}

// ---------------------------------------------------------------------------
// Tensor-core bf16x3 linear+ReLU: out = relu(A @ W + b), A [NTP x 128] banks,
// Wt [128 x 128] transposed hi/lo. Epilogue writes hi/lo banks + norms
// (+ optional fp32). One block = 128 rows x all 128 cols.
// ---------------------------------------------------------------------------
__global__ void __launch_bounds__(256)
mma_linear_kernel(const __nv_bfloat16* __restrict__ Ahi, const __nv_bfloat16* __restrict__ Alo,
                  const __nv_bfloat16* __restrict__ Wth, const __nv_bfloat16* __restrict__ Wtl,
                  const float* __restrict__ bias,
                  __nv_bfloat16* __restrict__ Ohi, __nv_bfloat16* __restrict__ Olo,
                  float* __restrict__ nrm, float* __restrict__ Ofp, int KP)
{
    __shared__ __align__(16) __nv_bfloat16 As[2][128 * 24];
    __shared__ __align__(16) __nv_bfloat16 Bs[2][128 * 24];
    __shared__ float snorm[128];
    __shared__ float sbias[128];
    const int tid = threadIdx.x;
    const int wid = tid >> 5, lane = tid & 31;
    const int m0 = blockIdx.x * 128;
    const int wm = (wid & 3) * 32;
    const int wn = (wid >> 2) * 64;
    const int lr = tid >> 1, lh = tid & 1;
    const int fr = lane >> 2, fc = (lane & 3) * 2;

    if (tid < 128) { sbias[tid] = bias[tid]; snorm[tid] = 0.f; }

    float acc[2][8][4];
#pragma unroll
    for (int mt = 0; mt < 2; mt++)
#pragma unroll
        for (int nt = 0; nt < 8; nt++)
#pragma unroll
            for (int j = 0; j < 4; j++) acc[mt][nt][j] = 0.f;

    const int S = 3 * (KP >> 4);
    tile_load_async(Ahi, Wth, As[0], Bs[0], m0, 0, 0, lr, lh);

    int nseg = 0, nk = 16;
    for (int s = 0; s < S; s++) {
        int buf = s & 1;
        if (s + 1 < S) {
            if (nk == KP) { nk = 0; nseg++; }
            const __nv_bfloat16* Ap = (nseg == 1) ? Alo : Ahi;
            const __nv_bfloat16* Bp = (nseg == 2) ? Wtl : Wth;
            tile_load_async(Ap, Bp, As[buf ^ 1], Bs[buf ^ 1], m0, 0, nk, lr, lh);
            nk += 16;
            asm volatile("cp.async.wait_group 1;" ::: "memory");
        } else {
            asm volatile("cp.async.wait_group 0;" ::: "memory");
        }
        __syncthreads();

        const __nv_bfloat16* Ab = As[buf];
        const __nv_bfloat16* Bb = Bs[buf];
        uint32_t a[2][4];
#pragma unroll
        for (int mt = 0; mt < 2; mt++) {
            int basem = wm + mt * 16;
            a[mt][0] = *(const uint32_t*)&Ab[(basem + fr) * 24 + fc];
            a[mt][1] = *(const uint32_t*)&Ab[(basem + fr + 8) * 24 + fc];
            a[mt][2] = *(const uint32_t*)&Ab[(basem + fr) * 24 + fc + 8];
            a[mt][3] = *(const uint32_t*)&Ab[(basem + fr + 8) * 24 + fc + 8];
        }
#pragma unroll
        for (int nt = 0; nt < 8; nt++) {
            uint32_t b[2];
            int nb = wn + nt * 8;
            b[0] = *(const uint32_t*)&Bb[(nb + fr) * 24 + fc];
            b[1] = *(const uint32_t*)&Bb[(nb + fr) * 24 + fc + 8];
            mma_bf16(acc[0][nt], a[0], b);
            mma_bf16(acc[1][nt], a[1], b);
        }
        __syncthreads();
    }

    // epilogue: relu(acc + b) -> hi/lo banks (+optional fp32) + row norms
#pragma unroll
    for (int mt = 0; mt < 2; mt++) {
        int r0 = wm + mt * 16 + fr;
        int r1 = r0 + 8;
        size_t g0 = (size_t)(m0 + r0) * 128;
        size_t g1 = (size_t)(m0 + r1) * 128;
        float ns0 = 0.f, ns1 = 0.f;
#pragma unroll
        for (int nt = 0; nt < 8; nt++) {
            int n = wn + nt * 8 + fc;
            float b0 = sbias[n], b1 = sbias[n + 1];
            float v00 = fmaxf(acc[mt][nt][0] + b0, 0.f);
            float v01 = fmaxf(acc[mt][nt][1] + b1, 0.f);
            float v10 = fmaxf(acc[mt][nt][2] + b0, 0.f);
            float v11 = fmaxf(acc[mt][nt][3] + b1, 0.f);
            ns0 += v00 * v00 + v01 * v01;
            ns1 += v10 * v10 + v11 * v11;
            __nv_bfloat162 h, l;
            h.x = __float2bfloat16_rn(v00);
            h.y = __float2bfloat16_rn(v01);
            l.x = __float2bfloat16_rn(v00 - __bfloat162float(h.x));
            l.y = __float2bfloat16_rn(v01 - __bfloat162float(h.y));
            *(__nv_bfloat162*)&Ohi[g0 + n] = h;
            *(__nv_bfloat162*)&Olo[g0 + n] = l;
            h.x = __float2bfloat16_rn(v10);
            h.y = __float2bfloat16_rn(v11);
            l.x = __float2bfloat16_rn(v10 - __bfloat162float(h.x));
            l.y = __float2bfloat16_rn(v11 - __bfloat162float(h.y));
            *(__nv_bfloat162*)&Ohi[g1 + n] = h;
            *(__nv_bfloat162*)&Olo[g1 + n] = l;
            if (Ofp) {
                *(float2*)&Ofp[g0 + n] = make_float2(v00, v01);
                *(float2*)&Ofp[g1 + n] = make_float2(v10, v11);
            }
        }
        atomicAdd(&snorm[r0], ns0);
        atomicAdd(&snorm[r1], ns1);
    }
    __syncthreads();
    if (tid < 128 && m0 + tid < NT) nrm[m0 + tid] = snorm[tid];
}

// ---------------------------------------------------------------------------
// Query-side SIMT linear+ReLU (tiny, 1024 rows).
// ---------------------------------------------------------------------------
__global__ void __launch_bounds__(256)
linear_relu_kernel(const float* __restrict__ A, const float* __restrict__ W,
                   const float* __restrict__ bias, float* __restrict__ out,
                   int M, int K)
{
    __shared__ __align__(16) float As[16 * 68];
    __shared__ __align__(16) float Bs[16 * 136];
    const int tx = threadIdx.x, ty = threadIdx.y;
    const int tid = ty * 16 + tx;
    const int m0 = blockIdx.x * 64;

    float acc[4][8];
#pragma unroll
    for (int r = 0; r < 4; r++)
#pragma unroll
        for (int c = 0; c < 8; c++) acc[r][c] = 0.f;

    const int nChunks = (K + 15) / 16;
    for (int ch = 0; ch < nChunks; ch++) {
        const int k0 = ch * 16;
#pragma unroll
        for (int i = 0; i < 4; i++) {
            int e = tid + i * 256;
            int k = e & 15, m = e >> 4;
            float v = 0.f;
            if (k0 + k < K && m0 + m < M) v = A[(size_t)(m0 + m) * K + k0 + k];
            As[k * 68 + m] = v;
        }
#pragma unroll
        for (int i = 0; i < 8; i++) {
            int e = tid + i * 256;
            int h = e & 127, k = e >> 7;
            float v = 0.f;
            if (k0 + k < K) v = W[(size_t)(k0 + k) * HD + h];
            Bs[k * 136 + h] = v;
        }
        __syncthreads();
#pragma unroll
        for (int k = 0; k < 16; k++) {
            float4 a  = *(const float4*)&As[k * 68 + ty * 4];
            float4 b0 = *(const float4*)&Bs[k * 136 + tx * 4];
            float4 b1 = *(const float4*)&Bs[k * 136 + 64 + tx * 4];
            float av[4] = {a.x, a.y, a.z, a.w};
            float bv[8] = {b0.x, b0.y, b0.z, b0.w, b1.x, b1.y, b1.z, b1.w};
#pragma unroll
            for (int r = 0; r < 4; r++)
#pragma unroll
                for (int c = 0; c < 8; c++) acc[r][c] += av[r] * bv[c];
        }
        __syncthreads();
    }
#pragma unroll
    for (int r = 0; r < 4; r++) {
        int m = m0 + ty * 4 + r;
        if (m >= M) continue;
#pragma unroll
        for (int half = 0; half < 2; half++) {
#pragma unroll
            for (int c = 0; c < 4; c++) {
                int h = half * 64 + tx * 4 + c;
                float v = acc[r][half * 4 + c] + bias[h];
                out[(size_t)m * HD + h] = fmaxf(v, 0.f);
            }
        }
    }
}

// ---------------------------------------------------------------------------
__global__ void __launch_bounds__(256)
linear_softmax_kernel(const float* __restrict__ A, const float* __restrict__ W,
                      const float* __restrict__ bias, float* __restrict__ out, int M)
{
    __shared__ float Ws[HD * NL];
    __shared__ float bs[NL];
    int tid = threadIdx.x;
    for (int i = tid; i < HD * NL; i += 256) Ws[i] = W[i];
    if (tid < NL) bs[tid] = bias[tid];
    __syncthreads();

    int warp = tid >> 5, lane = tid & 31;
    int m = blockIdx.x * 8 + warp;
    if (m >= M) return;

    float acc[NL];
#pragma unroll
    for (int h = 0; h < NL; h++) acc[h] = 0.f;
    for (int k = lane; k < HD; k += 32) {
        float x = A[(size_t)m * HD + k];
#pragma unroll
        for (int h = 0; h < NL; h++) acc[h] += x * Ws[k * NL + h];
    }
#pragma unroll
    for (int h = 0; h < NL; h++)
#pragma unroll
        for (int off = 16; off > 0; off >>= 1)
            acc[h] += __shfl_down_sync(0xFFFFFFFFu, acc[h], off);

    if (lane == 0) {
        float v[NL], mx = -1e30f;
#pragma unroll
        for (int h = 0; h < NL; h++) { v[h] = acc[h] + bs[h]; mx = fmaxf(mx, v[h]); }
        float s = 0.f;
#pragma unroll
        for (int h = 0; h < NL; h++) { v[h] = expf(v[h] - mx); s += v[h]; }
        float inv = 1.0f / s;
#pragma unroll
        for (int h = 0; h < NL; h++) out[(size_t)m * NL + h] = v[h] * inv;
    }
}

// ---------------------------------------------------------------------------
__global__ void __launch_bounds__(256)
rownorm_kernel(const float* __restrict__ A, float* __restrict__ out, int M, int D)
{
    int warp = threadIdx.x >> 5, lane = threadIdx.x & 31;
    int m = blockIdx.x * 8 + warp;
    if (m >= M) return;
    float s = 0.f;
    for (int k = lane; k < D; k += 32) { float v = A[(size_t)m * D + k]; s += v * v; }
#pragma unroll
    for (int off = 16; off > 0; off >>= 1) s += __shfl_down_sync(0xFFFFFFFFu, s, off);
    if (lane == 0) out[m] = s;
}

// ---------------------------------------------------------------------------
// SIMT fp32 distance GEMM (layer 4, D=8) + tile min.
// ---------------------------------------------------------------------------
__global__ void __launch_bounds__(256)
dist_kernel(const float* __restrict__ Q, const float* __restrict__ T,
            const float* __restrict__ qn, const float* __restrict__ tn,
            float* __restrict__ out, float* __restrict__ gmin, int D, int Ncols)
{
    __shared__ __align__(16) float As[16 * 68];
    __shared__ __align__(16) float Bs[16 * 136];
    __shared__ unsigned sMinU[64];
    const int tx = threadIdx.x, ty = threadIdx.y;
    const int tid = ty * 16 + tx;
    const int n0 = blockIdx.x * 128;
    const int m0 = blockIdx.y * 64;

    if (tid < 64) sMinU[tid] = 0x7F800000u;

    float acc[4][8];
#pragma unroll
    for (int r = 0; r < 4; r++)
#pragma unroll
        for (int c = 0; c < 8; c++) acc[r][c] = 0.f;

    const int nChunks = (D + 15) / 16;
    for (int ch = 0; ch < nChunks; ch++) {
        const int k0 = ch * 16;
#pragma unroll
        for (int i = 0; i < 4; i++) {
            int e = tid + i * 256;
            int k = e & 15, m = e >> 4;
            float v = (k0 + k < D) ? Q[(size_t)(m0 + m) * D + k0 + k] : 0.f;
            As[k * 68 + m] = v;
        }
#pragma unroll
        for (int i = 0; i < 8; i++) {
            int e = tid + i * 256;
            int k = e & 15, n = e >> 4;
            int gn = n0 + n;
            float v = 0.f;
            if (k0 + k < D && gn < Ncols) v = T[(size_t)gn * D + k0 + k];
            Bs[k * 136 + n] = v;
        }
        __syncthreads();
#pragma unroll
        for (int k = 0; k < 16; k++) {
            float4 a  = *(const float4*)&As[k * 68 + ty * 4];
            float4 b0 = *(const float4*)&Bs[k * 136 + tx * 4];
            float4 b1 = *(const float4*)&Bs[k * 136 + 64 + tx * 4];
            float av[4] = {a.x, a.y, a.z, a.w};
            float bv[8] = {b0.x, b0.y, b0.z, b0.w, b1.x, b1.y, b1.z, b1.w};
#pragma unroll
            for (int r = 0; r < 4; r++)
#pragma unroll
                for (int c = 0; c < 8; c++) acc[r][c] += av[r] * bv[c];
        }
        __syncthreads();
    }
    const float FINF = __int_as_float(0x7F800000);
#pragma unroll
    for (int r = 0; r < 4; r++) {
        int m = m0 + ty * 4 + r;
        float qv = qn[m];
        float lm = FINF;
#pragma unroll
        for (int half = 0; half < 2; half++) {
#pragma unroll
            for (int c = 0; c < 4; c++) {
                int n = n0 + half * 64 + tx * 4 + c;
                if (n < Ncols) {
                    float d = fmaxf(qv + tn[n] - 2.f * acc[r][half * 4 + c], 0.f);
                    out[(size_t)m * Ncols + n] = d;
                    lm = fminf(lm, d);
                }
            }
        }
        if (lm < FINF) atomicMin(&sMinU[ty * 4 + r], __float_as_uint(lm));
    }
    __syncthreads();
    if (tid < 64)
        gmin[(size_t)(m0 + tid) * NTILES + blockIdx.x] = __uint_as_float(sMinU[tid]);
}

// ---------------------------------------------------------------------------
// Exact top-K select: tile-min threshold + single-scan compaction.
// ---------------------------------------------------------------------------
#define SEL_THREADS 512
#define SEL_CAP 2048
#define OFF_CAND  16384
#define OFF_SEL   (OFF_CAND + SEL_CAP * 8)
#define OFF_TIES  (OFF_SEL + 1024)
#define OFF_TLAB  (OFF_TIES + 1024)
#define OFF_MINS  (OFF_TLAB + 512)
#define SEL_SMEM  (OFF_MINS + 392 * 4)

__device__ __forceinline__ void find_kth(const unsigned* hist, int NB, unsigned kth,
                                         int tid, unsigned* s_bin, unsigned* s_kthr)
{
    if (tid < 32) {
        unsigned running = 0;
        for (int base = 0; base < NB; base += 32) {
            unsigned v = hist[base + tid];
            unsigned sc = v;
#pragma unroll
            for (int off = 1; off < 32; off <<= 1) {
                unsigned t = __shfl_up_sync(0xFFFFFFFFu, sc, off);
                if (tid >= off) sc += t;
            }
            unsigned tot = __shfl_sync(0xFFFFFFFFu, sc, 31);
            if (running + tot >= kth) {
                unsigned mask = __ballot_sync(0xFFFFFFFFu, running + sc >= kth);
                int l = __ffs(mask) - 1;
                if (tid == l) { *s_bin = (unsigned)(base + l); *s_kthr = kth - running - (sc - v); }
                break;
            }
            running += tot;
        }
    }
}

__global__ void __launch_bounds__(SEL_THREADS)
select_kernel(const float* __restrict__ d2mat, const float* __restrict__ gmin,
              const int* __restrict__ labels, float* __restrict__ total, int init)
{
    extern __shared__ __align__(16) char sms[];
    unsigned* hist = (unsigned*)sms;
    u64* cand  = (u64*)(sms + OFF_CAND);
    u64* sel   = (u64*)(sms + OFF_SEL);
    u64* ties  = (u64*)(sms + OFF_TIES);
    int* tlab  = (int*)(sms + OFF_TLAB);
    float* mins = (float*)(sms + OFF_MINS);

    __shared__ unsigned s_M75, s_bin, s_kthr, s_candcnt, s_selcnt, s_tiecnt;
    __shared__ float s_w[80];
    __shared__ int s_lab[80];

    const int b = blockIdx.x, tid = threadIdx.x, lane = tid & 31;
    const uint4* usrc = (const uint4*)(d2mat + (size_t)b * NT);
    const int NH = NT / 4;

    for (int i = tid; i < NTILES; i += SEL_THREADS)
        mins[i] = gmin[(size_t)b * NTILES + i];
    if (tid == 0) { s_candcnt = 0; s_selcnt = 0; s_tiecnt = 0; }
    __syncthreads();
    if (tid < NTILES) {
        unsigned key = __float_as_uint(mins[tid]);
        int c = 0;
        for (int j = 0; j < NTILES; j++) {
            unsigned kj = __float_as_uint(mins[j]);
            c += (kj < key) || (kj == key && j < tid);
        }
        if (c == KNN - 1) s_M75 = key;
    }
    __syncthreads();
    const unsigned Mkey = s_M75;

    // ---- single full scan (2-way ILP, uint compares), compact key <= Mkey ----
    for (int base = 0; base < NH; base += 2 * SEL_THREADS) {
        int i0 = base + tid;
        int i1 = base + SEL_THREADS + tid;
        uint4 a = (i0 < NH) ? usrc[i0] : make_uint4(~0u, ~0u, ~0u, ~0u);
        uint4 c4 = (i1 < NH) ? usrc[i1] : make_uint4(~0u, ~0u, ~0u, ~0u);
        unsigned k0[4] = {a.x, a.y, a.z, a.w};
        unsigned k1[4] = {c4.x, c4.y, c4.z, c4.w};
#pragma unroll
        for (int j = 0; j < 4; j++) {
            if (k0[j] <= Mkey) {
                unsigned s = atomicAdd(&s_candcnt, 1u);
                if (s < SEL_CAP) cand[s] = ((u64)k0[j] << 32) | (unsigned)(i0 * 4 + j);
            }
            if (k1[j] <= Mkey) {
                unsigned s = atomicAdd(&s_candcnt, 1u);
                if (s < SEL_CAP) cand[s] = ((u64)k1[j] << 32) | (unsigned)(i1 * 4 + j);
            }
        }
    }
    __syncthreads();

    unsigned Tkey;
    const unsigned candTotal = s_candcnt;

    if (candTotal <= SEL_CAP) {
        const int cc = (int)candTotal;
        for (int i = tid; i < 4096; i += SEL_THREADS) hist[i] = 0;
        __syncthreads();
        for (int i = tid; i < cc; i += SEL_THREADS)
            atomicAdd(&hist[(unsigned)(cand[i] >> 52)], 1u);
        __syncthreads();
        find_kth(hist, 4096, KNN, tid, &s_bin, &s_kthr);
        __syncthreads();
        const unsigned pfx = s_bin;
        const unsigned k1v = s_kthr;
        for (int i = tid; i < 4096; i += SEL_THREADS) hist[i] = 0;
        __syncthreads();
        for (int i = tid; i < cc; i += SEL_THREADS) {
            unsigned key = (unsigned)(cand[i] >> 32);
            if ((key >> 20) == pfx) atomicAdd(&hist[(key >> 8) & 0xFFFu], 1u);
        }
        __syncthreads();
        find_kth(hist, 4096, k1v, tid, &s_bin, &s_kthr);
        __syncthreads();
        const unsigned pfx20 = (pfx << 12) | s_bin;
        const unsigned k2v = s_kthr;
        for (int i = tid; i < 256; i += SEL_THREADS) hist[i] = 0;
        __syncthreads();
        for (int i = tid; i < cc; i += SEL_THREADS) {
            unsigned key = (unsigned)(cand[i] >> 32);
            if ((key >> 8) == pfx20) atomicAdd(&hist[key & 0xFFu], 1u);
        }
        __syncthreads();
        find_kth(hist, 256, k2v, tid, &s_bin, &s_kthr);
        __syncthreads();
        Tkey = (pfx20 << 8) | s_bin;
        for (int i = tid; i < cc; i += SEL_THREADS) {
            u64 cv = cand[i];
            unsigned key = (unsigned)(cv >> 32);
            if (key < Tkey) {
                unsigned s = atomicAdd(&s_selcnt, 1u);
                if (s < 128) sel[s] = cv;
            } else if (key == Tkey) {
                unsigned s = atomicAdd(&s_tiecnt, 1u);
                if (s < 128) ties[s] = cv;
            }
        }
        __syncthreads();
    } else {
        // fallback: full gmem radix passes (degenerate distributions)
        const float4* src = (const float4*)(d2mat + (size_t)b * NT);
        const int NIT = (NT / 4 + SEL_THREADS - 1) / SEL_THREADS;
        for (int i = tid; i < 4096; i += SEL_THREADS) hist[i] = 0;
        __syncthreads();
        for (int it = 0; it < NIT; it++) {
            int i = it * SEL_THREADS + tid;
            bool valid = (i < NH);
            float4 v = valid ? src[i] : make_float4(0.f, 0.f, 0.f, 0.f);
            float e[4] = {v.x, v.y, v.z, v.w};
#pragma unroll
            for (int j = 0; j < 4; j++) {
                unsigned bin = valid ? (__float_as_uint(e[j]) >> 20) : 0xFFFFFFFFu;
                unsigned grp = __match_any_sync(0xFFFFFFFFu, bin);
                if (bin != 0xFFFFFFFFu && lane == __ffs(grp) - 1)
                    atomicAdd(&hist[bin], (unsigned)__popc(grp));
            }
        }
        __syncthreads();
        find_kth(hist, 4096, KNN, tid, &s_bin, &s_kthr);
        __syncthreads();
        const unsigned pfx = s_bin;
        const unsigned k1v = s_kthr;

        for (int i = tid; i < 4096; i += SEL_THREADS) hist[i] = 0;
        __syncthreads();
        for (int it = 0; it < NIT; it++) {
            int i = it * SEL_THREADS + tid;
            bool valid = (i < NH);
            float4 v = valid ? src[i] : make_float4(0.f, 0.f, 0.f, 0.f);
            float e[4] = {v.x, v.y, v.z, v.w};
#pragma unroll
            for (int j = 0; j < 4; j++) {
                unsigned key = __float_as_uint(e[j]);
                unsigned bin = (valid && (key >> 20) == pfx) ? ((key >> 8) & 0xFFFu)
                                                             : 0xFFFFFFFFu;
                unsigned grp = __match_any_sync(0xFFFFFFFFu, bin);
                if (bin != 0xFFFFFFFFu && lane == __ffs(grp) - 1)
                    atomicAdd(&hist[bin], (unsigned)__popc(grp));
            }
        }
        __syncthreads();
        find_kth(hist, 4096, k1v, tid, &s_bin, &s_kthr);
        __syncthreads();
        const unsigned pfx20 = (pfx << 12) | s_bin;
        const unsigned k2v = s_kthr;

        for (int i = tid; i < 256; i += SEL_THREADS) hist[i] = 0;
        __syncthreads();
        for (int it = 0; it < NIT; it++) {
            int i = it * SEL_THREADS + tid;
            bool valid = (i < NH);
            float4 v = valid ? src[i] : make_float4(0.f, 0.f, 0.f, 0.f);
            float e[4] = {v.x, v.y, v.z, v.w};
#pragma unroll
            for (int j = 0; j < 4; j++) {
                unsigned key = __float_as_uint(e[j]);
                unsigned bin = (valid && (key >> 8) == pfx20) ? (key & 0xFFu)
                                                              : 0xFFFFFFFFu;
                unsigned grp = __match_any_sync(0xFFFFFFFFu, bin);
                if (bin != 0xFFFFFFFFu && lane == __ffs(grp) - 1)
                    atomicAdd(&hist[bin], (unsigned)__popc(grp));
            }
        }
        __syncthreads();
        find_kth(hist, 256, k2v, tid, &s_bin, &s_kthr);
        __syncthreads();
        Tkey = (pfx20 << 8) | s_bin;

        for (int it = 0; it < NIT; it++) {
            int i = it * SEL_THREADS + tid;
            if (i < NH) {
                float4 v = src[i];
                float e[4] = {v.x, v.y, v.z, v.w};
#pragma unroll
                for (int j = 0; j < 4; j++) {
                    unsigned key = __float_as_uint(e[j]);
                    if (key < Tkey) {
                        unsigned s = atomicAdd(&s_selcnt, 1u);
                        if (s < 128) sel[s] = ((u64)key << 32) | (unsigned)(i * 4 + j);
                    } else if (key == Tkey) {
                        unsigned s = atomicAdd(&s_tiecnt, 1u);
                        if (s < 128) ties[s] = ((u64)key << 32) | (unsigned)(i * 4 + j);
                    }
                }
            }
        }
        __syncthreads();
    }

    const int ns = min((int)s_selcnt, 128);
    const int ne = min((int)s_tiecnt, 128);

    if (tid < ns) {
        u64 mine = sel[tid];
        unsigned my_idx = (unsigned)(mine & 0xFFFFFFFFu);
        int rank = 0;
        for (int j = 0; j < ns; j++) rank += ((unsigned)(sel[j] & 0xFFFFFFFFu) < my_idx);
        float d2 = __uint_as_float((unsigned)(mine >> 32));
        s_w[rank] = (d2 > 0.f) ? __fdiv_rn(1.0f, __fsqrt_rn(d2)) : 0.f;
        s_lab[rank] = labels[my_idx];
    }
    if (tid >= 128 && tid - 128 < ne) {
        int t = tid - 128;
        unsigned my_idx = (unsigned)(ties[t] & 0xFFFFFFFFu);
        int rank = 0;
        for (int j = 0; j < ne; j++) rank += ((unsigned)(ties[j] & 0xFFFFFFFFu) < my_idx);
        tlab[rank] = labels[my_idx];
    }
    __syncthreads();

    if (tid == 0) {
        float cls[NL];
#pragma unroll
        for (int l = 0; l < NL; l++) cls[l] = 0.f;
        float stot = 0.f;
        for (int j = 0; j < ns; j++) { stot += s_w[j]; cls[s_lab[j]] += s_w[j]; }
        int need = KNN - ns;
        float d2T = __uint_as_float(Tkey);
        float wT = (d2T > 0.f) ? __fdiv_rn(1.0f, __fsqrt_rn(d2T)) : 0.f;
        int m = (need < ne) ? need : ne;
        for (int j = 0; j < m; j++) { stot += wT; cls[tlab[j]] += wT; }
#pragma unroll
        for (int l = 0; l < NL; l++) {
            float val = stot - cls[l];
            size_t o = (size_t)b * NL + l;
            if (init) total[o] = val; else total[o] += val;
        }
    }
}

// ---------------------------------------------------------------------------
__global__ void __launch_bounds__(256)
pvalue_kernel(const float* __restrict__ total, const float* __restrict__ cali,
              float* __restrict__ out)
{
    const int b = blockIdx.x, tid = threadIdx.x;
    float t[NL];
#pragma unroll
    for (int l = 0; l < NL; l++) t[l] = total[(size_t)b * NL + l];
    int cnt[NL];
#pragma unroll
    for (int l = 0; l < NL; l++) cnt[l] = 0;
    for (int i = tid; i < NC; i += 256) {
        float c = cali[i];
#pragma unroll
        for (int l = 0; l < NL; l++) cnt[l] += (c >= t[l]) ? 1 : 0;
    }
    __shared__ int sc[NL];
    if (tid < NL) sc[tid] = 0;
    __syncthreads();
#pragma unroll
    for (int l = 0; l < NL; l++) atomicAdd(&sc[l], cnt[l]);
    __syncthreads();
    if (tid < NL) out[(size_t)b * NL + tid] = (float)sc[tid] * (1.0f / NC);
}

// ---------------------------------------------------------------------------
extern "C" void kernel_launch(void* const* d_in, const int* in_sizes, int n_in,
                              void* d_out, int out_size)
{
    const float* x        = (const float*)d_in[0];
    const float* train_x  = (const float*)d_in[1];
    const int*   lab      = (const int*)  d_in[2];
    const float* cali     = (const float*)d_in[3];
    const float* W1 = (const float*)d_in[4];  const float* b1 = (const float*)d_in[5];
    const float* W2 = (const float*)d_in[6];  const float* b2 = (const float*)d_in[7];
    const float* W3 = (const float*)d_in[8];  const float* b3 = (const float*)d_in[9];
    const float* W4 = (const float*)d_in[10]; const float* b4 = (const float*)d_in[11];
    float* out = (float*)d_out;

    float *h1p, *h2p, *h3p, *q4p, *t3p, *t4p, *d2p, *qnp, *tnp, *totp, *minp;
    __nv_bfloat16 *qhip, *qlop, *thip, *tlop, *thi2p, *tlo2p;
    __nv_bfloat16 *w1th, *w1tl, *w2th, *w2tl, *w3th, *w3tl;
    cudaGetSymbolAddress((void**)&h1p, g_h1);
    cudaGetSymbolAddress((void**)&h2p, g_h2);
    cudaGetSymbolAddress((void**)&h3p, g_h3);
    cudaGetSymbolAddress((void**)&q4p, g_q4);
    cudaGetSymbolAddress((void**)&t3p, g_t3);
    cudaGetSymbolAddress((void**)&t4p, g_t4);
    cudaGetSymbolAddress((void**)&d2p, g_d2);
    cudaGetSymbolAddress((void**)&minp, g_min);
    cudaGetSymbolAddress((void**)&qnp, g_qn);
    cudaGetSymbolAddress((void**)&tnp, g_tn);
    cudaGetSymbolAddress((void**)&totp, g_tot);
    cudaGetSymbolAddress((void**)&qhip, g_qhi);
    cudaGetSymbolAddress((void**)&qlop, g_qlo);
    cudaGetSymbolAddress((void**)&thip, g_thi);
    cudaGetSymbolAddress((void**)&tlop, g_tlo);
    cudaGetSymbolAddress((void**)&thi2p, g_thi2);
    cudaGetSymbolAddress((void**)&tlo2p, g_tlo2);
    cudaGetSymbolAddress((void**)&w1th, g_w1th);
    cudaGetSymbolAddress((void**)&w1tl, g_w1tl);
    cudaGetSymbolAddress((void**)&w2th, g_w2th);
    cudaGetSymbolAddress((void**)&w2tl, g_w2tl);
    cudaGetSymbolAddress((void**)&w3th, g_w3th);
    cudaGetSymbolAddress((void**)&w3tl, g_w3tl);

    cudaFuncSetAttribute(select_kernel,
                         cudaFuncAttributeMaxDynamicSharedMemorySize, SEL_SMEM);

    dim3 tb(16, 16);
    const int D0 = 83;
    const dim3 mgrid(NTILES, BQ / 128);

    // 1-3: conv q, conv t (bank0), weight transposes
    conv_norm_kernel<<<BQ / 8, 256>>>(x, qhip, qlop, qnp, BQ, D0);
    conv_norm_kernel<<<NTP / 8, 256>>>(train_x, thip, tlop, tnp, NT, D0);
    wt_convert_kernel<<<(3 * 128 * 128 + 255) / 256, 256>>>(W1, W2, W3);

    // 4-5: layer 0 dist (PROFILED launch #4) + select
    mma_dist_kernel<<<mgrid, 256>>>(qhip, qlop, thip, tlop, qnp, tnp, d2p, minp, 96);
    select_kernel<<<BQ, SEL_THREADS, SEL_SMEM>>>(d2p, minp, lab, totp, 1);

    // query-side MLP (tiny SIMT)
    linear_relu_kernel<<<BQ / 64, tb>>>(x,   W1, b1, h1p, BQ, D0);
    linear_relu_kernel<<<BQ / 64, tb>>>(h1p, W2, b2, h2p, BQ, HD);
    linear_relu_kernel<<<BQ / 64, tb>>>(h2p, W3, b3, h3p, BQ, HD);
    linear_softmax_kernel<<<(BQ + 7) / 8, 256>>>(h3p, W4, b4, q4p, BQ);

    // layer 1: train MLP on tensor cores (bank0 -> bank1) + dist + select
    mma_linear_kernel<<<NTILES, 256>>>(thip, tlop, w1th, w1tl, b1,
                                       thi2p, tlo2p, tnp, (float*)0, 96);
    conv_norm_kernel<<<BQ / 8, 256>>>(h1p, qhip, qlop, qnp, BQ, HD);
    mma_dist_kernel<<<mgrid, 256>>>(qhip, qlop, thi2p, tlo2p, qnp, tnp, d2p, minp, 128);
    select_kernel<<<BQ, SEL_THREADS, SEL_SMEM>>>(d2p, minp, lab, totp, 0);

    // layer 2: bank1 -> bank0
    mma_linear_kernel<<<NTILES, 256>>>(thi2p, tlo2p, w2th, w2tl, b2,
                                       thip, tlop, tnp, (float*)0, 128);
    conv_norm_kernel<<<BQ / 8, 256>>>(h2p, qhip, qlop, qnp, BQ, HD);
    mma_dist_kernel<<<mgrid, 256>>>(qhip, qlop, thip, tlop, qnp, tnp, d2p, minp, 128);
    select_kernel<<<BQ, SEL_THREADS, SEL_SMEM>>>(d2p, minp, lab, totp, 0);

    // layer 3: bank0 -> bank1 (+ fp32 t3 for softmax)
    mma_linear_kernel<<<NTILES, 256>>>(thip, tlop, w3th, w3tl, b3,
                                       thi2p, tlo2p, tnp, t3p, 128);
    conv_norm_kernel<<<BQ / 8, 256>>>(h3p, qhip, qlop, qnp, BQ, HD);
    mma_dist_kernel<<<mgrid, 256>>>(qhip, qlop, thi2p, tlo2p, qnp, tnp, d2p, minp, 128);
    select_kernel<<<BQ, SEL_THREADS, SEL_SMEM>>>(d2p, minp, lab, totp, 0);

    // layer 4 (softmax features, D=8): exact fp32 path
    linear_softmax_kernel<<<(NT + 7) / 8, 256>>>(t3p, W4, b4, t4p, NT);
    rownorm_kernel<<<(BQ + 7) / 8, 256>>>(q4p, qnp, BQ, NL);
    rownorm_kernel<<<(NT + 7) / 8, 256>>>(t4p, tnp, NT, NL);
    dist_kernel<<<dim3(NTILES, BQ / 64), tb>>>(q4p, t4p, qnp, tnp, d2p, minp, NL, NT);
    select_kernel<<<BQ, SEL_THREADS, SEL_SMEM>>>(d2p, minp, lab, totp, 0);

    pvalue_kernel<<<BQ, 256>>>(totp, cali, out);
}

// round 8
// speedup vs baseline: 3.6620x; 1.0450x over previous
#include <cuda_runtime.h>
#include <cuda_bf16.h>
#include <math.h>
#include <stdint.h>

#define BQ   1024
#define NT   50000
#define NTP  50048
#define NL   8
#define KNN  75
#define HD   128
#define NC   10000
#define NTILES 391          // NTP/128

typedef unsigned long long u64;

// ---------------- device scratch ----------------
__device__ float g_h1[BQ * HD];
__device__ float g_h2[BQ * HD];
__device__ float g_h3[BQ * HD];
__device__ float g_q4[BQ * NL];
__device__ float g_t3[(size_t)NT * HD];
__device__ float g_t4[(size_t)NT * NL];
__device__ float g_d2[(size_t)BQ * NT];
__device__ float g_min[(size_t)BQ * NTILES];
__device__ float g_qn[BQ];
__device__ float g_tn[NT];
__device__ float g_tot[BQ * NL];
__device__ __nv_bfloat16 g_qhi[(size_t)BQ * 128];
__device__ __nv_bfloat16 g_qlo[(size_t)BQ * 128];
__device__ __nv_bfloat16 g_thi[(size_t)NTP * 128];    // bank A
__device__ __nv_bfloat16 g_tlo[(size_t)NTP * 128];
__device__ __nv_bfloat16 g_thi2[(size_t)NTP * 128];   // bank B
__device__ __nv_bfloat16 g_tlo2[(size_t)NTP * 128];
__device__ __nv_bfloat16 g_w1th[128 * 128], g_w1tl[128 * 128];
__device__ __nv_bfloat16 g_w2th[128 * 128], g_w2tl[128 * 128];
__device__ __nv_bfloat16 g_w3th[128 * 128], g_w3tl[128 * 128];

// ---------------------------------------------------------------------------
__device__ __forceinline__ void mma_bf16(float* d, const uint32_t* a, const uint32_t* b)
{
    asm volatile(
        "mma.sync.aligned.m16n8k16.row.col.f32.bf16.bf16.f32 "
        "{%0,%1,%2,%3}, {%4,%5,%6,%7}, {%8,%9}, {%0,%1,%2,%3};"
        : "+f"(d[0]), "+f"(d[1]), "+f"(d[2]), "+f"(d[3])
        : "r"(a[0]), "r"(a[1]), "r"(a[2]), "r"(a[3]), "r"(b[0]), "r"(b[1]));
}

// smem tile slice: 128 rows x 16 bf16 cols, row stride 24 (48B) -> conflict-free
#define SLICE_ELEMS (128 * 24)

// one 16-wide k-chunk of a [*,128] bank -> smem slice, via cp.async (one tile)
__device__ __forceinline__ void slice_load_async(
    const __nv_bfloat16* __restrict__ Gp, __nv_bfloat16* Ss,
    int row0, int k0, int lr, int lh)
{
    uint32_t sa = (uint32_t)__cvta_generic_to_shared(Ss + lr * 24 + lh * 8);
    const void* ga = Gp + (size_t)(row0 + lr) * 128 + k0 + lh * 8;
    asm volatile("cp.async.cg.shared.global [%0], [%1], 16;\n" :: "r"(sa), "l"(ga));
}

// ---------------------------------------------------------------------------
// Fused split-convert + row norm (one warp per row).
// ---------------------------------------------------------------------------
__global__ void __launch_bounds__(256)
conv_norm_kernel(const float* __restrict__ A, __nv_bfloat16* __restrict__ hi,
                 __nv_bfloat16* __restrict__ lo, float* __restrict__ nrm,
                 int Mreal, int D)
{
    int warp = threadIdx.x >> 5, lane = threadIdx.x & 31;
    int row = blockIdx.x * 8 + warp;
    int base = lane * 4;

    float ss = 0.f;
    __nv_bfloat16 hb[4], lb[4];
#pragma unroll
    for (int j = 0; j < 4; j++) {
        int col = base + j;
        float v = (row < Mreal && col < D) ? A[(size_t)row * D + col] : 0.f;
        ss += v * v;
        hb[j] = __float2bfloat16_rn(v);
        lb[j] = __float2bfloat16_rn(v - __bfloat162float(hb[j]));
    }
    __nv_bfloat162 h01, h23, l01, l23;
    h01.x = hb[0]; h01.y = hb[1]; h23.x = hb[2]; h23.y = hb[3];
    l01.x = lb[0]; l01.y = lb[1]; l23.x = lb[2]; l23.y = lb[3];
    *(__nv_bfloat162*)&hi[(size_t)row * 128 + base]     = h01;
    *(__nv_bfloat162*)&hi[(size_t)row * 128 + base + 2] = h23;
    *(__nv_bfloat162*)&lo[(size_t)row * 128 + base]     = l01;
    *(__nv_bfloat162*)&lo[(size_t)row * 128 + base + 2] = l23;

#pragma unroll
    for (int off = 16; off > 0; off >>= 1) ss += __shfl_down_sync(0xFFFFFFFFu, ss, off);
    if (lane == 0 && row < Mreal) nrm[row] = ss;
}

// ---------------------------------------------------------------------------
__global__ void __launch_bounds__(256)
wt_convert_kernel(const float* __restrict__ W1, const float* __restrict__ W2,
                  const float* __restrict__ W3)
{
    int idx = blockIdx.x * 256 + threadIdx.x;
    if (idx >= 3 * 128 * 128) return;
    int which = idx >> 14;
    int e = idx & 16383;
    int n = e & 127, k = e >> 7;
    const float* W = (which == 0) ? W1 : (which == 1) ? W2 : W3;
    int K = (which == 0) ? 83 : 128;
    float v = (k < K) ? W[(size_t)k * 128 + n] : 0.f;
    __nv_bfloat16 h = __float2bfloat16_rn(v);
    __nv_bfloat16 l = __float2bfloat16_rn(v - __bfloat162float(h));
    __nv_bfloat16* dh = (which == 0) ? g_w1th : (which == 1) ? g_w2th : g_w3th;
    __nv_bfloat16* dl = (which == 0) ? g_w1tl : (which == 1) ? g_w2tl : g_w3tl;
    dh[e] = h;
    dl[e] = l;
}

// ---------------------------------------------------------------------------
// Shared bf16x3 GEMM mainloop macro body (per-chunk all-combo):
//   per 16-wide k-chunk, load 4 slices (Ahi,Alo,Bhi,Blo) once, then
//   acc += Ahi*Bhi + Alo*Bhi + Ahi*Blo   (48 MMAs / barrier pair)
// ---------------------------------------------------------------------------
__device__ __forceinline__ void gemm3_mainloop(
    const __nv_bfloat16* Ahi, const __nv_bfloat16* Alo,
    const __nv_bfloat16* Bhi, const __nv_bfloat16* Blo,
    __nv_bfloat16* smem, int m0, int n0, int nCh,
    int wm, int wn, int fr, int fc, int lr, int lh,
    float acc[2][8][4])
{
    __nv_bfloat16* AhiS[2] = {smem,                   smem + 4 * SLICE_ELEMS};
    __nv_bfloat16* AloS[2] = {smem + 1 * SLICE_ELEMS, smem + 5 * SLICE_ELEMS};
    __nv_bfloat16* BhiS[2] = {smem + 2 * SLICE_ELEMS, smem + 6 * SLICE_ELEMS};
    __nv_bfloat16* BloS[2] = {smem + 3 * SLICE_ELEMS, smem + 7 * SLICE_ELEMS};

    // prefetch chunk 0
    slice_load_async(Ahi, AhiS[0], m0, 0, lr, lh);
    slice_load_async(Alo, AloS[0], m0, 0, lr, lh);
    slice_load_async(Bhi, BhiS[0], n0, 0, lr, lh);
    slice_load_async(Blo, BloS[0], n0, 0, lr, lh);
    asm volatile("cp.async.commit_group;\n" ::: "memory");

    for (int c = 0; c < nCh; c++) {
        int buf = c & 1;
        if (c + 1 < nCh) {
            int k0 = (c + 1) * 16;
            slice_load_async(Ahi, AhiS[buf ^ 1], m0, k0, lr, lh);
            slice_load_async(Alo, AloS[buf ^ 1], m0, k0, lr, lh);
            slice_load_async(Bhi, BhiS[buf ^ 1], n0, k0, lr, lh);
            slice_load_async(Blo, BloS[buf ^ 1], n0, k0, lr, lh);
            asm volatile("cp.async.commit_group;\n" ::: "memory");
            asm volatile("cp.async.wait_group 1;" ::: "memory");
        } else {
            asm volatile("cp.async.wait_group 0;" ::: "memory");
        }
        __syncthreads();

        const __nv_bfloat16* Ah = AhiS[buf];
        const __nv_bfloat16* Al = AloS[buf];
        const __nv_bfloat16* Bh = BhiS[buf];
        const __nv_bfloat16* Bl = BloS[buf];

        uint32_t ah[2][4], al[2][4];
#pragma unroll
        for (int mt = 0; mt < 2; mt++) {
            int bm = wm + mt * 16;
            ah[mt][0] = *(const uint32_t*)&Ah[(bm + fr) * 24 + fc];
            ah[mt][1] = *(const uint32_t*)&Ah[(bm + fr + 8) * 24 + fc];
            ah[mt][2] = *(const uint32_t*)&Ah[(bm + fr) * 24 + fc + 8];
            ah[mt][3] = *(const uint32_t*)&Ah[(bm + fr + 8) * 24 + fc + 8];
            al[mt][0] = *(const uint32_t*)&Al[(bm + fr) * 24 + fc];
            al[mt][1] = *(const uint32_t*)&Al[(bm + fr + 8) * 24 + fc];
            al[mt][2] = *(const uint32_t*)&Al[(bm + fr) * 24 + fc + 8];
            al[mt][3] = *(const uint32_t*)&Al[(bm + fr + 8) * 24 + fc + 8];
        }
#pragma unroll
        for (int nt = 0; nt < 8; nt++) {
            int nb = wn + nt * 8;
            uint32_t bh[2], bl[2];
            bh[0] = *(const uint32_t*)&Bh[(nb + fr) * 24 + fc];
            bh[1] = *(const uint32_t*)&Bh[(nb + fr) * 24 + fc + 8];
            bl[0] = *(const uint32_t*)&Bl[(nb + fr) * 24 + fc];
            bl[1] = *(const uint32_t*)&Bl[(nb + fr) * 24 + fc + 8];
            mma_bf16(acc[0][nt], ah[0], bh);
            mma_bf16(acc[1][nt], ah[1], bh);
            mma_bf16(acc[0][nt], al[0], bh);
            mma_bf16(acc[1][nt], al[1], bh);
            mma_bf16(acc[0][nt], ah[0], bl);
            mma_bf16(acc[1][nt], ah[1], bl);
        }
        __syncthreads();
    }
}

// ---------------------------------------------------------------------------
// Tensor-core bf16x3 distance GEMM + per-(query,tile) min output.
// ---------------------------------------------------------------------------
__global__ void __launch_bounds__(256)
mma_dist_kernel(const __nv_bfloat16* __restrict__ Qhi, const __nv_bfloat16* __restrict__ Qlo,
                const __nv_bfloat16* __restrict__ Thi, const __nv_bfloat16* __restrict__ Tlo,
                const float* __restrict__ qn, const float* __restrict__ tn,
                float* __restrict__ out, float* __restrict__ gmin, int nCh)
{
    __shared__ __align__(16) __nv_bfloat16 smem[8 * SLICE_ELEMS];
    __shared__ float sMin[128][2];
    const int tid = threadIdx.x;
    const int wid = tid >> 5, lane = tid & 31;
    const int n0 = blockIdx.x * 128;
    const int m0 = blockIdx.y * 128;
    const int wm = (wid & 3) * 32;
    const int wn = (wid >> 2) * 64;
    const int lr = tid >> 1, lh = tid & 1;
    const int fr = lane >> 2, fc = (lane & 3) * 2;

    float acc[2][8][4];
#pragma unroll
    for (int mt = 0; mt < 2; mt++)
#pragma unroll
        for (int nt = 0; nt < 8; nt++)
#pragma unroll
            for (int j = 0; j < 4; j++) acc[mt][nt][j] = 0.f;

    gemm3_mainloop(Qhi, Qlo, Thi, Tlo, smem, m0, n0, nCh,
                   wm, wn, fr, fc, lr, lh, acc);

    const float FINF = __int_as_float(0x7F800000);
    float rmin[2][2] = {{FINF, FINF}, {FINF, FINF}};
#pragma unroll
    for (int mt = 0; mt < 2; mt++) {
        int mrow = m0 + wm + mt * 16 + fr;
        float q0 = qn[mrow], q1 = qn[mrow + 8];
#pragma unroll
        for (int nt = 0; nt < 8; nt++) {
            int n = n0 + wn + nt * 8 + fc;
            if (n < NT) {
                float t0 = tn[n], t1 = tn[n + 1];
                float2 o;
                o.x = fmaxf(q0 + t0 - 2.f * acc[mt][nt][0], 0.f);
                o.y = fmaxf(q0 + t1 - 2.f * acc[mt][nt][1], 0.f);
                *(float2*)&out[(size_t)mrow * NT + n] = o;
                rmin[mt][0] = fminf(rmin[mt][0], fminf(o.x, o.y));
                o.x = fmaxf(q1 + t0 - 2.f * acc[mt][nt][2], 0.f);
                o.y = fmaxf(q1 + t1 - 2.f * acc[mt][nt][3], 0.f);
                *(float2*)&out[(size_t)(mrow + 8) * NT + n] = o;
                rmin[mt][1] = fminf(rmin[mt][1], fminf(o.x, o.y));
            }
        }
    }
#pragma unroll
    for (int mt = 0; mt < 2; mt++)
#pragma unroll
        for (int rr = 0; rr < 2; rr++) {
            float m = rmin[mt][rr];
            m = fminf(m, __shfl_xor_sync(0xFFFFFFFFu, m, 1));
            m = fminf(m, __shfl_xor_sync(0xFFFFFFFFu, m, 2));
            if ((lane & 3) == 0)
                sMin[wm + mt * 16 + rr * 8 + fr][wn >> 6] = m;
        }
    __syncthreads();
    if (tid < 128)
        gmin[(size_t)(m0 + tid) * NTILES + blockIdx.x] =
            fminf(sMin[tid][0], sMin[tid][1]);
}

// ---------------------------------------------------------------------------
// Tensor-core bf16x3 linear+ReLU (train side).
// ---------------------------------------------------------------------------
__global__ void __launch_bounds__(256)
mma_linear_kernel(const __nv_bfloat16* __restrict__ Ahi, const __nv_bfloat16* __restrict__ Alo,
                  const __nv_bfloat16* __restrict__ Wth, const __nv_bfloat16* __restrict__ Wtl,
                  const float* __restrict__ bias,
                  __nv_bfloat16* __restrict__ Ohi, __nv_bfloat16* __restrict__ Olo,
                  float* __restrict__ nrm, float* __restrict__ Ofp, int nCh)
{
    __shared__ __align__(16) __nv_bfloat16 smem[8 * SLICE_ELEMS];
    __shared__ float snorm[128];
    __shared__ float sbias[128];
    const int tid = threadIdx.x;
    const int wid = tid >> 5, lane = tid & 31;
    const int m0 = blockIdx.x * 128;
    const int wm = (wid & 3) * 32;
    const int wn = (wid >> 2) * 64;
    const int lr = tid >> 1, lh = tid & 1;
    const int fr = lane >> 2, fc = (lane & 3) * 2;

    if (tid < 128) { sbias[tid] = bias[tid]; snorm[tid] = 0.f; }

    float acc[2][8][4];
#pragma unroll
    for (int mt = 0; mt < 2; mt++)
#pragma unroll
        for (int nt = 0; nt < 8; nt++)
#pragma unroll
            for (int j = 0; j < 4; j++) acc[mt][nt][j] = 0.f;

    gemm3_mainloop(Ahi, Alo, Wth, Wtl, smem, m0, 0, nCh,
                   wm, wn, fr, fc, lr, lh, acc);

#pragma unroll
    for (int mt = 0; mt < 2; mt++) {
        int r0 = wm + mt * 16 + fr;
        int r1 = r0 + 8;
        size_t g0 = (size_t)(m0 + r0) * 128;
        size_t g1 = (size_t)(m0 + r1) * 128;
        float ns0 = 0.f, ns1 = 0.f;
#pragma unroll
        for (int nt = 0; nt < 8; nt++) {
            int n = wn + nt * 8 + fc;
            float b0 = sbias[n], b1 = sbias[n + 1];
            float v00 = fmaxf(acc[mt][nt][0] + b0, 0.f);
            float v01 = fmaxf(acc[mt][nt][1] + b1, 0.f);
            float v10 = fmaxf(acc[mt][nt][2] + b0, 0.f);
            float v11 = fmaxf(acc[mt][nt][3] + b1, 0.f);
            ns0 += v00 * v00 + v01 * v01;
            ns1 += v10 * v10 + v11 * v11;
            __nv_bfloat162 h, l;
            h.x = __float2bfloat16_rn(v00);
            h.y = __float2bfloat16_rn(v01);
            l.x = __float2bfloat16_rn(v00 - __bfloat162float(h.x));
            l.y = __float2bfloat16_rn(v01 - __bfloat162float(h.y));
            *(__nv_bfloat162*)&Ohi[g0 + n] = h;
            *(__nv_bfloat162*)&Olo[g0 + n] = l;
            h.x = __float2bfloat16_rn(v10);
            h.y = __float2bfloat16_rn(v11);
            l.x = __float2bfloat16_rn(v10 - __bfloat162float(h.x));
            l.y = __float2bfloat16_rn(v11 - __bfloat162float(h.y));
            *(__nv_bfloat162*)&Ohi[g1 + n] = h;
            *(__nv_bfloat162*)&Olo[g1 + n] = l;
            if (Ofp) {
                *(float2*)&Ofp[g0 + n] = make_float2(v00, v01);
                *(float2*)&Ofp[g1 + n] = make_float2(v10, v11);
            }
        }
        atomicAdd(&snorm[r0], ns0);
        atomicAdd(&snorm[r1], ns1);
    }
    __syncthreads();
    if (tid < 128 && m0 + tid < NT) nrm[m0 + tid] = snorm[tid];
}

// ---------------------------------------------------------------------------
// Query-side SIMT linear+ReLU (tiny, 1024 rows).
// ---------------------------------------------------------------------------
__global__ void __launch_bounds__(256)
linear_relu_kernel(const float* __restrict__ A, const float* __restrict__ W,
                   const float* __restrict__ bias, float* __restrict__ out,
                   int M, int K)
{
    __shared__ __align__(16) float As[16 * 68];
    __shared__ __align__(16) float Bs[16 * 136];
    const int tx = threadIdx.x, ty = threadIdx.y;
    const int tid = ty * 16 + tx;
    const int m0 = blockIdx.x * 64;

    float acc[4][8];
#pragma unroll
    for (int r = 0; r < 4; r++)
#pragma unroll
        for (int c = 0; c < 8; c++) acc[r][c] = 0.f;

    const int nChunks = (K + 15) / 16;
    for (int ch = 0; ch < nChunks; ch++) {
        const int k0 = ch * 16;
#pragma unroll
        for (int i = 0; i < 4; i++) {
            int e = tid + i * 256;
            int k = e & 15, m = e >> 4;
            float v = 0.f;
            if (k0 + k < K && m0 + m < M) v = A[(size_t)(m0 + m) * K + k0 + k];
            As[k * 68 + m] = v;
        }
#pragma unroll
        for (int i = 0; i < 8; i++) {
            int e = tid + i * 256;
            int h = e & 127, k = e >> 7;
            float v = 0.f;
            if (k0 + k < K) v = W[(size_t)(k0 + k) * HD + h];
            Bs[k * 136 + h] = v;
        }
        __syncthreads();
#pragma unroll
        for (int k = 0; k < 16; k++) {
            float4 a  = *(const float4*)&As[k * 68 + ty * 4];
            float4 b0 = *(const float4*)&Bs[k * 136 + tx * 4];
            float4 b1 = *(const float4*)&Bs[k * 136 + 64 + tx * 4];
            float av[4] = {a.x, a.y, a.z, a.w};
            float bv[8] = {b0.x, b0.y, b0.z, b0.w, b1.x, b1.y, b1.z, b1.w};
#pragma unroll
            for (int r = 0; r < 4; r++)
#pragma unroll
                for (int c = 0; c < 8; c++) acc[r][c] += av[r] * bv[c];
        }
        __syncthreads();
    }
#pragma unroll
    for (int r = 0; r < 4; r++) {
        int m = m0 + ty * 4 + r;
        if (m >= M) continue;
#pragma unroll
        for (int half = 0; half < 2; half++) {
#pragma unroll
            for (int c = 0; c < 4; c++) {
                int h = half * 64 + tx * 4 + c;
                float v = acc[r][half * 4 + c] + bias[h];
                out[(size_t)m * HD + h] = fmaxf(v, 0.f);
            }
        }
    }
}

// ---------------------------------------------------------------------------
__global__ void __launch_bounds__(256)
linear_softmax_kernel(const float* __restrict__ A, const float* __restrict__ W,
                      const float* __restrict__ bias, float* __restrict__ out, int M)
{
    __shared__ float Ws[HD * NL];
    __shared__ float bs[NL];
    int tid = threadIdx.x;
    for (int i = tid; i < HD * NL; i += 256) Ws[i] = W[i];
    if (tid < NL) bs[tid] = bias[tid];
    __syncthreads();

    int warp = tid >> 5, lane = tid & 31;
    int m = blockIdx.x * 8 + warp;
    if (m >= M) return;

    float acc[NL];
#pragma unroll
    for (int h = 0; h < NL; h++) acc[h] = 0.f;
    for (int k = lane; k < HD; k += 32) {
        float x = A[(size_t)m * HD + k];
#pragma unroll
        for (int h = 0; h < NL; h++) acc[h] += x * Ws[k * NL + h];
    }
#pragma unroll
    for (int h = 0; h < NL; h++)
#pragma unroll
        for (int off = 16; off > 0; off >>= 1)
            acc[h] += __shfl_down_sync(0xFFFFFFFFu, acc[h], off);

    if (lane == 0) {
        float v[NL], mx = -1e30f;
#pragma unroll
        for (int h = 0; h < NL; h++) { v[h] = acc[h] + bs[h]; mx = fmaxf(mx, v[h]); }
        float s = 0.f;
#pragma unroll
        for (int h = 0; h < NL; h++) { v[h] = expf(v[h] - mx); s += v[h]; }
        float inv = 1.0f / s;
#pragma unroll
        for (int h = 0; h < NL; h++) out[(size_t)m * NL + h] = v[h] * inv;
    }
}

// ---------------------------------------------------------------------------
__global__ void __launch_bounds__(256)
rownorm_kernel(const float* __restrict__ A, float* __restrict__ out, int M, int D)
{
    int warp = threadIdx.x >> 5, lane = threadIdx.x & 31;
    int m = blockIdx.x * 8 + warp;
    if (m >= M) return;
    float s = 0.f;
    for (int k = lane; k < D; k += 32) { float v = A[(size_t)m * D + k]; s += v * v; }
#pragma unroll
    for (int off = 16; off > 0; off >>= 1) s += __shfl_down_sync(0xFFFFFFFFu, s, off);
    if (lane == 0) out[m] = s;
}

// ---------------------------------------------------------------------------
// SIMT fp32 distance GEMM (layer 4, D=8) + tile min.
// ---------------------------------------------------------------------------
__global__ void __launch_bounds__(256)
dist_kernel(const float* __restrict__ Q, const float* __restrict__ T,
            const float* __restrict__ qn, const float* __restrict__ tn,
            float* __restrict__ out, float* __restrict__ gmin, int D, int Ncols)
{
    __shared__ __align__(16) float As[16 * 68];
    __shared__ __align__(16) float Bs[16 * 136];
    __shared__ unsigned sMinU[64];
    const int tx = threadIdx.x, ty = threadIdx.y;
    const int tid = ty * 16 + tx;
    const int n0 = blockIdx.x * 128;
    const int m0 = blockIdx.y * 64;

    if (tid < 64) sMinU[tid] = 0x7F800000u;

    float acc[4][8];
#pragma unroll
    for (int r = 0; r < 4; r++)
#pragma unroll
        for (int c = 0; c < 8; c++) acc[r][c] = 0.f;

    const int nChunks = (D + 15) / 16;
    for (int ch = 0; ch < nChunks; ch++) {
        const int k0 = ch * 16;
#pragma unroll
        for (int i = 0; i < 4; i++) {
            int e = tid + i * 256;
            int k = e & 15, m = e >> 4;
            float v = (k0 + k < D) ? Q[(size_t)(m0 + m) * D + k0 + k] : 0.f;
            As[k * 68 + m] = v;
        }
#pragma unroll
        for (int i = 0; i < 8; i++) {
            int e = tid + i * 256;
            int k = e & 15, n = e >> 4;
            int gn = n0 + n;
            float v = 0.f;
            if (k0 + k < D && gn < Ncols) v = T[(size_t)gn * D + k0 + k];
            Bs[k * 136 + n] = v;
        }
        __syncthreads();
#pragma unroll
        for (int k = 0; k < 16; k++) {
            float4 a  = *(const float4*)&As[k * 68 + ty * 4];
            float4 b0 = *(const float4*)&Bs[k * 136 + tx * 4];
            float4 b1 = *(const float4*)&Bs[k * 136 + 64 + tx * 4];
            float av[4] = {a.x, a.y, a.z, a.w};
            float bv[8] = {b0.x, b0.y, b0.z, b0.w, b1.x, b1.y, b1.z, b1.w};
#pragma unroll
            for (int r = 0; r < 4; r++)
#pragma unroll
                for (int c = 0; c < 8; c++) acc[r][c] += av[r] * bv[c];
        }
        __syncthreads();
    }
    const float FINF = __int_as_float(0x7F800000);
#pragma unroll
    for (int r = 0; r < 4; r++) {
        int m = m0 + ty * 4 + r;
        float qv = qn[m];
        float lm = FINF;
#pragma unroll
        for (int half = 0; half < 2; half++) {
#pragma unroll
            for (int c = 0; c < 4; c++) {
                int n = n0 + half * 64 + tx * 4 + c;
                if (n < Ncols) {
                    float d = fmaxf(qv + tn[n] - 2.f * acc[r][half * 4 + c], 0.f);
                    out[(size_t)m * Ncols + n] = d;
                    lm = fminf(lm, d);
                }
            }
        }
        if (lm < FINF) atomicMin(&sMinU[ty * 4 + r], __float_as_uint(lm));
    }
    __syncthreads();
    if (tid < 64)
        gmin[(size_t)(m0 + tid) * NTILES + blockIdx.x] = __uint_as_float(sMinU[tid]);
}

// ---------------------------------------------------------------------------
// Exact top-K select: tile-min threshold + single-scan compaction.
// ---------------------------------------------------------------------------
#define SEL_THREADS 512
#define SEL_CAP 2048
#define OFF_CAND  16384
#define OFF_SEL   (OFF_CAND + SEL_CAP * 8)
#define OFF_TIES  (OFF_SEL + 1024)
#define OFF_TLAB  (OFF_TIES + 1024)
#define OFF_MINS  (OFF_TLAB + 512)
#define SEL_SMEM  (OFF_MINS + 392 * 4)

__device__ __forceinline__ void find_kth(const unsigned* hist, int NB, unsigned kth,
                                         int tid, unsigned* s_bin, unsigned* s_kthr)
{
    if (tid < 32) {
        unsigned running = 0;
        for (int base = 0; base < NB; base += 32) {
            unsigned v = hist[base + tid];
            unsigned sc = v;
#pragma unroll
            for (int off = 1; off < 32; off <<= 1) {
                unsigned t = __shfl_up_sync(0xFFFFFFFFu, sc, off);
                if (tid >= off) sc += t;
            }
            unsigned tot = __shfl_sync(0xFFFFFFFFu, sc, 31);
            if (running + tot >= kth) {
                unsigned mask = __ballot_sync(0xFFFFFFFFu, running + sc >= kth);
                int l = __ffs(mask) - 1;
                if (tid == l) { *s_bin = (unsigned)(base + l); *s_kthr = kth - running - (sc - v); }
                break;
            }
            running += tot;
        }
    }
}

__global__ void __launch_bounds__(SEL_THREADS)
select_kernel(const float* __restrict__ d2mat, const float* __restrict__ gmin,
              const int* __restrict__ labels, float* __restrict__ total, int init)
{
    extern __shared__ __align__(16) char sms[];
    unsigned* hist = (unsigned*)sms;
    u64* cand  = (u64*)(sms + OFF_CAND);
    u64* sel   = (u64*)(sms + OFF_SEL);
    u64* ties  = (u64*)(sms + OFF_TIES);
    int* tlab  = (int*)(sms + OFF_TLAB);
    float* mins = (float*)(sms + OFF_MINS);

    __shared__ unsigned s_M75, s_bin, s_kthr, s_candcnt, s_selcnt, s_tiecnt;
    __shared__ float s_w[80];
    __shared__ int s_lab[80];

    const int b = blockIdx.x, tid = threadIdx.x, lane = tid & 31;
    const uint4* usrc = (const uint4*)(d2mat + (size_t)b * NT);
    const int NH = NT / 4;

    for (int i = tid; i < NTILES; i += SEL_THREADS)
        mins[i] = gmin[(size_t)b * NTILES + i];
    if (tid == 0) { s_candcnt = 0; s_selcnt = 0; s_tiecnt = 0; }
    __syncthreads();
    if (tid < NTILES) {
        unsigned key = __float_as_uint(mins[tid]);
        int c = 0;
        for (int j = 0; j < NTILES; j++) {
            unsigned kj = __float_as_uint(mins[j]);
            c += (kj < key) || (kj == key && j < tid);
        }
        if (c == KNN - 1) s_M75 = key;
    }
    __syncthreads();
    const unsigned Mkey = s_M75;

    for (int base = 0; base < NH; base += 2 * SEL_THREADS) {
        int i0 = base + tid;
        int i1 = base + SEL_THREADS + tid;
        uint4 a = (i0 < NH) ? usrc[i0] : make_uint4(~0u, ~0u, ~0u, ~0u);
        uint4 c4 = (i1 < NH) ? usrc[i1] : make_uint4(~0u, ~0u, ~0u, ~0u);
        unsigned k0[4] = {a.x, a.y, a.z, a.w};
        unsigned k1[4] = {c4.x, c4.y, c4.z, c4.w};
#pragma unroll
        for (int j = 0; j < 4; j++) {
            if (k0[j] <= Mkey) {
                unsigned s = atomicAdd(&s_candcnt, 1u);
                if (s < SEL_CAP) cand[s] = ((u64)k0[j] << 32) | (unsigned)(i0 * 4 + j);
            }
            if (k1[j] <= Mkey) {
                unsigned s = atomicAdd(&s_candcnt, 1u);
                if (s < SEL_CAP) cand[s] = ((u64)k1[j] << 32) | (unsigned)(i1 * 4 + j);
            }
        }
    }
    __syncthreads();

    unsigned Tkey;
    const unsigned candTotal = s_candcnt;

    if (candTotal <= SEL_CAP) {
        const int cc = (int)candTotal;
        for (int i = tid; i < 4096; i += SEL_THREADS) hist[i] = 0;
        __syncthreads();
        for (int i = tid; i < cc; i += SEL_THREADS)
            atomicAdd(&hist[(unsigned)(cand[i] >> 52)], 1u);
        __syncthreads();
        find_kth(hist, 4096, KNN, tid, &s_bin, &s_kthr);
        __syncthreads();
        const unsigned pfx = s_bin;
        const unsigned k1v = s_kthr;
        for (int i = tid; i < 4096; i += SEL_THREADS) hist[i] = 0;
        __syncthreads();
        for (int i = tid; i < cc; i += SEL_THREADS) {
            unsigned key = (unsigned)(cand[i] >> 32);
            if ((key >> 20) == pfx) atomicAdd(&hist[(key >> 8) & 0xFFFu], 1u);
        }
        __syncthreads();
        find_kth(hist, 4096, k1v, tid, &s_bin, &s_kthr);
        __syncthreads();
        const unsigned pfx20 = (pfx << 12) | s_bin;
        const unsigned k2v = s_kthr;
        for (int i = tid; i < 256; i += SEL_THREADS) hist[i] = 0;
        __syncthreads();
        for (int i = tid; i < cc; i += SEL_THREADS) {
            unsigned key = (unsigned)(cand[i] >> 32);
            if ((key >> 8) == pfx20) atomicAdd(&hist[key & 0xFFu], 1u);
        }
        __syncthreads();
        find_kth(hist, 256, k2v, tid, &s_bin, &s_kthr);
        __syncthreads();
        Tkey = (pfx20 << 8) | s_bin;
        for (int i = tid; i < cc; i += SEL_THREADS) {
            u64 cv = cand[i];
            unsigned key = (unsigned)(cv >> 32);
            if (key < Tkey) {
                unsigned s = atomicAdd(&s_selcnt, 1u);
                if (s < 128) sel[s] = cv;
            } else if (key == Tkey) {
                unsigned s = atomicAdd(&s_tiecnt, 1u);
                if (s < 128) ties[s] = cv;
            }
        }
        __syncthreads();
    } else {
        // fallback: full gmem radix passes (degenerate distributions)
        const float4* src = (const float4*)(d2mat + (size_t)b * NT);
        const int NIT = (NT / 4 + SEL_THREADS - 1) / SEL_THREADS;
        for (int i = tid; i < 4096; i += SEL_THREADS) hist[i] = 0;
        __syncthreads();
        for (int it = 0; it < NIT; it++) {
            int i = it * SEL_THREADS + tid;
            bool valid = (i < NH);
            float4 v = valid ? src[i] : make_float4(0.f, 0.f, 0.f, 0.f);
            float e[4] = {v.x, v.y, v.z, v.w};
#pragma unroll
            for (int j = 0; j < 4; j++) {
                unsigned bin = valid ? (__float_as_uint(e[j]) >> 20) : 0xFFFFFFFFu;
                unsigned grp = __match_any_sync(0xFFFFFFFFu, bin);
                if (bin != 0xFFFFFFFFu && lane == __ffs(grp) - 1)
                    atomicAdd(&hist[bin], (unsigned)__popc(grp));
            }
        }
        __syncthreads();
        find_kth(hist, 4096, KNN, tid, &s_bin, &s_kthr);
        __syncthreads();
        const unsigned pfx = s_bin;
        const unsigned k1v = s_kthr;

        for (int i = tid; i < 4096; i += SEL_THREADS) hist[i] = 0;
        __syncthreads();
        for (int it = 0; it < NIT; it++) {
            int i = it * SEL_THREADS + tid;
            bool valid = (i < NH);
            float4 v = valid ? src[i] : make_float4(0.f, 0.f, 0.f, 0.f);
            float e[4] = {v.x, v.y, v.z, v.w};
#pragma unroll
            for (int j = 0; j < 4; j++) {
                unsigned key = __float_as_uint(e[j]);
                unsigned bin = (valid && (key >> 20) == pfx) ? ((key >> 8) & 0xFFFu)
                                                             : 0xFFFFFFFFu;
                unsigned grp = __match_any_sync(0xFFFFFFFFu, bin);
                if (bin != 0xFFFFFFFFu && lane == __ffs(grp) - 1)
                    atomicAdd(&hist[bin], (unsigned)__popc(grp));
            }
        }
        __syncthreads();
        find_kth(hist, 4096, k1v, tid, &s_bin, &s_kthr);
        __syncthreads();
        const unsigned pfx20 = (pfx << 12) | s_bin;
        const unsigned k2v = s_kthr;

        for (int i = tid; i < 256; i += SEL_THREADS) hist[i] = 0;
        __syncthreads();
        for (int it = 0; it < NIT; it++) {
            int i = it * SEL_THREADS + tid;
            bool valid = (i < NH);
            float4 v = valid ? src[i] : make_float4(0.f, 0.f, 0.f, 0.f);
            float e[4] = {v.x, v.y, v.z, v.w};
#pragma unroll
            for (int j = 0; j < 4; j++) {
                unsigned key = __float_as_uint(e[j]);
                unsigned bin = (valid && (key >> 8) == pfx20) ? (key & 0xFFu)
                                                              : 0xFFFFFFFFu;
                unsigned grp = __match_any_sync(0xFFFFFFFFu, bin);
                if (bin != 0xFFFFFFFFu && lane == __ffs(grp) - 1)
                    atomicAdd(&hist[bin], (unsigned)__popc(grp));
            }
        }
        __syncthreads();
        find_kth(hist, 256, k2v, tid, &s_bin, &s_kthr);
        __syncthreads();
        Tkey = (pfx20 << 8) | s_bin;

        for (int it = 0; it < NIT; it++) {
            int i = it * SEL_THREADS + tid;
            if (i < NH) {
                float4 v = src[i];
                float e[4] = {v.x, v.y, v.z, v.w};
#pragma unroll
                for (int j = 0; j < 4; j++) {
                    unsigned key = __float_as_uint(e[j]);
                    if (key < Tkey) {
                        unsigned s = atomicAdd(&s_selcnt, 1u);
                        if (s < 128) sel[s] = ((u64)key << 32) | (unsigned)(i * 4 + j);
                    } else if (key == Tkey) {
                        unsigned s = atomicAdd(&s_tiecnt, 1u);
                        if (s < 128) ties[s] = ((u64)key << 32) | (unsigned)(i * 4 + j);
                    }
                }
            }
        }
        __syncthreads();
    }

    const int ns = min((int)s_selcnt, 128);
    const int ne = min((int)s_tiecnt, 128);

    if (tid < ns) {
        u64 mine = sel[tid];
        unsigned my_idx = (unsigned)(mine & 0xFFFFFFFFu);
        int rank = 0;
        for (int j = 0; j < ns; j++) rank += ((unsigned)(sel[j] & 0xFFFFFFFFu) < my_idx);
        float d2 = __uint_as_float((unsigned)(mine >> 32));
        s_w[rank] = (d2 > 0.f) ? __fdiv_rn(1.0f, __fsqrt_rn(d2)) : 0.f;
        s_lab[rank] = labels[my_idx];
    }
    if (tid >= 128 && tid - 128 < ne) {
        int t = tid - 128;
        unsigned my_idx = (unsigned)(ties[t] & 0xFFFFFFFFu);
        int rank = 0;
        for (int j = 0; j < ne; j++) rank += ((unsigned)(ties[j] & 0xFFFFFFFFu) < my_idx);
        tlab[rank] = labels[my_idx];
    }
    __syncthreads();

    if (tid == 0) {
        float cls[NL];
#pragma unroll
        for (int l = 0; l < NL; l++) cls[l] = 0.f;
        float stot = 0.f;
        for (int j = 0; j < ns; j++) { stot += s_w[j]; cls[s_lab[j]] += s_w[j]; }
        int need = KNN - ns;
        float d2T = __uint_as_float(Tkey);
        float wT = (d2T > 0.f) ? __fdiv_rn(1.0f, __fsqrt_rn(d2T)) : 0.f;
        int m = (need < ne) ? need : ne;
        for (int j = 0; j < m; j++) { stot += wT; cls[tlab[j]] += wT; }
#pragma unroll
        for (int l = 0; l < NL; l++) {
            float val = stot - cls[l];
            size_t o = (size_t)b * NL + l;
            if (init) total[o] = val; else total[o] += val;
        }
    }
}

// ---------------------------------------------------------------------------
__global__ void __launch_bounds__(256)
pvalue_kernel(const float* __restrict__ total, const float* __restrict__ cali,
              float* __restrict__ out)
{
    const int b = blockIdx.x, tid = threadIdx.x;
    float t[NL];
#pragma unroll
    for (int l = 0; l < NL; l++) t[l] = total[(size_t)b * NL + l];
    int cnt[NL];
#pragma unroll
    for (int l = 0; l < NL; l++) cnt[l] = 0;
    for (int i = tid; i < NC; i += 256) {
        float c = cali[i];
#pragma unroll
        for (int l = 0; l < NL; l++) cnt[l] += (c >= t[l]) ? 1 : 0;
    }
    __shared__ int sc[NL];
    if (tid < NL) sc[tid] = 0;
    __syncthreads();
#pragma unroll
    for (int l = 0; l < NL; l++) atomicAdd(&sc[l], cnt[l]);
    __syncthreads();
    if (tid < NL) out[(size_t)b * NL + tid] = (float)sc[tid] * (1.0f / NC);
}

// ---------------------------------------------------------------------------
extern "C" void kernel_launch(void* const* d_in, const int* in_sizes, int n_in,
                              void* d_out, int out_size)
{
    const float* x        = (const float*)d_in[0];
    const float* train_x  = (const float*)d_in[1];
    const int*   lab      = (const int*)  d_in[2];
    const float* cali     = (const float*)d_in[3];
    const float* W1 = (const float*)d_in[4];  const float* b1 = (const float*)d_in[5];
    const float* W2 = (const float*)d_in[6];  const float* b2 = (const float*)d_in[7];
    const float* W3 = (const float*)d_in[8];  const float* b3 = (const float*)d_in[9];
    const float* W4 = (const float*)d_in[10]; const float* b4 = (const float*)d_in[11];
    float* out = (float*)d_out;

    float *h1p, *h2p, *h3p, *q4p, *t3p, *t4p, *d2p, *qnp, *tnp, *totp, *minp;
    __nv_bfloat16 *qhip, *qlop, *thip, *tlop, *thi2p, *tlo2p;
    __nv_bfloat16 *w1th, *w1tl, *w2th, *w2tl, *w3th, *w3tl;
    cudaGetSymbolAddress((void**)&h1p, g_h1);
    cudaGetSymbolAddress((void**)&h2p, g_h2);
    cudaGetSymbolAddress((void**)&h3p, g_h3);
    cudaGetSymbolAddress((void**)&q4p, g_q4);
    cudaGetSymbolAddress((void**)&t3p, g_t3);
    cudaGetSymbolAddress((void**)&t4p, g_t4);
    cudaGetSymbolAddress((void**)&d2p, g_d2);
    cudaGetSymbolAddress((void**)&minp, g_min);
    cudaGetSymbolAddress((void**)&qnp, g_qn);
    cudaGetSymbolAddress((void**)&tnp, g_tn);
    cudaGetSymbolAddress((void**)&totp, g_tot);
    cudaGetSymbolAddress((void**)&qhip, g_qhi);
    cudaGetSymbolAddress((void**)&qlop, g_qlo);
    cudaGetSymbolAddress((void**)&thip, g_thi);
    cudaGetSymbolAddress((void**)&tlop, g_tlo);
    cudaGetSymbolAddress((void**)&thi2p, g_thi2);
    cudaGetSymbolAddress((void**)&tlo2p, g_tlo2);
    cudaGetSymbolAddress((void**)&w1th, g_w1th);
    cudaGetSymbolAddress((void**)&w1tl, g_w1tl);
    cudaGetSymbolAddress((void**)&w2th, g_w2th);
    cudaGetSymbolAddress((void**)&w2tl, g_w2tl);
    cudaGetSymbolAddress((void**)&w3th, g_w3th);
    cudaGetSymbolAddress((void**)&w3tl, g_w3tl);

    cudaFuncSetAttribute(select_kernel,
                         cudaFuncAttributeMaxDynamicSharedMemorySize, SEL_SMEM);

    dim3 tb(16, 16);
    const int D0 = 83;
    const dim3 mgrid(NTILES, BQ / 128);

    conv_norm_kernel<<<BQ / 8, 256>>>(x, qhip, qlop, qnp, BQ, D0);
    conv_norm_kernel<<<NTP / 8, 256>>>(train_x, thip, tlop, tnp, NT, D0);
    wt_convert_kernel<<<(3 * 128 * 128 + 255) / 256, 256>>>(W1, W2, W3);

    // layer 0 (mma_dist = launch #4 -> profiled)
    mma_dist_kernel<<<mgrid, 256>>>(qhip, qlop, thip, tlop, qnp, tnp, d2p, minp, 6);
    select_kernel<<<BQ, SEL_THREADS, SEL_SMEM>>>(d2p, minp, lab, totp, 1);

    // query-side MLP (tiny SIMT)
    linear_relu_kernel<<<BQ / 64, tb>>>(x,   W1, b1, h1p, BQ, D0);
    linear_relu_kernel<<<BQ / 64, tb>>>(h1p, W2, b2, h2p, BQ, HD);
    linear_relu_kernel<<<BQ / 64, tb>>>(h2p, W3, b3, h3p, BQ, HD);
    linear_softmax_kernel<<<(BQ + 7) / 8, 256>>>(h3p, W4, b4, q4p, BQ);

    // layer 1
    mma_linear_kernel<<<NTILES, 256>>>(thip, tlop, w1th, w1tl, b1,
                                       thi2p, tlo2p, tnp, (float*)0, 6);
    conv_norm_kernel<<<BQ / 8, 256>>>(h1p, qhip, qlop, qnp, BQ, HD);
    mma_dist_kernel<<<mgrid, 256>>>(qhip, qlop, thi2p, tlo2p, qnp, tnp, d2p, minp, 8);
    select_kernel<<<BQ, SEL_THREADS, SEL_SMEM>>>(d2p, minp, lab, totp, 0);

    // layer 2
    mma_linear_kernel<<<NTILES, 256>>>(thi2p, tlo2p, w2th, w2tl, b2,
                                       thip, tlop, tnp, (float*)0, 8);
    conv_norm_kernel<<<BQ / 8, 256>>>(h2p, qhip, qlop, qnp, BQ, HD);
    mma_dist_kernel<<<mgrid, 256>>>(qhip, qlop, thip, tlop, qnp, tnp, d2p, minp, 8);
    select_kernel<<<BQ, SEL_THREADS, SEL_SMEM>>>(d2p, minp, lab, totp, 0);

    // layer 3 (+ fp32 t3 for softmax)
    mma_linear_kernel<<<NTILES, 256>>>(thip, tlop, w3th, w3tl, b3,
                                       thi2p, tlo2p, tnp, t3p, 8);
    conv_norm_kernel<<<BQ / 8, 256>>>(h3p, qhip, qlop, qnp, BQ, HD);
    mma_dist_kernel<<<mgrid, 256>>>(qhip, qlop, thi2p, tlo2p, qnp, tnp, d2p, minp, 8);
    select_kernel<<<BQ, SEL_THREADS, SEL_SMEM>>>(d2p, minp, lab, totp, 0);

    // layer 4 (softmax features, D=8): exact fp32 path
    linear_softmax_kernel<<<(NT + 7) / 8, 256>>>(t3p, W4, b4, t4p, NT);
    rownorm_kernel<<<(BQ + 7) / 8, 256>>>(q4p, qnp, BQ, NL);
    rownorm_kernel<<<(NT + 7) / 8, 256>>>(t4p, tnp, NT, NL);
    dist_kernel<<<dim3(NTILES, BQ / 64), tb>>>(q4p, t4p, qnp, tnp, d2p, minp, NL, NT);
    select_kernel<<<BQ, SEL_THREADS, SEL_SMEM>>>(d2p, minp, lab, totp, 0);

    pvalue_kernel<<<BQ, 256>>>(totp, cali, out);
}

// round 9
// speedup vs baseline: 3.8647x; 1.0553x over previous
#include <cuda_runtime.h>
#include <cuda_bf16.h>
#include <math.h>
#include <stdint.h>

#define BQ   1024
#define NT   50000
#define NTP  50048
#define NL   8
#define KNN  75
#define HD   128
#define NC   10000
#define NTILES 391          // NTP/128

typedef unsigned long long u64;

// ---------------- device scratch ----------------
__device__ float g_h1[BQ * HD];
__device__ float g_h2[BQ * HD];
__device__ float g_h3[BQ * HD];
__device__ float g_q4[BQ * NL];
__device__ float g_t3[(size_t)NT * HD];
__device__ float g_t4[(size_t)NT * NL];
__device__ float g_d2[(size_t)BQ * NT];
__device__ float g_min[(size_t)BQ * NTILES];
__device__ float g_qn[BQ];
__device__ float g_tn[NT];
__device__ float g_tot[BQ * NL];
__device__ __nv_bfloat16 g_qhi[(size_t)BQ * 128];
__device__ __nv_bfloat16 g_qlo[(size_t)BQ * 128];
__device__ __nv_bfloat16 g_thi[(size_t)NTP * 128];    // bank A
__device__ __nv_bfloat16 g_tlo[(size_t)NTP * 128];
__device__ __nv_bfloat16 g_thi2[(size_t)NTP * 128];   // bank B
__device__ __nv_bfloat16 g_tlo2[(size_t)NTP * 128];
__device__ __nv_bfloat16 g_w1th[128 * 128], g_w1tl[128 * 128];
__device__ __nv_bfloat16 g_w2th[128 * 128], g_w2tl[128 * 128];
__device__ __nv_bfloat16 g_w3th[128 * 128], g_w3tl[128 * 128];

// ---------------------------------------------------------------------------
__device__ __forceinline__ void mma_bf16(float* d, const uint32_t* a, const uint32_t* b)
{
    asm volatile(
        "mma.sync.aligned.m16n8k16.row.col.f32.bf16.bf16.f32 "
        "{%0,%1,%2,%3}, {%4,%5,%6,%7}, {%8,%9}, {%0,%1,%2,%3};"
        : "+f"(d[0]), "+f"(d[1]), "+f"(d[2]), "+f"(d[3])
        : "r"(a[0]), "r"(a[1]), "r"(a[2]), "r"(a[3]), "r"(b[0]), "r"(b[1]));
}

#define SLICE_ELEMS (128 * 24)

__device__ __forceinline__ void slice_load_async(
    const __nv_bfloat16* __restrict__ Gp, __nv_bfloat16* Ss,
    int row0, int k0, int lr, int lh)
{
    uint32_t sa = (uint32_t)__cvta_generic_to_shared(Ss + lr * 24 + lh * 8);
    const void* ga = Gp + (size_t)(row0 + lr) * 128 + k0 + lh * 8;
    asm volatile("cp.async.cg.shared.global [%0], [%1], 16;\n" :: "r"(sa), "l"(ga));
}

// ---------------------------------------------------------------------------
__global__ void __launch_bounds__(256)
conv_norm_kernel(const float* __restrict__ A, __nv_bfloat16* __restrict__ hi,
                 __nv_bfloat16* __restrict__ lo, float* __restrict__ nrm,
                 int Mreal, int D)
{
    int warp = threadIdx.x >> 5, lane = threadIdx.x & 31;
    int row = blockIdx.x * 8 + warp;
    int base = lane * 4;

    float ss = 0.f;
    __nv_bfloat16 hb[4], lb[4];
#pragma unroll
    for (int j = 0; j < 4; j++) {
        int col = base + j;
        float v = (row < Mreal && col < D) ? A[(size_t)row * D + col] : 0.f;
        ss += v * v;
        hb[j] = __float2bfloat16_rn(v);
        lb[j] = __float2bfloat16_rn(v - __bfloat162float(hb[j]));
    }
    __nv_bfloat162 h01, h23, l01, l23;
    h01.x = hb[0]; h01.y = hb[1]; h23.x = hb[2]; h23.y = hb[3];
    l01.x = lb[0]; l01.y = lb[1]; l23.x = lb[2]; l23.y = lb[3];
    *(__nv_bfloat162*)&hi[(size_t)row * 128 + base]     = h01;
    *(__nv_bfloat162*)&hi[(size_t)row * 128 + base + 2] = h23;
    *(__nv_bfloat162*)&lo[(size_t)row * 128 + base]     = l01;
    *(__nv_bfloat162*)&lo[(size_t)row * 128 + base + 2] = l23;

#pragma unroll
    for (int off = 16; off > 0; off >>= 1) ss += __shfl_down_sync(0xFFFFFFFFu, ss, off);
    if (lane == 0 && row < Mreal) nrm[row] = ss;
}

// ---------------------------------------------------------------------------
__global__ void __launch_bounds__(256)
wt_convert_kernel(const float* __restrict__ W1, const float* __restrict__ W2,
                  const float* __restrict__ W3)
{
    int idx = blockIdx.x * 256 + threadIdx.x;
    if (idx >= 3 * 128 * 128) return;
    int which = idx >> 14;
    int e = idx & 16383;
    int n = e & 127, k = e >> 7;
    const float* W = (which == 0) ? W1 : (which == 1) ? W2 : W3;
    int K = (which == 0) ? 83 : 128;
    float v = (k < K) ? W[(size_t)k * 128 + n] : 0.f;
    __nv_bfloat16 h = __float2bfloat16_rn(v);
    __nv_bfloat16 l = __float2bfloat16_rn(v - __bfloat162float(h));
    __nv_bfloat16* dh = (which == 0) ? g_w1th : (which == 1) ? g_w2th : g_w3th;
    __nv_bfloat16* dl = (which == 0) ? g_w1tl : (which == 1) ? g_w2tl : g_w3tl;
    dh[e] = h;
    dl[e] = l;
}

// ---------------------------------------------------------------------------
// bf16x3 GEMM mainloop: per k-chunk, 4 slices loaded once, 3 combos (48 MMAs).
// ---------------------------------------------------------------------------
__device__ __forceinline__ void gemm3_mainloop(
    const __nv_bfloat16* Ahi, const __nv_bfloat16* Alo,
    const __nv_bfloat16* Bhi, const __nv_bfloat16* Blo,
    __nv_bfloat16* smem, int m0, int n0, int nCh,
    int wm, int wn, int fr, int fc, int lr, int lh,
    float acc[2][8][4])
{
    __nv_bfloat16* AhiS[2] = {smem,                   smem + 4 * SLICE_ELEMS};
    __nv_bfloat16* AloS[2] = {smem + 1 * SLICE_ELEMS, smem + 5 * SLICE_ELEMS};
    __nv_bfloat16* BhiS[2] = {smem + 2 * SLICE_ELEMS, smem + 6 * SLICE_ELEMS};
    __nv_bfloat16* BloS[2] = {smem + 3 * SLICE_ELEMS, smem + 7 * SLICE_ELEMS};

    slice_load_async(Ahi, AhiS[0], m0, 0, lr, lh);
    slice_load_async(Alo, AloS[0], m0, 0, lr, lh);
    slice_load_async(Bhi, BhiS[0], n0, 0, lr, lh);
    slice_load_async(Blo, BloS[0], n0, 0, lr, lh);
    asm volatile("cp.async.commit_group;\n" ::: "memory");

    for (int c = 0; c < nCh; c++) {
        int buf = c & 1;
        if (c + 1 < nCh) {
            int k0 = (c + 1) * 16;
            slice_load_async(Ahi, AhiS[buf ^ 1], m0, k0, lr, lh);
            slice_load_async(Alo, AloS[buf ^ 1], m0, k0, lr, lh);
            slice_load_async(Bhi, BhiS[buf ^ 1], n0, k0, lr, lh);
            slice_load_async(Blo, BloS[buf ^ 1], n0, k0, lr, lh);
            asm volatile("cp.async.commit_group;\n" ::: "memory");
            asm volatile("cp.async.wait_group 1;" ::: "memory");
        } else {
            asm volatile("cp.async.wait_group 0;" ::: "memory");
        }
        __syncthreads();

        const __nv_bfloat16* Ah = AhiS[buf];
        const __nv_bfloat16* Al = AloS[buf];
        const __nv_bfloat16* Bh = BhiS[buf];
        const __nv_bfloat16* Bl = BloS[buf];

        uint32_t ah[2][4], al[2][4];
#pragma unroll
        for (int mt = 0; mt < 2; mt++) {
            int bm = wm + mt * 16;
            ah[mt][0] = *(const uint32_t*)&Ah[(bm + fr) * 24 + fc];
            ah[mt][1] = *(const uint32_t*)&Ah[(bm + fr + 8) * 24 + fc];
            ah[mt][2] = *(const uint32_t*)&Ah[(bm + fr) * 24 + fc + 8];
            ah[mt][3] = *(const uint32_t*)&Ah[(bm + fr + 8) * 24 + fc + 8];
            al[mt][0] = *(const uint32_t*)&Al[(bm + fr) * 24 + fc];
            al[mt][1] = *(const uint32_t*)&Al[(bm + fr + 8) * 24 + fc];
            al[mt][2] = *(const uint32_t*)&Al[(bm + fr) * 24 + fc + 8];
            al[mt][3] = *(const uint32_t*)&Al[(bm + fr + 8) * 24 + fc + 8];
        }
#pragma unroll
        for (int nt = 0; nt < 8; nt++) {
            int nb = wn + nt * 8;
            uint32_t bh[2], bl[2];
            bh[0] = *(const uint32_t*)&Bh[(nb + fr) * 24 + fc];
            bh[1] = *(const uint32_t*)&Bh[(nb + fr) * 24 + fc + 8];
            bl[0] = *(const uint32_t*)&Bl[(nb + fr) * 24 + fc];
            bl[1] = *(const uint32_t*)&Bl[(nb + fr) * 24 + fc + 8];
            mma_bf16(acc[0][nt], ah[0], bh);
            mma_bf16(acc[1][nt], ah[1], bh);
            mma_bf16(acc[0][nt], al[0], bh);
            mma_bf16(acc[1][nt], al[1], bh);
            mma_bf16(acc[0][nt], ah[0], bl);
            mma_bf16(acc[1][nt], ah[1], bl);
        }
        __syncthreads();
    }
}

// ---------------------------------------------------------------------------
__global__ void __launch_bounds__(256)
mma_dist_kernel(const __nv_bfloat16* __restrict__ Qhi, const __nv_bfloat16* __restrict__ Qlo,
                const __nv_bfloat16* __restrict__ Thi, const __nv_bfloat16* __restrict__ Tlo,
                const float* __restrict__ qn, const float* __restrict__ tn,
                float* __restrict__ out, float* __restrict__ gmin, int nCh)
{
    __shared__ __align__(16) __nv_bfloat16 smem[8 * SLICE_ELEMS];
    __shared__ float sMin[128][2];
    const int tid = threadIdx.x;
    const int wid = tid >> 5, lane = tid & 31;
    const int n0 = blockIdx.x * 128;
    const int m0 = blockIdx.y * 128;
    const int wm = (wid & 3) * 32;
    const int wn = (wid >> 2) * 64;
    const int lr = tid >> 1, lh = tid & 1;
    const int fr = lane >> 2, fc = (lane & 3) * 2;

    float acc[2][8][4];
#pragma unroll
    for (int mt = 0; mt < 2; mt++)
#pragma unroll
        for (int nt = 0; nt < 8; nt++)
#pragma unroll
            for (int j = 0; j < 4; j++) acc[mt][nt][j] = 0.f;

    gemm3_mainloop(Qhi, Qlo, Thi, Tlo, smem, m0, n0, nCh,
                   wm, wn, fr, fc, lr, lh, acc);

    const float FINF = __int_as_float(0x7F800000);
    float rmin[2][2] = {{FINF, FINF}, {FINF, FINF}};
#pragma unroll
    for (int mt = 0; mt < 2; mt++) {
        int mrow = m0 + wm + mt * 16 + fr;
        float q0 = qn[mrow], q1 = qn[mrow + 8];
#pragma unroll
        for (int nt = 0; nt < 8; nt++) {
            int n = n0 + wn + nt * 8 + fc;
            if (n < NT) {
                float t0 = tn[n], t1 = tn[n + 1];
                float2 o;
                o.x = fmaxf(q0 + t0 - 2.f * acc[mt][nt][0], 0.f);
                o.y = fmaxf(q0 + t1 - 2.f * acc[mt][nt][1], 0.f);
                *(float2*)&out[(size_t)mrow * NT + n] = o;
                rmin[mt][0] = fminf(rmin[mt][0], fminf(o.x, o.y));
                o.x = fmaxf(q1 + t0 - 2.f * acc[mt][nt][2], 0.f);
                o.y = fmaxf(q1 + t1 - 2.f * acc[mt][nt][3], 0.f);
                *(float2*)&out[(size_t)(mrow + 8) * NT + n] = o;
                rmin[mt][1] = fminf(rmin[mt][1], fminf(o.x, o.y));
            }
        }
    }
#pragma unroll
    for (int mt = 0; mt < 2; mt++)
#pragma unroll
        for (int rr = 0; rr < 2; rr++) {
            float m = rmin[mt][rr];
            m = fminf(m, __shfl_xor_sync(0xFFFFFFFFu, m, 1));
            m = fminf(m, __shfl_xor_sync(0xFFFFFFFFu, m, 2));
            if ((lane & 3) == 0)
                sMin[wm + mt * 16 + rr * 8 + fr][wn >> 6] = m;
        }
    __syncthreads();
    if (tid < 128)
        gmin[(size_t)(m0 + tid) * NTILES + blockIdx.x] =
            fminf(sMin[tid][0], sMin[tid][1]);
}

// ---------------------------------------------------------------------------
__global__ void __launch_bounds__(256)
mma_linear_kernel(const __nv_bfloat16* __restrict__ Ahi, const __nv_bfloat16* __restrict__ Alo,
                  const __nv_bfloat16* __restrict__ Wth, const __nv_bfloat16* __restrict__ Wtl,
                  const float* __restrict__ bias,
                  __nv_bfloat16* __restrict__ Ohi, __nv_bfloat16* __restrict__ Olo,
                  float* __restrict__ nrm, float* __restrict__ Ofp, int nCh)
{
    __shared__ __align__(16) __nv_bfloat16 smem[8 * SLICE_ELEMS];
    __shared__ float snorm[128];
    __shared__ float sbias[128];
    const int tid = threadIdx.x;
    const int wid = tid >> 5, lane = tid & 31;
    const int m0 = blockIdx.x * 128;
    const int wm = (wid & 3) * 32;
    const int wn = (wid >> 2) * 64;
    const int lr = tid >> 1, lh = tid & 1;
    const int fr = lane >> 2, fc = (lane & 3) * 2;

    if (tid < 128) { sbias[tid] = bias[tid]; snorm[tid] = 0.f; }

    float acc[2][8][4];
#pragma unroll
    for (int mt = 0; mt < 2; mt++)
#pragma unroll
        for (int nt = 0; nt < 8; nt++)
#pragma unroll
            for (int j = 0; j < 4; j++) acc[mt][nt][j] = 0.f;

    gemm3_mainloop(Ahi, Alo, Wth, Wtl, smem, m0, 0, nCh,
                   wm, wn, fr, fc, lr, lh, acc);

#pragma unroll
    for (int mt = 0; mt < 2; mt++) {
        int r0 = wm + mt * 16 + fr;
        int r1 = r0 + 8;
        size_t g0 = (size_t)(m0 + r0) * 128;
        size_t g1 = (size_t)(m0 + r1) * 128;
        float ns0 = 0.f, ns1 = 0.f;
#pragma unroll
        for (int nt = 0; nt < 8; nt++) {
            int n = wn + nt * 8 + fc;
            float b0 = sbias[n], b1 = sbias[n + 1];
            float v00 = fmaxf(acc[mt][nt][0] + b0, 0.f);
            float v01 = fmaxf(acc[mt][nt][1] + b1, 0.f);
            float v10 = fmaxf(acc[mt][nt][2] + b0, 0.f);
            float v11 = fmaxf(acc[mt][nt][3] + b1, 0.f);
            ns0 += v00 * v00 + v01 * v01;
            ns1 += v10 * v10 + v11 * v11;
            __nv_bfloat162 h, l;
            h.x = __float2bfloat16_rn(v00);
            h.y = __float2bfloat16_rn(v01);
            l.x = __float2bfloat16_rn(v00 - __bfloat162float(h.x));
            l.y = __float2bfloat16_rn(v01 - __bfloat162float(h.y));
            *(__nv_bfloat162*)&Ohi[g0 + n] = h;
            *(__nv_bfloat162*)&Olo[g0 + n] = l;
            h.x = __float2bfloat16_rn(v10);
            h.y = __float2bfloat16_rn(v11);
            l.x = __float2bfloat16_rn(v10 - __bfloat162float(h.x));
            l.y = __float2bfloat16_rn(v11 - __bfloat162float(h.y));
            *(__nv_bfloat162*)&Ohi[g1 + n] = h;
            *(__nv_bfloat162*)&Olo[g1 + n] = l;
            if (Ofp) {
                *(float2*)&Ofp[g0 + n] = make_float2(v00, v01);
                *(float2*)&Ofp[g1 + n] = make_float2(v10, v11);
            }
        }
        atomicAdd(&snorm[r0], ns0);
        atomicAdd(&snorm[r1], ns1);
    }
    __syncthreads();
    if (tid < 128 && m0 + tid < NT) nrm[m0 + tid] = snorm[tid];
}

// ---------------------------------------------------------------------------
__global__ void __launch_bounds__(256)
linear_relu_kernel(const float* __restrict__ A, const float* __restrict__ W,
                   const float* __restrict__ bias, float* __restrict__ out,
                   int M, int K)
{
    __shared__ __align__(16) float As[16 * 68];
    __shared__ __align__(16) float Bs[16 * 136];
    const int tx = threadIdx.x, ty = threadIdx.y;
    const int tid = ty * 16 + tx;
    const int m0 = blockIdx.x * 64;

    float acc[4][8];
#pragma unroll
    for (int r = 0; r < 4; r++)
#pragma unroll
        for (int c = 0; c < 8; c++) acc[r][c] = 0.f;

    const int nChunks = (K + 15) / 16;
    for (int ch = 0; ch < nChunks; ch++) {
        const int k0 = ch * 16;
#pragma unroll
        for (int i = 0; i < 4; i++) {
            int e = tid + i * 256;
            int k = e & 15, m = e >> 4;
            float v = 0.f;
            if (k0 + k < K && m0 + m < M) v = A[(size_t)(m0 + m) * K + k0 + k];
            As[k * 68 + m] = v;
        }
#pragma unroll
        for (int i = 0; i < 8; i++) {
            int e = tid + i * 256;
            int h = e & 127, k = e >> 7;
            float v = 0.f;
            if (k0 + k < K) v = W[(size_t)(k0 + k) * HD + h];
            Bs[k * 136 + h] = v;
        }
        __syncthreads();
#pragma unroll
        for (int k = 0; k < 16; k++) {
            float4 a  = *(const float4*)&As[k * 68 + ty * 4];
            float4 b0 = *(const float4*)&Bs[k * 136 + tx * 4];
            float4 b1 = *(const float4*)&Bs[k * 136 + 64 + tx * 4];
            float av[4] = {a.x, a.y, a.z, a.w};
            float bv[8] = {b0.x, b0.y, b0.z, b0.w, b1.x, b1.y, b1.z, b1.w};
#pragma unroll
            for (int r = 0; r < 4; r++)
#pragma unroll
                for (int c = 0; c < 8; c++) acc[r][c] += av[r] * bv[c];
        }
        __syncthreads();
    }
#pragma unroll
    for (int r = 0; r < 4; r++) {
        int m = m0 + ty * 4 + r;
        if (m >= M) continue;
#pragma unroll
        for (int half = 0; half < 2; half++) {
#pragma unroll
            for (int c = 0; c < 4; c++) {
                int h = half * 64 + tx * 4 + c;
                float v = acc[r][half * 4 + c] + bias[h];
                out[(size_t)m * HD + h] = fmaxf(v, 0.f);
            }
        }
    }
}

// ---------------------------------------------------------------------------
__global__ void __launch_bounds__(256)
linear_softmax_kernel(const float* __restrict__ A, const float* __restrict__ W,
                      const float* __restrict__ bias, float* __restrict__ out, int M)
{
    __shared__ float Ws[HD * NL];
    __shared__ float bs[NL];
    int tid = threadIdx.x;
    for (int i = tid; i < HD * NL; i += 256) Ws[i] = W[i];
    if (tid < NL) bs[tid] = bias[tid];
    __syncthreads();

    int warp = tid >> 5, lane = tid & 31;
    int m = blockIdx.x * 8 + warp;
    if (m >= M) return;

    float acc[NL];
#pragma unroll
    for (int h = 0; h < NL; h++) acc[h] = 0.f;
    for (int k = lane; k < HD; k += 32) {
        float x = A[(size_t)m * HD + k];
#pragma unroll
        for (int h = 0; h < NL; h++) acc[h] += x * Ws[k * NL + h];
    }
#pragma unroll
    for (int h = 0; h < NL; h++)
#pragma unroll
        for (int off = 16; off > 0; off >>= 1)
            acc[h] += __shfl_down_sync(0xFFFFFFFFu, acc[h], off);

    if (lane == 0) {
        float v[NL], mx = -1e30f;
#pragma unroll
        for (int h = 0; h < NL; h++) { v[h] = acc[h] + bs[h]; mx = fmaxf(mx, v[h]); }
        float s = 0.f;
#pragma unroll
        for (int h = 0; h < NL; h++) { v[h] = expf(v[h] - mx); s += v[h]; }
        float inv = 1.0f / s;
#pragma unroll
        for (int h = 0; h < NL; h++) out[(size_t)m * NL + h] = v[h] * inv;
    }
}

// ---------------------------------------------------------------------------
__global__ void __launch_bounds__(256)
rownorm_kernel(const float* __restrict__ A, float* __restrict__ out, int M, int D)
{
    int warp = threadIdx.x >> 5, lane = threadIdx.x & 31;
    int m = blockIdx.x * 8 + warp;
    if (m >= M) return;
    float s = 0.f;
    for (int k = lane; k < D; k += 32) { float v = A[(size_t)m * D + k]; s += v * v; }
#pragma unroll
    for (int off = 16; off > 0; off >>= 1) s += __shfl_down_sync(0xFFFFFFFFu, s, off);
    if (lane == 0) out[m] = s;
}

// ---------------------------------------------------------------------------
__global__ void __launch_bounds__(256)
dist_kernel(const float* __restrict__ Q, const float* __restrict__ T,
            const float* __restrict__ qn, const float* __restrict__ tn,
            float* __restrict__ out, float* __restrict__ gmin, int D, int Ncols)
{
    __shared__ __align__(16) float As[16 * 68];
    __shared__ __align__(16) float Bs[16 * 136];
    __shared__ unsigned sMinU[64];
    const int tx = threadIdx.x, ty = threadIdx.y;
    const int tid = ty * 16 + tx;
    const int n0 = blockIdx.x * 128;
    const int m0 = blockIdx.y * 64;

    if (tid < 64) sMinU[tid] = 0x7F800000u;

    float acc[4][8];
#pragma unroll
    for (int r = 0; r < 4; r++)
#pragma unroll
        for (int c = 0; c < 8; c++) acc[r][c] = 0.f;

    const int nChunks = (D + 15) / 16;
    for (int ch = 0; ch < nChunks; ch++) {
        const int k0 = ch * 16;
#pragma unroll
        for (int i = 0; i < 4; i++) {
            int e = tid + i * 256;
            int k = e & 15, m = e >> 4;
            float v = (k0 + k < D) ? Q[(size_t)(m0 + m) * D + k0 + k] : 0.f;
            As[k * 68 + m] = v;
        }
#pragma unroll
        for (int i = 0; i < 8; i++) {
            int e = tid + i * 256;
            int k = e & 15, n = e >> 4;
            int gn = n0 + n;
            float v = 0.f;
            if (k0 + k < D && gn < Ncols) v = T[(size_t)gn * D + k0 + k];
            Bs[k * 136 + n] = v;
        }
        __syncthreads();
#pragma unroll
        for (int k = 0; k < 16; k++) {
            float4 a  = *(const float4*)&As[k * 68 + ty * 4];
            float4 b0 = *(const float4*)&Bs[k * 136 + tx * 4];
            float4 b1 = *(const float4*)&Bs[k * 136 + 64 + tx * 4];
            float av[4] = {a.x, a.y, a.z, a.w};
            float bv[8] = {b0.x, b0.y, b0.z, b0.w, b1.x, b1.y, b1.z, b1.w};
#pragma unroll
            for (int r = 0; r < 4; r++)
#pragma unroll
                for (int c = 0; c < 8; c++) acc[r][c] += av[r] * bv[c];
        }
        __syncthreads();
    }
    const float FINF = __int_as_float(0x7F800000);
#pragma unroll
    for (int r = 0; r < 4; r++) {
        int m = m0 + ty * 4 + r;
        float qv = qn[m];
        float lm = FINF;
#pragma unroll
        for (int half = 0; half < 2; half++) {
#pragma unroll
            for (int c = 0; c < 4; c++) {
                int n = n0 + half * 64 + tx * 4 + c;
                if (n < Ncols) {
                    float d = fmaxf(qv + tn[n] - 2.f * acc[r][half * 4 + c], 0.f);
                    out[(size_t)m * Ncols + n] = d;
                    lm = fminf(lm, d);
                }
            }
        }
        if (lm < FINF) atomicMin(&sMinU[ty * 4 + r], __float_as_uint(lm));
    }
    __syncthreads();
    if (tid < 64)
        gmin[(size_t)(m0 + tid) * NTILES + blockIdx.x] = __uint_as_float(sMinU[tid]);
}

// ---------------------------------------------------------------------------
// Exact top-K select v4: tile-min threshold + TILE-SUBSET scan.
// Only tiles with min <= M75 (~75 of 391) can hold candidates.
// ---------------------------------------------------------------------------
#define SEL_THREADS 512
#define SEL_CAP 2048
#define OFF_CAND  16384
#define OFF_SEL   (OFF_CAND + SEL_CAP * 8)
#define OFF_TIES  (OFF_SEL + 1024)
#define OFF_TLAB  (OFF_TIES + 1024)
#define OFF_MINS  (OFF_TLAB + 512)
#define OFF_TLIST (OFF_MINS + 392 * 4)
#define SEL_SMEM  (OFF_TLIST + 392 * 4)

__device__ __forceinline__ void find_kth(const unsigned* hist, int NB, unsigned kth,
                                         int tid, unsigned* s_bin, unsigned* s_kthr)
{
    if (tid < 32) {
        unsigned running = 0;
        for (int base = 0; base < NB; base += 32) {
            unsigned v = hist[base + tid];
            unsigned sc = v;
#pragma unroll
            for (int off = 1; off < 32; off <<= 1) {
                unsigned t = __shfl_up_sync(0xFFFFFFFFu, sc, off);
                if (tid >= off) sc += t;
            }
            unsigned tot = __shfl_sync(0xFFFFFFFFu, sc, 31);
            if (running + tot >= kth) {
                unsigned mask = __ballot_sync(0xFFFFFFFFu, running + sc >= kth);
                int l = __ffs(mask) - 1;
                if (tid == l) { *s_bin = (unsigned)(base + l); *s_kthr = kth - running - (sc - v); }
                break;
            }
            running += tot;
        }
    }
}

__global__ void __launch_bounds__(SEL_THREADS)
select_kernel(const float* __restrict__ d2mat, const float* __restrict__ gmin,
              const int* __restrict__ labels, float* __restrict__ total, int init)
{
    extern __shared__ __align__(16) char sms[];
    unsigned* hist = (unsigned*)sms;
    u64* cand  = (u64*)(sms + OFF_CAND);
    u64* sel   = (u64*)(sms + OFF_SEL);
    u64* ties  = (u64*)(sms + OFF_TIES);
    int* tlab  = (int*)(sms + OFF_TLAB);
    float* mins = (float*)(sms + OFF_MINS);
    int* tlist = (int*)(sms + OFF_TLIST);

    __shared__ unsigned s_M75, s_bin, s_kthr, s_candcnt, s_selcnt, s_tiecnt, s_ntiles;
    __shared__ float s_w[80];
    __shared__ int s_lab[80];

    const int b = blockIdx.x, tid = threadIdx.x, lane = tid & 31;
    const uint4* usrc = (const uint4*)(d2mat + (size_t)b * NT);
    const int NH = NT / 4;

    // phase 0a: load tile minima
    for (int i = tid; i < NTILES; i += SEL_THREADS)
        mins[i] = gmin[(size_t)b * NTILES + i];
    if (tid == 0) { s_candcnt = 0; s_selcnt = 0; s_tiecnt = 0; s_ntiles = 0; }
    __syncthreads();

    // phase 0b: M75 = 75th smallest tile-min (rank by (key, index))
    if (tid < NTILES) {
        unsigned key = __float_as_uint(mins[tid]);
        int c = 0;
        for (int j = 0; j < NTILES; j++) {
            unsigned kj = __float_as_uint(mins[j]);
            c += (kj < key) || (kj == key && j < tid);
        }
        if (c == KNN - 1) s_M75 = key;
    }
    __syncthreads();
    const unsigned Mkey = s_M75;

    // phase 0c: build subset of tiles that can hold candidates (min <= M75)
    if (tid < NTILES) {
        if (__float_as_uint(mins[tid]) <= Mkey) {
            unsigned s = atomicAdd(&s_ntiles, 1u);
            tlist[s] = tid;
        }
    }
    __syncthreads();
    const int ntl = (int)s_ntiles;   // >= KNN by construction

    // phase 1: scan ONLY listed tiles, compact elements with key <= Mkey.
    // Each tile row = 32 uint4 (last tile partial, i4 < NH guards it).
    for (int w = tid; w < ntl * 32; w += SEL_THREADS) {
        int t = tlist[w >> 5];
        int i4 = t * 32 + (w & 31);
        if (i4 < NH) {
            uint4 a = usrc[i4];
            unsigned k[4] = {a.x, a.y, a.z, a.w};
#pragma unroll
            for (int j = 0; j < 4; j++) {
                if (k[j] <= Mkey) {
                    unsigned s = atomicAdd(&s_candcnt, 1u);
                    if (s < SEL_CAP) cand[s] = ((u64)k[j] << 32) | (unsigned)(i4 * 4 + j);
                }
            }
        }
    }
    __syncthreads();

    unsigned Tkey;
    const unsigned candTotal = s_candcnt;

    if (candTotal <= SEL_CAP) {
        const int cc = (int)candTotal;
        for (int i = tid; i < 4096; i += SEL_THREADS) hist[i] = 0;
        __syncthreads();
        for (int i = tid; i < cc; i += SEL_THREADS)
            atomicAdd(&hist[(unsigned)(cand[i] >> 52)], 1u);
        __syncthreads();
        find_kth(hist, 4096, KNN, tid, &s_bin, &s_kthr);
        __syncthreads();
        const unsigned pfx = s_bin;
        const unsigned k1v = s_kthr;
        for (int i = tid; i < 4096; i += SEL_THREADS) hist[i] = 0;
        __syncthreads();
        for (int i = tid; i < cc; i += SEL_THREADS) {
            unsigned key = (unsigned)(cand[i] >> 32);
            if ((key >> 20) == pfx) atomicAdd(&hist[(key >> 8) & 0xFFFu], 1u);
        }
        __syncthreads();
        find_kth(hist, 4096, k1v, tid, &s_bin, &s_kthr);
        __syncthreads();
        const unsigned pfx20 = (pfx << 12) | s_bin;
        const unsigned k2v = s_kthr;
        for (int i = tid; i < 256; i += SEL_THREADS) hist[i] = 0;
        __syncthreads();
        for (int i = tid; i < cc; i += SEL_THREADS) {
            unsigned key = (unsigned)(cand[i] >> 32);
            if ((key >> 8) == pfx20) atomicAdd(&hist[key & 0xFFu], 1u);
        }
        __syncthreads();
        find_kth(hist, 256, k2v, tid, &s_bin, &s_kthr);
        __syncthreads();
        Tkey = (pfx20 << 8) | s_bin;
        for (int i = tid; i < cc; i += SEL_THREADS) {
            u64 cv = cand[i];
            unsigned key = (unsigned)(cv >> 32);
            if (key < Tkey) {
                unsigned s = atomicAdd(&s_selcnt, 1u);
                if (s < 128) sel[s] = cv;
            } else if (key == Tkey) {
                unsigned s = atomicAdd(&s_tiecnt, 1u);
                if (s < 128) ties[s] = cv;
            }
        }
        __syncthreads();
    } else {
        // fallback (degenerate ties): radix over the tile subset.
        // All elements <= Mkey (which contain the top-KNN) live in listed tiles.
        for (int i = tid; i < 4096; i += SEL_THREADS) hist[i] = 0;
        __syncthreads();
        for (int w = tid; w < ntl * 32; w += SEL_THREADS) {
            int t = tlist[w >> 5];
            int i4 = t * 32 + (w & 31);
            uint4 a = (i4 < NH) ? usrc[i4] : make_uint4(~0u, ~0u, ~0u, ~0u);
            unsigned k[4] = {a.x, a.y, a.z, a.w};
#pragma unroll
            for (int j = 0; j < 4; j++) {
                unsigned bin = (k[j] <= Mkey) ? (k[j] >> 20) : 0xFFFFFFFFu;
                unsigned grp = __match_any_sync(0xFFFFFFFFu, bin);
                if (bin != 0xFFFFFFFFu && lane == __ffs(grp) - 1)
                    atomicAdd(&hist[bin], (unsigned)__popc(grp));
            }
        }
        __syncthreads();
        find_kth(hist, 4096, KNN, tid, &s_bin, &s_kthr);
        __syncthreads();
        const unsigned pfx = s_bin;
        const unsigned k1v = s_kthr;

        for (int i = tid; i < 4096; i += SEL_THREADS) hist[i] = 0;
        __syncthreads();
        for (int w = tid; w < ntl * 32; w += SEL_THREADS) {
            int t = tlist[w >> 5];
            int i4 = t * 32 + (w & 31);
            uint4 a = (i4 < NH) ? usrc[i4] : make_uint4(~0u, ~0u, ~0u, ~0u);
            unsigned k[4] = {a.x, a.y, a.z, a.w};
#pragma unroll
            for (int j = 0; j < 4; j++) {
                unsigned bin = (k[j] <= Mkey && (k[j] >> 20) == pfx)
                               ? ((k[j] >> 8) & 0xFFFu) : 0xFFFFFFFFu;
                unsigned grp = __match_any_sync(0xFFFFFFFFu, bin);
                if (bin != 0xFFFFFFFFu && lane == __ffs(grp) - 1)
                    atomicAdd(&hist[bin], (unsigned)__popc(grp));
            }
        }
        __syncthreads();
        find_kth(hist, 4096, k1v, tid, &s_bin, &s_kthr);
        __syncthreads();
        const unsigned pfx20 = (pfx << 12) | s_bin;
        const unsigned k2v = s_kthr;

        for (int i = tid; i < 256; i += SEL_THREADS) hist[i] = 0;
        __syncthreads();
        for (int w = tid; w < ntl * 32; w += SEL_THREADS) {
            int t = tlist[w >> 5];
            int i4 = t * 32 + (w & 31);
            uint4 a = (i4 < NH) ? usrc[i4] : make_uint4(~0u, ~0u, ~0u, ~0u);
            unsigned k[4] = {a.x, a.y, a.z, a.w};
#pragma unroll
            for (int j = 0; j < 4; j++) {
                unsigned bin = (k[j] <= Mkey && (k[j] >> 8) == pfx20)
                               ? (k[j] & 0xFFu) : 0xFFFFFFFFu;
                unsigned grp = __match_any_sync(0xFFFFFFFFu, bin);
                if (bin != 0xFFFFFFFFu && lane == __ffs(grp) - 1)
                    atomicAdd(&hist[bin], (unsigned)__popc(grp));
            }
        }
        __syncthreads();
        find_kth(hist, 256, k2v, tid, &s_bin, &s_kthr);
        __syncthreads();
        Tkey = (pfx20 << 8) | s_bin;

        for (int w = tid; w < ntl * 32; w += SEL_THREADS) {
            int t = tlist[w >> 5];
            int i4 = t * 32 + (w & 31);
            if (i4 < NH) {
                uint4 a = usrc[i4];
                unsigned k[4] = {a.x, a.y, a.z, a.w};
#pragma unroll
                for (int j = 0; j < 4; j++) {
                    if (k[j] < Tkey) {
                        unsigned s = atomicAdd(&s_selcnt, 1u);
                        if (s < 128) sel[s] = ((u64)k[j] << 32) | (unsigned)(i4 * 4 + j);
                    } else if (k[j] == Tkey) {
                        unsigned s = atomicAdd(&s_tiecnt, 1u);
                        if (s < 128) ties[s] = ((u64)k[j] << 32) | (unsigned)(i4 * 4 + j);
                    }
                }
            }
        }
        __syncthreads();
    }

    const int ns = min((int)s_selcnt, 128);
    const int ne = min((int)s_tiecnt, 128);

    if (tid < ns) {
        u64 mine = sel[tid];
        unsigned my_idx = (unsigned)(mine & 0xFFFFFFFFu);
        int rank = 0;
        for (int j = 0; j < ns; j++) rank += ((unsigned)(sel[j] & 0xFFFFFFFFu) < my_idx);
        float d2 = __uint_as_float((unsigned)(mine >> 32));
        s_w[rank] = (d2 > 0.f) ? __fdiv_rn(1.0f, __fsqrt_rn(d2)) : 0.f;
        s_lab[rank] = labels[my_idx];
    }
    if (tid >= 128 && tid - 128 < ne) {
        int t = tid - 128;
        unsigned my_idx = (unsigned)(ties[t] & 0xFFFFFFFFu);
        int rank = 0;
        for (int j = 0; j < ne; j++) rank += ((unsigned)(ties[j] & 0xFFFFFFFFu) < my_idx);
        tlab[rank] = labels[my_idx];
    }
    __syncthreads();

    if (tid == 0) {
        float cls[NL];
#pragma unroll
        for (int l = 0; l < NL; l++) cls[l] = 0.f;
        float stot = 0.f;
        for (int j = 0; j < ns; j++) { stot += s_w[j]; cls[s_lab[j]] += s_w[j]; }
        int need = KNN - ns;
        float d2T = __uint_as_float(Tkey);
        float wT = (d2T > 0.f) ? __fdiv_rn(1.0f, __fsqrt_rn(d2T)) : 0.f;
        int m = (need < ne) ? need : ne;
        for (int j = 0; j < m; j++) { stot += wT; cls[tlab[j]] += wT; }
#pragma unroll
        for (int l = 0; l < NL; l++) {
            float val = stot - cls[l];
            size_t o = (size_t)b * NL + l;
            if (init) total[o] = val; else total[o] += val;
        }
    }
}

// ---------------------------------------------------------------------------
__global__ void __launch_bounds__(256)
pvalue_kernel(const float* __restrict__ total, const float* __restrict__ cali,
              float* __restrict__ out)
{
    const int b = blockIdx.x, tid = threadIdx.x;
    float t[NL];
#pragma unroll
    for (int l = 0; l < NL; l++) t[l] = total[(size_t)b * NL + l];
    int cnt[NL];
#pragma unroll
    for (int l = 0; l < NL; l++) cnt[l] = 0;
    for (int i = tid; i < NC; i += 256) {
        float c = cali[i];
#pragma unroll
        for (int l = 0; l < NL; l++) cnt[l] += (c >= t[l]) ? 1 : 0;
    }
    __shared__ int sc[NL];
    if (tid < NL) sc[tid] = 0;
    __syncthreads();
#pragma unroll
    for (int l = 0; l < NL; l++) atomicAdd(&sc[l], cnt[l]);
    __syncthreads();
    if (tid < NL) out[(size_t)b * NL + tid] = (float)sc[tid] * (1.0f / NC);
}

// ---------------------------------------------------------------------------
extern "C" void kernel_launch(void* const* d_in, const int* in_sizes, int n_in,
                              void* d_out, int out_size)
{
    const float* x        = (const float*)d_in[0];
    const float* train_x  = (const float*)d_in[1];
    const int*   lab      = (const int*)  d_in[2];
    const float* cali     = (const float*)d_in[3];
    const float* W1 = (const float*)d_in[4];  const float* b1 = (const float*)d_in[5];
    const float* W2 = (const float*)d_in[6];  const float* b2 = (const float*)d_in[7];
    const float* W3 = (const float*)d_in[8];  const float* b3 = (const float*)d_in[9];
    const float* W4 = (const float*)d_in[10]; const float* b4 = (const float*)d_in[11];
    float* out = (float*)d_out;

    float *h1p, *h2p, *h3p, *q4p, *t3p, *t4p, *d2p, *qnp, *tnp, *totp, *minp;
    __nv_bfloat16 *qhip, *qlop, *thip, *tlop, *thi2p, *tlo2p;
    __nv_bfloat16 *w1th, *w1tl, *w2th, *w2tl, *w3th, *w3tl;
    cudaGetSymbolAddress((void**)&h1p, g_h1);
    cudaGetSymbolAddress((void**)&h2p, g_h2);
    cudaGetSymbolAddress((void**)&h3p, g_h3);
    cudaGetSymbolAddress((void**)&q4p, g_q4);
    cudaGetSymbolAddress((void**)&t3p, g_t3);
    cudaGetSymbolAddress((void**)&t4p, g_t4);
    cudaGetSymbolAddress((void**)&d2p, g_d2);
    cudaGetSymbolAddress((void**)&minp, g_min);
    cudaGetSymbolAddress((void**)&qnp, g_qn);
    cudaGetSymbolAddress((void**)&tnp, g_tn);
    cudaGetSymbolAddress((void**)&totp, g_tot);
    cudaGetSymbolAddress((void**)&qhip, g_qhi);
    cudaGetSymbolAddress((void**)&qlop, g_qlo);
    cudaGetSymbolAddress((void**)&thip, g_thi);
    cudaGetSymbolAddress((void**)&tlop, g_tlo);
    cudaGetSymbolAddress((void**)&thi2p, g_thi2);
    cudaGetSymbolAddress((void**)&tlo2p, g_tlo2);
    cudaGetSymbolAddress((void**)&w1th, g_w1th);
    cudaGetSymbolAddress((void**)&w1tl, g_w1tl);
    cudaGetSymbolAddress((void**)&w2th, g_w2th);
    cudaGetSymbolAddress((void**)&w2tl, g_w2tl);
    cudaGetSymbolAddress((void**)&w3th, g_w3th);
    cudaGetSymbolAddress((void**)&w3tl, g_w3tl);

    cudaFuncSetAttribute(select_kernel,
                         cudaFuncAttributeMaxDynamicSharedMemorySize, SEL_SMEM);

    dim3 tb(16, 16);
    const int D0 = 83;
    const dim3 mgrid(NTILES, BQ / 128);

    conv_norm_kernel<<<BQ / 8, 256>>>(x, qhip, qlop, qnp, BQ, D0);
    conv_norm_kernel<<<NTP / 8, 256>>>(train_x, thip, tlop, tnp, NT, D0);
    wt_convert_kernel<<<(3 * 128 * 128 + 255) / 256, 256>>>(W1, W2, W3);

    // layer 0 (mma_dist = launch #4 -> profiled)
    mma_dist_kernel<<<mgrid, 256>>>(qhip, qlop, thip, tlop, qnp, tnp, d2p, minp, 6);
    select_kernel<<<BQ, SEL_THREADS, SEL_SMEM>>>(d2p, minp, lab, totp, 1);

    // query-side MLP (tiny SIMT)
    linear_relu_kernel<<<BQ / 64, tb>>>(x,   W1, b1, h1p, BQ, D0);
    linear_relu_kernel<<<BQ / 64, tb>>>(h1p, W2, b2, h2p, BQ, HD);
    linear_relu_kernel<<<BQ / 64, tb>>>(h2p, W3, b3, h3p, BQ, HD);
    linear_softmax_kernel<<<(BQ + 7) / 8, 256>>>(h3p, W4, b4, q4p, BQ);

    // layer 1
    mma_linear_kernel<<<NTILES, 256>>>(thip, tlop, w1th, w1tl, b1,
                                       thi2p, tlo2p, tnp, (float*)0, 6);
    conv_norm_kernel<<<BQ / 8, 256>>>(h1p, qhip, qlop, qnp, BQ, HD);
    mma_dist_kernel<<<mgrid, 256>>>(qhip, qlop, thi2p, tlo2p, qnp, tnp, d2p, minp, 8);
    select_kernel<<<BQ, SEL_THREADS, SEL_SMEM>>>(d2p, minp, lab, totp, 0);

    // layer 2
    mma_linear_kernel<<<NTILES, 256>>>(thi2p, tlo2p, w2th, w2tl, b2,
                                       thip, tlop, tnp, (float*)0, 8);
    conv_norm_kernel<<<BQ / 8, 256>>>(h2p, qhip, qlop, qnp, BQ, HD);
    mma_dist_kernel<<<mgrid, 256>>>(qhip, qlop, thip, tlop, qnp, tnp, d2p, minp, 8);
    select_kernel<<<BQ, SEL_THREADS, SEL_SMEM>>>(d2p, minp, lab, totp, 0);

    // layer 3 (+ fp32 t3 for softmax)
    mma_linear_kernel<<<NTILES, 256>>>(thip, tlop, w3th, w3tl, b3,
                                       thi2p, tlo2p, tnp, t3p, 8);
    conv_norm_kernel<<<BQ / 8, 256>>>(h3p, qhip, qlop, qnp, BQ, HD);
    mma_dist_kernel<<<mgrid, 256>>>(qhip, qlop, thi2p, tlo2p, qnp, tnp, d2p, minp, 8);
    select_kernel<<<BQ, SEL_THREADS, SEL_SMEM>>>(d2p, minp, lab, totp, 0);

    // layer 4 (softmax features, D=8): exact fp32 path
    linear_softmax_kernel<<<(NT + 7) / 8, 256>>>(t3p, W4, b4, t4p, NT);
    rownorm_kernel<<<(BQ + 7) / 8, 256>>>(q4p, qnp, BQ, NL);
    rownorm_kernel<<<(NT + 7) / 8, 256>>>(t4p, tnp, NT, NL);
    dist_kernel<<<dim3(NTILES, BQ / 64), tb>>>(q4p, t4p, qnp, tnp, d2p, minp, NL, NT);
    select_kernel<<<BQ, SEL_THREADS, SEL_SMEM>>>(d2p, minp, lab, totp, 0);

    pvalue_kernel<<<BQ, 256>>>(totp, cali, out);
}